// round 11
// baseline (speedup 1.0000x reference)
#include <cuda_runtime.h>
#include <cuda_bf16.h>
#include <cuda_fp16.h>
#include <math.h>
#include <stdint.h>

// ---------------- problem constants ----------------
#define TT 1024
#define EE 1024
#define VV 32000
#define NH 16
#define NKV 4
#define DHD 64
#define KVD (NKV*DHD)     // 256
#define QKVN 1536
#define LNUM 2
#define RNUM 2
#define FF 4096
#define EPSV 1e-5f

typedef __nv_bfloat16 bf16;

// ---------------- device scratch ----------------
__device__ float g_x[TT*EE];
__device__ bf16  g_hh[TT*EE], g_hl[TT*EE];
__device__ __half g_hf[TT*EE];                         // fp16 LN2 output (FFN input)
__device__ __half g_fff[TT*FF];                        // fp16 gelu(FFN1) output
__device__ float g_att[(size_t)NH*TT*TT];
__device__ bf16  g_atth[(size_t)NH*TT*TT], g_attl[(size_t)NH*TT*TT];
__device__ float g_part[3*TT*QKVN];          // split-K partials (reused)
__device__ bf16  g_qh[NH*TT*DHD],  g_ql[NH*TT*DHD];
__device__ bf16  g_kh[NKV*TT*DHD], g_kl[NKV*TT*DHD];
__device__ bf16  g_vth[NKV*DHD*TT], g_vtl[NKV*DHD*TT];   // transposed V
__device__ bf16  g_yh[TT*EE], g_yl[TT*EE];
__device__ bf16  g_wqkv_h[LNUM*QKVN*EE], g_wqkv_l[LNUM*QKVN*EE];
__device__ bf16  g_wo_h[LNUM*EE*EE],     g_wo_l[LNUM*EE*EE];
__device__ __half g_w1fh[LNUM*FF*EE],    g_w1fl[LNUM*FF*EE];   // fp16 hi/lo W1
__device__ __half g_w2fh[LNUM*EE*FF],    g_w2fl[LNUM*EE*FF];   // fp16 hi/lo W2
// int8 logits path
__device__ char  g_e1[(size_t)VV*EE], g_e2[(size_t)VV*EE];     // int8 2-term embed
__device__ float g_sbv[VV];                                     // embed row scales
__device__ char  g_a1[TT*EE], g_a2[TT*EE];                      // int8 2-term final-LN
__device__ float g_saq[TT];                                     // row scales
__device__ float g_logits[(size_t)TT*VV];
__device__ float g_loss;

// ---------------- generic helpers ----------------
__device__ __forceinline__ float blk_sum256(float v, float* sh) {
    int tid = threadIdx.x;
    sh[tid] = v; __syncthreads();
    #pragma unroll
    for (int s = 128; s > 0; s >>= 1) { if (tid < s) sh[tid] += sh[tid + s]; __syncthreads(); }
    float r = sh[0]; __syncthreads();
    return r;
}
__device__ __forceinline__ float blk_max256(float v, float* sh) {
    int tid = threadIdx.x;
    sh[tid] = v; __syncthreads();
    #pragma unroll
    for (int s = 128; s > 0; s >>= 1) { if (tid < s) sh[tid] = fmaxf(sh[tid], sh[tid + s]); __syncthreads(); }
    float r = sh[0]; __syncthreads();
    return r;
}
__device__ __forceinline__ float gelu_exact(float x) {
    return 0.5f * x * (1.0f + erff(x * 0.7071067811865476f));
}
__device__ __forceinline__ void split_bf16(float v, bf16& h, bf16& l) {
    h = __float2bfloat16(v);
    l = __float2bfloat16(v - __bfloat162float(h));
}
__device__ __forceinline__ void split_fp16(float v, __half& h, __half& l) {
    h = __float2half_rn(v);
    l = __float2half_rn(v - __half2float(h));
}
// 2-level int8 quantization: v ~= scale * (q1 + q2/256)
__device__ __forceinline__ void quant8(float v, float inv_s, char& q1, char& q2) {
    float q = v * inv_s;                    // in [-127, 127]
    float a1 = rintf(q);
    float r = (q - a1) * 256.0f;
    float a2 = rintf(r);
    a2 = fminf(fmaxf(a2, -127.0f), 127.0f);
    q1 = (char)(int)a1;
    q2 = (char)(int)a2;
}

// ---------------- PTX wrappers ----------------
__device__ __forceinline__ void mma_bf16(float* d, const uint32_t* a, const uint32_t* b) {
    asm volatile("mma.sync.aligned.m16n8k16.row.col.f32.bf16.bf16.f32 "
        "{%0,%1,%2,%3}, {%4,%5,%6,%7}, {%8,%9}, {%0,%1,%2,%3};"
        : "+f"(d[0]), "+f"(d[1]), "+f"(d[2]), "+f"(d[3])
        : "r"(a[0]), "r"(a[1]), "r"(a[2]), "r"(a[3]), "r"(b[0]), "r"(b[1]));
}
__device__ __forceinline__ void mma_fp16(float* d, const uint32_t* a, const uint32_t* b) {
    asm volatile("mma.sync.aligned.m16n8k16.row.col.f32.f16.f16.f32 "
        "{%0,%1,%2,%3}, {%4,%5,%6,%7}, {%8,%9}, {%0,%1,%2,%3};"
        : "+f"(d[0]), "+f"(d[1]), "+f"(d[2]), "+f"(d[3])
        : "r"(a[0]), "r"(a[1]), "r"(a[2]), "r"(a[3]), "r"(b[0]), "r"(b[1]));
}
__device__ __forceinline__ void mma_s8(int* d, const uint32_t* a, const uint32_t* b) {
    asm volatile("mma.sync.aligned.m16n8k32.row.col.s32.s8.s8.s32 "
        "{%0,%1,%2,%3}, {%4,%5,%6,%7}, {%8,%9}, {%0,%1,%2,%3};"
        : "+r"(d[0]), "+r"(d[1]), "+r"(d[2]), "+r"(d[3])
        : "r"(a[0]), "r"(a[1]), "r"(a[2]), "r"(a[3]), "r"(b[0]), "r"(b[1]));
}
__device__ __forceinline__ void ldsm4(uint32_t* r, uint32_t addr) {
    asm volatile("ldmatrix.sync.aligned.m8n8.x4.shared.b16 {%0,%1,%2,%3}, [%4];"
        : "=r"(r[0]), "=r"(r[1]), "=r"(r[2]), "=r"(r[3]) : "r"(addr));
}
__device__ __forceinline__ void cp16(uint32_t s, const void* g) {
    asm volatile("cp.async.cg.shared.global [%0], [%1], 16;" :: "r"(s), "l"(g));
}
#define CP_COMMIT()  asm volatile("cp.async.commit_group;")
#define CP_WAIT(n)   asm volatile("cp.async.wait_group %0;" :: "n"(n))

// SW128 swizzle: 128B rows, 16B chunks, chunk ^= row&7  (conflict-free ldmatrix)
__device__ __forceinline__ uint32_t sw_off(int row, int chunk) {
    return (uint32_t)(row * 128 + ((chunk ^ (row & 7)) << 4));
}

// ---------------- split-bf16 3-term HMMA GEMM (QKV / Wo) ----------------
template<int MODE, int TN, int NSTG>
__global__ __launch_bounds__(256, 1) void gemm_mma(
    const bf16* __restrict__ Ah, const bf16* __restrict__ Al,
    const bf16* __restrict__ Bh, const bf16* __restrict__ Bl,
    float* C, const float* Rs, bf16* Oh, bf16* Ol,
    int N, int K)
{
    constexpr int TSA = 128 * 128;
    constexpr int TSB = TN * 128;
    constexpr int SB  = 2 * TSA + 2 * TSB;
    constexpr int BCH = TN * 8;
    constexpr int TC  = 2048 + 2 * BCH;
    constexpr int NG  = TN / 64;
    constexpr int NF  = 2 * NG;

    extern __shared__ char dsm[];
    const int tid = threadIdx.x;
    const int lane = tid & 31, warp = tid >> 5;
    const int wm = warp & 1, wn = warp >> 1;
    const int row0 = blockIdx.x * 128, col0 = blockIdx.y * TN;
    const uint32_t sb = (uint32_t)__cvta_generic_to_shared(dsm);

    float acc[4][NF][4];
    #pragma unroll
    for (int i = 0; i < 4; i++)
        #pragma unroll
        for (int j = 0; j < NF; j++)
            #pragma unroll
            for (int r = 0; r < 4; r++) acc[i][j][r] = 0.f;

    auto load_stage = [&](int s) {
        int k0 = s * 64;
        uint32_t base = sb + (s % NSTG) * SB;
        #pragma unroll
        for (int ii = 0; ii < TC / 256; ii++) {
            int i = tid + ii * 256;
            const bf16* src;
            uint32_t toff;
            if (i < 2048) {
                int t = i >> 10, w = i & 1023;
                int r = w >> 3, c = w & 7;
                src = (t ? Al : Ah) + (size_t)(row0 + r) * K + k0 + c * 8;
                toff = t * TSA + sw_off(r, c);
            } else {
                int j = i - 2048;
                int t = j / BCH, w = j & (BCH - 1);
                int r = w >> 3, c = w & 7;
                src = (t ? Bl : Bh) + (size_t)(col0 + r) * K + k0 + c * 8;
                toff = 2 * TSA + t * TSB + sw_off(r, c);
            }
            cp16(base + toff, src);
        }
        CP_COMMIT();
    };

    const int Stot = K >> 6;
    const int SK = gridDim.z;
    const int Sc = (Stot + SK - 1) / SK;
    const int s0 = blockIdx.z * Sc;
    const int s1 = min(Stot, s0 + Sc);

    #pragma unroll
    for (int i = 0; i < NSTG; i++)
        if (s0 + i < s1) load_stage(s0 + i);

    const int lr = lane & 15, lcs = lane >> 4;

    for (int s = s0; s < s1; s++) {
        int ahead = s1 - 1 - s;
        int w = ahead < (NSTG - 1) ? ahead : (NSTG - 1);
        if (w == 2)      { CP_WAIT(2); }
        else if (w == 1) { CP_WAIT(1); }
        else             { CP_WAIT(0); }
        __syncthreads();
        uint32_t ab = sb + (s % NSTG) * SB;
        #pragma unroll
        for (int k16 = 0; k16 < 4; k16++) {
            const int cch = k16 * 2 + lcs;
            uint32_t ah[4][4], al[4][4];
            #pragma unroll
            for (int mf = 0; mf < 4; mf++) {
                int row = wm * 64 + mf * 16 + lr;
                uint32_t off = sw_off(row, cch);
                ldsm4(ah[mf], ab + off);
                ldsm4(al[mf], ab + TSA + off);
            }
            #pragma unroll
            for (int g = 0; g < NG; g++) {
                int row = wn * (TN / 4) + g * 16 + lr;
                uint32_t off = sw_off(row, cch);
                uint32_t rh[4], rl[4];
                ldsm4(rh, ab + 2 * TSA + off);
                ldsm4(rl, ab + 2 * TSA + TSB + off);
                uint32_t b0h[2] = {rh[0], rh[2]}, b1h[2] = {rh[1], rh[3]};
                uint32_t b0l[2] = {rl[0], rl[2]}, b1l[2] = {rl[1], rl[3]};
                #pragma unroll
                for (int mf = 0; mf < 4; mf++) {
                    mma_bf16(acc[mf][g*2], ah[mf], b0h);
                    mma_bf16(acc[mf][g*2], ah[mf], b0l);
                    mma_bf16(acc[mf][g*2], al[mf], b0h);
                    mma_bf16(acc[mf][g*2+1], ah[mf], b1h);
                    mma_bf16(acc[mf][g*2+1], ah[mf], b1l);
                    mma_bf16(acc[mf][g*2+1], al[mf], b1h);
                }
            }
        }
        __syncthreads();
        if (s + NSTG < s1) load_stage(s + NSTG);
    }

    const size_t pstride = (size_t)gridDim.x * 128 * N;
    float* Cp = C + (size_t)blockIdx.z * pstride;
    #pragma unroll
    for (int mf = 0; mf < 4; mf++)
        #pragma unroll
        for (int nf = 0; nf < NF; nf++) {
            int r = row0 + wm * 64 + mf * 16 + (lane >> 2);
            int c = col0 + wn * (TN / 4) + nf * 8 + (lane & 3) * 2;
            float* d = acc[mf][nf];
            *(float2*)(Cp + (size_t)r * N + c)       = make_float2(d[0], d[1]);
            *(float2*)(Cp + (size_t)(r + 8) * N + c) = make_float2(d[2], d[3]);
        }
}

#define GSM128 (3 * (2*128*128 + 2*128*128))   // 196608

// ---------------- fp16 2-term GEMM (FFN): C = A * (Bh+Bl)^T ----------------
template<int MODE, int TN, int NSTG>
__global__ __launch_bounds__(256, 1) void fp16_mma(
    const __half* __restrict__ A, const __half* __restrict__ Bh,
    const __half* __restrict__ Bl, float* __restrict__ C,
    __half* __restrict__ Of, int N, int K)
{
    constexpr int TSA = 128 * 128;
    constexpr int TSB = TN * 128;
    constexpr int SB  = TSA + 2 * TSB;
    constexpr int BCH = TN * 8;
    constexpr int TC  = 1024 + 2 * BCH;
    constexpr int NG  = TN / 64;
    constexpr int NF  = 2 * NG;

    extern __shared__ char dsm[];
    const int tid = threadIdx.x;
    const int lane = tid & 31, warp = tid >> 5;
    const int wm = warp & 1, wn = warp >> 1;
    const int row0 = blockIdx.x * 128, col0 = blockIdx.y * TN;
    const uint32_t sb = (uint32_t)__cvta_generic_to_shared(dsm);

    float acc[4][NF][4];
    #pragma unroll
    for (int i = 0; i < 4; i++)
        #pragma unroll
        for (int j = 0; j < NF; j++)
            #pragma unroll
            for (int r = 0; r < 4; r++) acc[i][j][r] = 0.f;

    auto load_stage = [&](int s) {
        int k0 = s * 64;
        uint32_t base = sb + (s % NSTG) * SB;
        #pragma unroll
        for (int ii = 0; ii < TC / 256; ii++) {
            int i = tid + ii * 256;
            const __half* src; uint32_t toff;
            if (i < 1024) {
                int r = i >> 3, c = i & 7;
                src = A + (size_t)(row0 + r) * K + k0 + c * 8;
                toff = sw_off(r, c);
            } else {
                int j = i - 1024;
                int t = j / BCH, w = j & (BCH - 1);
                int r = w >> 3, c = w & 7;
                src = (t ? Bl : Bh) + (size_t)(col0 + r) * K + k0 + c * 8;
                toff = TSA + t * TSB + sw_off(r, c);
            }
            cp16(base + toff, src);
        }
        CP_COMMIT();
    };

    const int Stot = K >> 6;
    const int SK = gridDim.z;
    const int Sc = (Stot + SK - 1) / SK;
    const int s0 = blockIdx.z * Sc;
    const int s1 = min(Stot, s0 + Sc);

    #pragma unroll
    for (int i = 0; i < NSTG; i++)
        if (s0 + i < s1) load_stage(s0 + i);

    const int lr = lane & 15, lcs = lane >> 4;

    for (int s = s0; s < s1; s++) {
        int ahead = s1 - 1 - s;
        int w = ahead < (NSTG - 1) ? ahead : (NSTG - 1);
        if (w == 2)      { CP_WAIT(2); }
        else if (w == 1) { CP_WAIT(1); }
        else             { CP_WAIT(0); }
        __syncthreads();
        uint32_t ab = sb + (s % NSTG) * SB;
        #pragma unroll
        for (int k16 = 0; k16 < 4; k16++) {
            const int cch = k16 * 2 + lcs;
            uint32_t ah[4][4];
            #pragma unroll
            for (int mf = 0; mf < 4; mf++)
                ldsm4(ah[mf], ab + sw_off(wm * 64 + mf * 16 + lr, cch));
            #pragma unroll
            for (int g = 0; g < NG; g++) {
                uint32_t off = sw_off(wn * (TN / 4) + g * 16 + lr, cch);
                uint32_t rh[4], rl[4];
                ldsm4(rh, ab + TSA + off);
                ldsm4(rl, ab + TSA + TSB + off);
                uint32_t b0h[2] = {rh[0], rh[2]}, b1h[2] = {rh[1], rh[3]};
                uint32_t b0l[2] = {rl[0], rl[2]}, b1l[2] = {rl[1], rl[3]};
                #pragma unroll
                for (int mf = 0; mf < 4; mf++) {
                    mma_fp16(acc[mf][g*2], ah[mf], b0h);
                    mma_fp16(acc[mf][g*2], ah[mf], b0l);
                    mma_fp16(acc[mf][g*2+1], ah[mf], b1h);
                    mma_fp16(acc[mf][g*2+1], ah[mf], b1l);
                }
            }
        }
        __syncthreads();
        if (s + NSTG < s1) load_stage(s + NSTG);
    }

    const size_t pstride = (size_t)gridDim.x * 128 * N;
    float* Cp = C + (size_t)blockIdx.z * pstride;
    #pragma unroll
    for (int mf = 0; mf < 4; mf++)
        #pragma unroll
        for (int nf = 0; nf < NF; nf++) {
            int r = row0 + wm * 64 + mf * 16 + (lane >> 2);
            int c = col0 + wn * (TN / 4) + nf * 8 + (lane & 3) * 2;
            float* d = acc[mf][nf];
            if (MODE == 0) {
                *(float2*)(Cp + (size_t)r * N + c)       = make_float2(d[0], d[1]);
                *(float2*)(Cp + (size_t)(r + 8) * N + c) = make_float2(d[2], d[3]);
            } else {
                __half o0 = __float2half_rn(gelu_exact(d[0]));
                __half o1 = __float2half_rn(gelu_exact(d[1]));
                __half o2 = __float2half_rn(gelu_exact(d[2]));
                __half o3 = __float2half_rn(gelu_exact(d[3]));
                *(__half2*)(Of + (size_t)r * N + c)       = __halves2half2(o0, o1);
                *(__half2*)(Of + (size_t)(r + 8) * N + c) = __halves2half2(o2, o3);
            }
        }
}

#define F16SM128 (3 * (128*128 + 2*128*128))   // 147456
#define F16SM256 (2 * (128*128 + 2*256*128))   // 163840

// ---------------- int8 2-term logits GEMM ----------------
// A = sa*(a1 + a2/256), B = sb*(b1 + b2/256).
// C = sa*sb*(a1*b1 + (a1*b2 + a2*b1)/256). 3 s8 MMAs per k32, TN=128.
// Byte-level operand layout of m16n8k32.s8 == m16n8k16.f16 -> same ldsm/swizzle.
#define LI8SM (3 * (2*128*128 + 2*128*128))    // 196608, BK=128 rows
__global__ __launch_bounds__(256, 1) void logits_i8(
    const char* __restrict__ A1, const char* __restrict__ A2,
    const char* __restrict__ B1, const char* __restrict__ B2,
    const float* __restrict__ sa, const float* __restrict__ sbv,
    float* __restrict__ C)
{
    constexpr int TSA = 128 * 128;     // 16KB: 128 rows x 128 int8 (BK=128)
    constexpr int TSB = 128 * 128;
    constexpr int SB  = 2 * TSA + 2 * TSB;   // 64KB
    constexpr int NSTG = 3;
    const int N = VV, K = EE;

    extern __shared__ char dsm[];
    const int tid = threadIdx.x;
    const int lane = tid & 31, warp = tid >> 5;
    const int wm = warp & 1, wn = warp >> 1;
    const int row0 = blockIdx.x * 128, col0 = blockIdx.y * 128;
    const uint32_t sb = (uint32_t)__cvta_generic_to_shared(dsm);

    int s1acc[4][4][4], s23acc[4][4][4];
    #pragma unroll
    for (int i = 0; i < 4; i++)
        #pragma unroll
        for (int j = 0; j < 4; j++)
            #pragma unroll
            for (int r = 0; r < 4; r++) { s1acc[i][j][r] = 0; s23acc[i][j][r] = 0; }

    auto load_stage = [&](int s) {
        int k0 = s * 128;   // BK = 128 int8
        uint32_t base = sb + (s % NSTG) * SB;
        #pragma unroll
        for (int ii = 0; ii < 16; ii++) {   // 4096 chunks / 256 threads
            int i = tid + ii * 256;
            int t = i >> 10;                 // 0:a1 1:a2 2:b1 3:b2
            int w = i & 1023;
            int r = w >> 3, c = w & 7;
            const char* src;
            if (t == 0)      src = A1 + (size_t)(row0 + r) * K + k0 + c * 16;
            else if (t == 1) src = A2 + (size_t)(row0 + r) * K + k0 + c * 16;
            else if (t == 2) src = B1 + (size_t)(col0 + r) * K + k0 + c * 16;
            else             src = B2 + (size_t)(col0 + r) * K + k0 + c * 16;
            cp16(base + t * TSA + sw_off(r, c), src);
        }
        CP_COMMIT();
    };

    const int S = K >> 7;   // 8 stages
    load_stage(0);
    load_stage(1);
    load_stage(2);
    const int lr = lane & 15, lcs = lane >> 4;

    for (int s = 0; s < S; s++) {
        int ahead = S - 1 - s;
        int w = ahead < 2 ? ahead : 2;
        if (w == 2)      { CP_WAIT(2); }
        else if (w == 1) { CP_WAIT(1); }
        else             { CP_WAIT(0); }
        __syncthreads();
        uint32_t ab = sb + (s % NSTG) * SB;
        #pragma unroll
        for (int k32 = 0; k32 < 4; k32++) {
            const int cch = k32 * 2 + lcs;
            uint32_t a1f[4][4], a2f[4][4];
            #pragma unroll
            for (int mf = 0; mf < 4; mf++) {
                uint32_t off = sw_off(wm * 64 + mf * 16 + lr, cch);
                ldsm4(a1f[mf], ab + off);
                ldsm4(a2f[mf], ab + TSA + off);
            }
            #pragma unroll
            for (int g = 0; g < 2; g++) {
                uint32_t off = sw_off(wn * 32 + g * 16 + lr, cch);
                uint32_t r1[4], r2[4];
                ldsm4(r1, ab + 2 * TSA + off);
                ldsm4(r2, ab + 3 * TSA + off);
                uint32_t b0_1[2] = {r1[0], r1[2]}, b1_1[2] = {r1[1], r1[3]};
                uint32_t b0_2[2] = {r2[0], r2[2]}, b1_2[2] = {r2[1], r2[3]};
                #pragma unroll
                for (int mf = 0; mf < 4; mf++) {
                    mma_s8(s1acc[mf][g*2],  a1f[mf], b0_1);
                    mma_s8(s23acc[mf][g*2], a1f[mf], b0_2);
                    mma_s8(s23acc[mf][g*2], a2f[mf], b0_1);
                    mma_s8(s1acc[mf][g*2+1],  a1f[mf], b1_1);
                    mma_s8(s23acc[mf][g*2+1], a1f[mf], b1_2);
                    mma_s8(s23acc[mf][g*2+1], a2f[mf], b1_1);
                }
            }
        }
        __syncthreads();
        if (s + NSTG < S) load_stage(s + NSTG);
    }

    #pragma unroll
    for (int mf = 0; mf < 4; mf++) {
        int r = row0 + wm * 64 + mf * 16 + (lane >> 2);
        float sa0 = sa[r], sa8 = sa[r + 8];
        #pragma unroll
        for (int nf = 0; nf < 4; nf++) {
            int c = col0 + wn * 32 + nf * 8 + (lane & 3) * 2;
            float sb0 = sbv[c], sb1 = sbv[c + 1];
            int* d1 = s1acc[mf][nf];
            int* d23 = s23acc[mf][nf];
            const float k = 1.0f / 256.0f;
            float v0 = sa0 * sb0 * ((float)d1[0] + (float)d23[0] * k);
            float v1 = sa0 * sb1 * ((float)d1[1] + (float)d23[1] * k);
            float v2 = sa8 * sb0 * ((float)d1[2] + (float)d23[2] * k);
            float v3 = sa8 * sb1 * ((float)d1[3] + (float)d23[3] * k);
            *(float2*)(C + (size_t)r * N + c)       = make_float2(v0, v1);
            *(float2*)(C + (size_t)(r + 8) * N + c) = make_float2(v2, v3);
        }
    }
}

// ---------------- fused QKV reduce + RoPE/transpose + split ----------------
__global__ void qkv_post_k(const float* __restrict__ part) {
    __shared__ float tile[64][65];
    int ttile = blockIdx.x, head = blockIdx.y;
    int tid = threadIdx.x;
    int cb;
    if (head < NH)            cb = head * DHD;
    else if (head < NH + NKV) cb = EE + (head - NH) * DHD;
    else                      cb = EE + KVD + (head - NH - NKV) * DHD;
    const int n = TT * QKVN;
    #pragma unroll
    for (int it = 0; it < 16; it++) {
        int i = tid + it * 256;
        int r = i >> 6, c = i & 63;
        size_t idx = (size_t)(ttile * 64 + r) * QKVN + cb + c;
        tile[r][c] = part[idx] + part[idx + n] + part[idx + 2 * (size_t)n];
    }
    __syncthreads();
    if (head < NH + NKV) {
        bf16 *dh, *dl; size_t off;
        if (head < NH) { dh = g_qh; dl = g_ql; off = (size_t)head * TT * DHD; }
        else           { dh = g_kh; dl = g_kl; off = (size_t)(head - NH) * TT * DHD; }
        #pragma unroll
        for (int it = 0; it < 16; it++) {
            int i = tid + it * 256;
            int r = i >> 6, d = i & 63;
            int t = ttile * 64 + r;
            float v;
            if (d < 32) {
                int j = d & 15;
                float theta = powf(10000.0f, -(float)j / 16.0f);
                float ang = (float)t * theta;
                float cs = cosf(ang), sn = sinf(ang);
                if (d < 16) v = tile[r][d] * cs - tile[r][d + 16] * sn;
                else        v = tile[r][d] * cs + tile[r][d - 16] * sn;
            } else v = tile[r][d];
            bf16 h, l; split_bf16(v, h, l);
            size_t o = off + (size_t)t * DHD + d;
            dh[o] = h; dl[o] = l;
        }
    } else {
        int kh = head - NH - NKV;
        #pragma unroll
        for (int it = 0; it < 16; it++) {
            int i = tid + it * 256;
            int d = i >> 6, tc = i & 63;
            float v = tile[tc][d];
            bf16 h, l; split_bf16(v, h, l);
            size_t o = ((size_t)kh * DHD + d) * TT + ttile * 64 + tc;
            g_vth[o] = h; g_vtl[o] = l;
        }
    }
}

// ---------------- HMMA attention scores: 64(t) x 128(s), K=64 ----------------
#define SCSM 49152
__global__ __launch_bounds__(256) void scores_mma() {
    int st = blockIdx.x, tt = blockIdx.y, h = blockIdx.z;
    if (2 * st > tt) return;
    int khid = h >> 2;
    extern __shared__ char dsm[];
    const uint32_t sb = (uint32_t)__cvta_generic_to_shared(dsm);
    const int tid = threadIdx.x;
    const int lane = tid & 31, warp = tid >> 5;

    #pragma unroll
    for (int it = 0; it < 12; it++) {
        int i = tid + it * 256;
        const bf16* src; uint32_t dst;
        if (i < 1024) {
            int sub = i >> 9, w = i & 511, r = w >> 3, c = w & 7;
            src = (sub ? g_ql : g_qh) + ((size_t)h * TT + tt * 64 + r) * DHD + c * 8;
            dst = sub * 8192 + sw_off(r, c);
        } else {
            int j = i - 1024;
            int sub = j >> 10, w = j & 1023, r = w >> 3, c = w & 7;
            src = (sub ? g_kl : g_kh) + ((size_t)khid * TT + st * 128 + r) * DHD + c * 8;
            dst = 16384 + sub * 16384 + sw_off(r, c);
        }
        cp16(sb + dst, src);
    }
    CP_COMMIT(); CP_WAIT(0);
    __syncthreads();

    const int wm = warp & 1, wn = warp >> 1;
    const int lr = lane & 15, lcs = lane >> 4;
    float acc[2][4][4];
    #pragma unroll
    for (int a = 0; a < 2; a++)
        #pragma unroll
        for (int b = 0; b < 4; b++)
            #pragma unroll
            for (int c = 0; c < 4; c++) acc[a][b][c] = 0.f;

    #pragma unroll
    for (int k16 = 0; k16 < 4; k16++) {
        const int cch = k16 * 2 + lcs;
        uint32_t ah[2][4], al[2][4];
        #pragma unroll
        for (int mf = 0; mf < 2; mf++) {
            int row = wm * 32 + mf * 16 + lr;
            uint32_t off = sw_off(row, cch);
            ldsm4(ah[mf], sb + off);
            ldsm4(al[mf], sb + 8192 + off);
        }
        #pragma unroll
        for (int g = 0; g < 2; g++) {
            int row = wn * 32 + g * 16 + lr;
            uint32_t off = sw_off(row, cch);
            uint32_t rh[4], rl[4];
            ldsm4(rh, sb + 16384 + off);
            ldsm4(rl, sb + 32768 + off);
            uint32_t b0h[2] = {rh[0], rh[2]}, b1h[2] = {rh[1], rh[3]};
            uint32_t b0l[2] = {rl[0], rl[2]}, b1l[2] = {rl[1], rl[3]};
            #pragma unroll
            for (int mf = 0; mf < 2; mf++) {
                mma_bf16(acc[mf][g*2], ah[mf], b0h);
                mma_bf16(acc[mf][g*2], ah[mf], b0l);
                mma_bf16(acc[mf][g*2], al[mf], b0h);
                mma_bf16(acc[mf][g*2+1], ah[mf], b1h);
                mma_bf16(acc[mf][g*2+1], ah[mf], b1l);
                mma_bf16(acc[mf][g*2+1], al[mf], b1h);
            }
        }
    }
    float* o = g_att + (size_t)h * TT * TT;
    #pragma unroll
    for (int mf = 0; mf < 2; mf++)
        #pragma unroll
        for (int nf = 0; nf < 4; nf++) {
            int r = tt * 64 + wm * 32 + mf * 16 + (lane >> 2);
            int c = st * 128 + wn * 32 + nf * 8 + (lane & 3) * 2;
            float* d = acc[mf][nf];
            *(float2*)(o + (size_t)r * TT + c)       = make_float2(d[0]*0.125f, d[1]*0.125f);
            *(float2*)(o + (size_t)(r + 8) * TT + c) = make_float2(d[2]*0.125f, d[3]*0.125f);
        }
}

// ---------------- single-pass softmax + gate, writes split-bf16 att ----------------
__global__ void softmax_thresh_k(const float* __restrict__ gate_all, int l) {
    __shared__ float sh[256];
    int t = blockIdx.x, h = blockIdx.y;
    int tid = threadIdx.x;
    const float* p = g_att + (size_t)h * TT * TT + (size_t)t * TT;
    float thr = 1.0f / (1.0f + expf(-gate_all[l * NH + h]));
    float x[4];
    #pragma unroll
    for (int k = 0; k < 4; k++) {
        int i = k * 256 + tid;
        x[k] = (i <= t) ? p[i] : -1e30f;
    }
    float m = fmaxf(fmaxf(x[0], x[1]), fmaxf(x[2], x[3]));
    m = blk_max256(m, sh);
    float e[4], s = 0.f;
    #pragma unroll
    for (int k = 0; k < 4; k++) {
        int i = k * 256 + tid;
        e[k] = (i <= t) ? expf(x[k] - m) : 0.f;
        s += e[k];
    }
    s = blk_sum256(s, sh);
    float inv = 1.0f / s;
    int kend = ((t >> 6) + 1) << 6;
    size_t base = (size_t)h * TT * TT + (size_t)t * TT;
    #pragma unroll
    for (int k = 0; k < 4; k++) {
        int i = k * 256 + tid;
        if (i < kend) {
            float pv = e[k] * inv;
            pv = (pv >= thr) ? pv : 0.f;
            bf16 hh2, ll2; split_bf16(pv, hh2, ll2);
            g_atth[base + i] = hh2;
            g_attl[base + i] = ll2;
        }
    }
}

// ---------------- HMMA AV: 64(t) x 64(d), K-loop over s (largest-K first) ----------------
#define AVSM 65536
__global__ __launch_bounds__(256) void av_mma() {
    int tt = gridDim.x - 1 - blockIdx.x;
    int h = blockIdx.y;
    int khid = h >> 2;
    int St = tt + 1;
    extern __shared__ char dsm[];
    const uint32_t sb = (uint32_t)__cvta_generic_to_shared(dsm);
    const int tid = threadIdx.x;
    const int lane = tid & 31, warp = tid >> 5;
    const int wm = warp & 1, wn = warp >> 1;
    const int lr = lane & 15, lcs = lane >> 4;

    auto load = [&](int s) {
        uint32_t base = sb + (s & 1) * 32768;
        #pragma unroll
        for (int it = 0; it < 8; it++) {
            int i = tid + it * 256;
            const bf16* src; uint32_t dst;
            if (i < 1024) {
                int sub = i >> 9, w = i & 511, r = w >> 3, c = w & 7;
                src = (sub ? g_attl : g_atth) + ((size_t)h * TT + tt * 64 + r) * TT + s * 64 + c * 8;
                dst = base + sub * 8192 + sw_off(r, c);
            } else {
                int j = i - 1024;
                int sub = j >> 9, w = j & 511, r = w >> 3, c = w & 7;
                src = (sub ? g_vtl : g_vth) + ((size_t)khid * DHD + r) * TT + s * 64 + c * 8;
                dst = base + 16384 + sub * 8192 + sw_off(r, c);
            }
            cp16(dst, src);
        }
        CP_COMMIT();
    };

    load(0);
    if (St > 1) load(1);

    float acc[2][2][4];
    #pragma unroll
    for (int a = 0; a < 2; a++)
        #pragma unroll
        for (int b = 0; b < 2; b++)
            #pragma unroll
            for (int c = 0; c < 4; c++) acc[a][b][c] = 0.f;

    for (int s = 0; s < St; s++) {
        if (s + 1 < St) { CP_WAIT(1); } else { CP_WAIT(0); }
        __syncthreads();
        uint32_t base = sb + (s & 1) * 32768;
        #pragma unroll
        for (int k16 = 0; k16 < 4; k16++) {
            const int cch = k16 * 2 + lcs;
            uint32_t ah[2][4], al[2][4];
            #pragma unroll
            for (int mf = 0; mf < 2; mf++) {
                int row = wm * 32 + mf * 16 + lr;
                uint32_t off = sw_off(row, cch);
                ldsm4(ah[mf], base + off);
                ldsm4(al[mf], base + 8192 + off);
            }
            int row = wn * 16 + lr;
            uint32_t off = sw_off(row, cch);
            uint32_t rh[4], rl[4];
            ldsm4(rh, base + 16384 + off);
            ldsm4(rl, base + 24576 + off);
            uint32_t b0h[2] = {rh[0], rh[2]}, b1h[2] = {rh[1], rh[3]};
            uint32_t b0l[2] = {rl[0], rl[2]}, b1l[2] = {rl[1], rl[3]};
            #pragma unroll
            for (int mf = 0; mf < 2; mf++) {
                mma_bf16(acc[mf][0], ah[mf], b0h);
                mma_bf16(acc[mf][0], ah[mf], b0l);
                mma_bf16(acc[mf][0], al[mf], b0h);
                mma_bf16(acc[mf][1], ah[mf], b1h);
                mma_bf16(acc[mf][1], ah[mf], b1l);
                mma_bf16(acc[mf][1], al[mf], b1h);
            }
        }
        __syncthreads();
        if (s + 2 < St) load(s + 2);
    }

    #pragma unroll
    for (int mf = 0; mf < 2; mf++)
        #pragma unroll
        for (int nf = 0; nf < 2; nf++) {
            int r = tt * 64 + wm * 32 + mf * 16 + (lane >> 2);
            int c = h * DHD + wn * 16 + nf * 8 + (lane & 3) * 2;
            float* d = acc[mf][nf];
            bf16 h0, l0, h1, l1, h2, l2, h3, l3;
            split_bf16(d[0], h0, l0); split_bf16(d[1], h1, l1);
            split_bf16(d[2], h2, l2); split_bf16(d[3], h3, l3);
            *(__nv_bfloat162*)(g_yh + (size_t)r * EE + c)       = __halves2bfloat162(h0, h1);
            *(__nv_bfloat162*)(g_yl + (size_t)r * EE + c)       = __halves2bfloat162(l0, l1);
            *(__nv_bfloat162*)(g_yh + (size_t)(r + 8) * EE + c) = __halves2bfloat162(h2, h3);
            *(__nv_bfloat162*)(g_yl + (size_t)(r + 8) * EE + c) = __halves2bfloat162(l2, l3);
        }
}

// ---------------- fused residual-add + layernorm + split (bf16 pair or fp16) ----------------
__global__ void add_ln_split_k(float* __restrict__ x, const float* __restrict__ p,
                               const float* __restrict__ g, const float* __restrict__ b,
                               bf16* __restrict__ oh, bf16* __restrict__ ol,
                               __half* __restrict__ of) {
    __shared__ float sh[256];
    int row = blockIdx.x, tid = threadIdx.x;
    const int n = TT * EE;
    float v[4];
    #pragma unroll
    for (int k = 0; k < 4; k++) {
        int i = row * EE + k * 256 + tid;
        v[k] = x[i] + p[i] + p[i + n];
        x[i] = v[k];
    }
    float mu = blk_sum256(v[0] + v[1] + v[2] + v[3], sh) * (1.0f / EE);
    float vs = 0.f;
    #pragma unroll
    for (int k = 0; k < 4; k++) { float d = v[k] - mu; vs += d * d; }
    float var = blk_sum256(vs, sh) * (1.0f / EE);
    float inv = rsqrtf(var + EPSV);
    #pragma unroll
    for (int k = 0; k < 4; k++) {
        int c = k * 256 + tid;
        float o = (v[k] - mu) * inv * g[c] + b[c];
        if (of) {
            of[row * EE + c] = __float2half_rn(o);
        } else {
            bf16 h, l; split_bf16(o, h, l);
            oh[row * EE + c] = h;
            ol[row * EE + c] = l;
        }
    }
}

// ---------------- final: residual-add + layernorm + int8 2-term quantize ----------------
__global__ void add_ln_quant_k(const float* __restrict__ x, const float* __restrict__ p,
                               const float* __restrict__ g, const float* __restrict__ b) {
    __shared__ float sh[256];
    int row = blockIdx.x, tid = threadIdx.x;
    const int n = TT * EE;
    float v[4];
    #pragma unroll
    for (int k = 0; k < 4; k++) {
        int i = row * EE + tid * 4 + k;
        v[k] = x[i] + p[i] + p[i + n];
    }
    float mu = blk_sum256(v[0] + v[1] + v[2] + v[3], sh) * (1.0f / EE);
    float vs = 0.f;
    #pragma unroll
    for (int k = 0; k < 4; k++) { float d = v[k] - mu; vs += d * d; }
    float var = blk_sum256(vs, sh) * (1.0f / EE);
    float inv = rsqrtf(var + EPSV);
    float o[4], mx = 0.f;
    #pragma unroll
    for (int k = 0; k < 4; k++) {
        int c = tid * 4 + k;
        o[k] = (v[k] - mu) * inv * g[c] + b[c];
        mx = fmaxf(mx, fabsf(o[k]));
    }
    mx = blk_max256(mx, sh);
    float scale = mx * (1.0f / 127.0f) + 1e-30f;
    float inv_s = 1.0f / scale;
    char q1[4], q2[4];
    #pragma unroll
    for (int k = 0; k < 4; k++) quant8(o[k], inv_s, q1[k], q2[k]);
    *(char4*)(g_a1 + row * EE + tid * 4) = make_char4(q1[0], q1[1], q1[2], q1[3]);
    *(char4*)(g_a2 + row * EE + tid * 4) = make_char4(q2[0], q2[1], q2[2], q2[3]);
    if (tid == 0) g_saq[row] = scale;
}

// ---------------- plain layernorm + split (first LN only) ----------------
__global__ void layernorm_split_k(const float* __restrict__ in, bf16* __restrict__ oh,
                                  bf16* __restrict__ ol,
                                  const float* __restrict__ g, const float* __restrict__ b) {
    __shared__ float sh[256];
    int row = blockIdx.x;
    const float* x = in + (size_t)row * EE;
    float s = 0.f;
    for (int i = threadIdx.x; i < EE; i += 256) s += x[i];
    float mu = blk_sum256(s, sh) * (1.0f / EE);
    float vs = 0.f;
    for (int i = threadIdx.x; i < EE; i += 256) { float d = x[i] - mu; vs += d * d; }
    float var = blk_sum256(vs, sh) * (1.0f / EE);
    float inv = rsqrtf(var + EPSV);
    for (int i = threadIdx.x; i < EE; i += 256) {
        float v = (x[i] - mu) * inv * g[i] + b[i];
        bf16 h, l; split_bf16(v, h, l);
        oh[(size_t)row * EE + i] = h;
        ol[(size_t)row * EE + i] = l;
    }
}

// ---------------- weight transpose + split (bf16) ----------------
__global__ void wtsplit_k(const float* __restrict__ W, bf16* __restrict__ Th,
                          bf16* __restrict__ Tl, int K, int N, int ldt) {
    __shared__ float t[32][33];
    int n0 = blockIdx.x * 32, k0 = blockIdx.y * 32;
    int tx = threadIdx.x, ty = threadIdx.y;
    #pragma unroll
    for (int r = ty; r < 32; r += 8)
        t[r][tx] = W[(size_t)(k0 + r) * N + n0 + tx];
    __syncthreads();
    #pragma unroll
    for (int r = ty; r < 32; r += 8) {
        float v = t[tx][r];
        bf16 h, l; split_bf16(v, h, l);
        Th[(size_t)(n0 + r) * ldt + k0 + tx] = h;
        Tl[(size_t)(n0 + r) * ldt + k0 + tx] = l;
    }
}

// ---------------- weight transpose + split (fp16) ----------------
__global__ void wtsplit_f16_k(const float* __restrict__ W, __half* __restrict__ Th,
                              __half* __restrict__ Tl, int K, int N, int ldt) {
    __shared__ float t[32][33];
    int n0 = blockIdx.x * 32, k0 = blockIdx.y * 32;
    int tx = threadIdx.x, ty = threadIdx.y;
    #pragma unroll
    for (int r = ty; r < 32; r += 8)
        t[r][tx] = W[(size_t)(k0 + r) * N + n0 + tx];
    __syncthreads();
    #pragma unroll
    for (int r = ty; r < 32; r += 8) {
        float v = t[tx][r];
        __half h, l; split_fp16(v, h, l);
        Th[(size_t)(n0 + r) * ldt + k0 + tx] = h;
        Tl[(size_t)(n0 + r) * ldt + k0 + tx] = l;
    }
}

// ---------------- embed quantize: int8 2-term per vocab row ----------------
__global__ void equant_k(const float* __restrict__ E) {
    __shared__ float sh[256];
    int row = blockIdx.x, tid = threadIdx.x;
    float4 v = *(const float4*)(E + (size_t)row * EE + tid * 4);
    float mx = fmaxf(fmaxf(fabsf(v.x), fabsf(v.y)), fmaxf(fabsf(v.z), fabsf(v.w)));
    mx = blk_max256(mx, sh);
    float scale = mx * (1.0f / 127.0f) + 1e-30f;
    float inv_s = 1.0f / scale;
    char q1[4], q2[4];
    quant8(v.x, inv_s, q1[0], q2[0]);
    quant8(v.y, inv_s, q1[1], q2[1]);
    quant8(v.z, inv_s, q1[2], q2[2]);
    quant8(v.w, inv_s, q1[3], q2[3]);
    *(char4*)(g_e1 + (size_t)row * EE + tid * 4) = make_char4(q1[0], q1[1], q1[2], q1[3]);
    *(char4*)(g_e2 + (size_t)row * EE + tid * 4) = make_char4(q2[0], q2[1], q2[2], q2[3]);
    if (tid == 0) g_sbv[row] = scale;
}

// ---------------- embedding gather ----------------
__global__ void gather_embed_k(const float* __restrict__ embed, const int* __restrict__ idx) {
    int i = blockIdx.x * blockDim.x + threadIdx.x;
    int t = i >> 10, e = i & 1023;
    g_x[i] = embed[(size_t)idx[t] * EE + e];
}

// ---------------- loss: single-pass online softmax ----------------
__global__ void zero_loss_k() { g_loss = 0.f; }

__global__ void loss_rows_k(const float* __restrict__ logits, const int* __restrict__ targets) {
    __shared__ float shm[256], shs[256];
    int t = blockIdx.x, tid = threadIdx.x;
    const float* row = logits + (size_t)t * VV;
    float m = -1e30f, s = 0.f;
    for (int i = tid; i < VV; i += 256) {
        float v = row[i];
        if (v > m) { s = s * expf(m - v) + 1.f; m = v; }
        else       { s += expf(v - m); }
    }
    shm[tid] = m; shs[tid] = s; __syncthreads();
    #pragma unroll
    for (int st = 128; st > 0; st >>= 1) {
        if (tid < st) {
            float m2 = shm[tid + st], s2 = shs[tid + st];
            float M = fmaxf(shm[tid], m2);
            shs[tid] = shs[tid] * expf(shm[tid] - M) + s2 * expf(m2 - M);
            shm[tid] = M;
        }
        __syncthreads();
    }
    if (tid == 0) {
        float lp = row[targets[t]] - shm[0] - logf(shs[0]);
        atomicAdd(&g_loss, -lp);
    }
}

__global__ void loss_fin_k(float* dst) { *dst = g_loss * (1.0f / (float)TT); }

// ---------------- host orchestration ----------------
extern "C" void kernel_launch(void* const* d_in, const int* in_sizes, int n_in,
                              void* d_out, int out_size) {
    const float* embed = (const float*)d_in[0];
    const float* ln1_g = (const float*)d_in[1];
    const float* ln1_b = (const float*)d_in[2];
    const float* Wq    = (const float*)d_in[3];
    const float* Wk    = (const float*)d_in[4];
    const float* Wv    = (const float*)d_in[5];
    const float* Wo    = (const float*)d_in[6];
    const float* gate  = (const float*)d_in[7];
    const float* ln2_g = (const float*)d_in[8];
    const float* ln2_b = (const float*)d_in[9];
    const float* W1    = (const float*)d_in[10];
    const float* W2    = (const float*)d_in[11];
    const float* lnf_g = (const float*)d_in[12];
    const float* lnf_b = (const float*)d_in[13];
    const int*   idx   = (const int*)d_in[14];
    const int*   tgt   = (const int*)d_in[15];

    float *xp, *logp, *partp, *saqp, *sbvp;
    bf16 *hh, *hl, *yh, *yl;
    bf16 *wqkvh, *wqkvl, *woh, *wol;
    __half *hf, *fff, *w1fh, *w1fl, *w2fh, *w2fl;
    char *a1p, *a2p, *e1p, *e2p;
    cudaGetSymbolAddress((void**)&xp,    g_x);
    cudaGetSymbolAddress((void**)&logp,  g_logits);
    cudaGetSymbolAddress((void**)&partp, g_part);
    cudaGetSymbolAddress((void**)&hh,    g_hh);
    cudaGetSymbolAddress((void**)&hl,    g_hl);
    cudaGetSymbolAddress((void**)&hf,    g_hf);
    cudaGetSymbolAddress((void**)&fff,   g_fff);
    cudaGetSymbolAddress((void**)&yh,    g_yh);
    cudaGetSymbolAddress((void**)&yl,    g_yl);
    cudaGetSymbolAddress((void**)&wqkvh, g_wqkv_h);
    cudaGetSymbolAddress((void**)&wqkvl, g_wqkv_l);
    cudaGetSymbolAddress((void**)&woh,   g_wo_h);
    cudaGetSymbolAddress((void**)&wol,   g_wo_l);
    cudaGetSymbolAddress((void**)&w1fh,  g_w1fh);
    cudaGetSymbolAddress((void**)&w1fl,  g_w1fl);
    cudaGetSymbolAddress((void**)&w2fh,  g_w2fh);
    cudaGetSymbolAddress((void**)&w2fl,  g_w2fl);
    cudaGetSymbolAddress((void**)&a1p,   g_a1);
    cudaGetSymbolAddress((void**)&a2p,   g_a2);
    cudaGetSymbolAddress((void**)&e1p,   g_e1);
    cudaGetSymbolAddress((void**)&e2p,   g_e2);
    cudaGetSymbolAddress((void**)&saqp,  g_saq);
    cudaGetSymbolAddress((void**)&sbvp,  g_sbv);

    cudaFuncSetAttribute(gemm_mma<0,128,3>, cudaFuncAttributeMaxDynamicSharedMemorySize, GSM128);
    cudaFuncSetAttribute(fp16_mma<0,128,3>, cudaFuncAttributeMaxDynamicSharedMemorySize, F16SM128);
    cudaFuncSetAttribute(fp16_mma<2,256,2>, cudaFuncAttributeMaxDynamicSharedMemorySize, F16SM256);
    cudaFuncSetAttribute(logits_i8, cudaFuncAttributeMaxDynamicSharedMemorySize, LI8SM);
    cudaFuncSetAttribute(scores_mma, cudaFuncAttributeMaxDynamicSharedMemorySize, SCSM);
    cudaFuncSetAttribute(av_mma, cudaFuncAttributeMaxDynamicSharedMemorySize, AVSM);

    // side stream + events (host-side objects, created once)
    static cudaStream_t s2 = nullptr;
    static cudaEvent_t ev_fork = nullptr, ev_w0 = nullptr, ev_w1 = nullptr, ev_e = nullptr;
    if (!s2) {
        cudaStreamCreateWithFlags(&s2, cudaStreamNonBlocking);
        cudaEventCreateWithFlags(&ev_fork, cudaEventDisableTiming);
        cudaEventCreateWithFlags(&ev_w0, cudaEventDisableTiming);
        cudaEventCreateWithFlags(&ev_w1, cudaEventDisableTiming);
        cudaEventCreateWithFlags(&ev_e, cudaEventDisableTiming);
    }

    const size_t BTV = (size_t)TT * VV;
    float* logits_dst = ((size_t)out_size >= BTV) ? (float*)d_out : logp;
    float* loss_dst = nullptr;
    if ((size_t)out_size > BTV)      loss_dst = (float*)d_out + BTV;
    else if ((size_t)out_size < BTV) loss_dst = (float*)d_out;

    dim3 tb(32, 8);

    // ---- fork: non-immediate preprocessing on s2 ----
    cudaEventRecord(ev_fork, 0);
    cudaStreamWaitEvent(s2, ev_fork, 0);

    wtsplit_k<<<dim3(EE/32, EE/32), tb, 0, s2>>>(Wo, woh, wol, EE, EE, EE);
    wtsplit_f16_k<<<dim3(FF/32, EE/32), tb, 0, s2>>>(W1, w1fh, w1fl, EE, FF, EE);
    wtsplit_f16_k<<<dim3(EE/32, FF/32), tb, 0, s2>>>(W2, w2fh, w2fl, FF, EE, FF);
    cudaEventRecord(ev_w0, s2);
    {
        const int l = 1;
        wtsplit_k<<<dim3(EE/32, EE/32), tb, 0, s2>>>(Wq + (size_t)l*EE*EE,
            wqkvh + (size_t)l*QKVN*EE, wqkvl + (size_t)l*QKVN*EE, EE, EE, EE);
        wtsplit_k<<<dim3(KVD/32, EE/32), tb, 0, s2>>>(Wk + (size_t)l*EE*KVD,
            wqkvh + (size_t)l*QKVN*EE + (size_t)EE*EE, wqkvl + (size_t)l*QKVN*EE + (size_t)EE*EE, EE, KVD, EE);
        wtsplit_k<<<dim3(KVD/32, EE/32), tb, 0, s2>>>(Wv + (size_t)l*EE*KVD,
            wqkvh + (size_t)l*QKVN*EE + (size_t)(EE+KVD)*EE, wqkvl + (size_t)l*QKVN*EE + (size_t)(EE+KVD)*EE, EE, KVD, EE);
        wtsplit_k<<<dim3(EE/32, EE/32), tb, 0, s2>>>(Wo + (size_t)l*EE*EE,
            woh + (size_t)l*EE*EE, wol + (size_t)l*EE*EE, EE, EE, EE);
        wtsplit_f16_k<<<dim3(FF/32, EE/32), tb, 0, s2>>>(W1 + (size_t)l*EE*FF,
            w1fh + (size_t)l*FF*EE, w1fl + (size_t)l*FF*EE, EE, FF, EE);
        wtsplit_f16_k<<<dim3(EE/32, FF/32), tb, 0, s2>>>(W2 + (size_t)l*FF*EE,
            w2fh + (size_t)l*EE*FF, w2fl + (size_t)l*EE*FF, FF, EE, FF);
    }
    cudaEventRecord(ev_w1, s2);
    equant_k<<<VV, 256, 0, s2>>>(embed);
    cudaEventRecord(ev_e, s2);

    // ---- main stream: critical path ----
    wtsplit_k<<<dim3(EE/32, EE/32), tb>>>(Wq, wqkvh, wqkvl, EE, EE, EE);
    wtsplit_k<<<dim3(KVD/32, EE/32), tb>>>(Wk, wqkvh + (size_t)EE*EE, wqkvl + (size_t)EE*EE, EE, KVD, EE);
    wtsplit_k<<<dim3(KVD/32, EE/32), tb>>>(Wv, wqkvh + (size_t)(EE+KVD)*EE, wqkvl + (size_t)(EE+KVD)*EE, EE, KVD, EE);
    gather_embed_k<<<(TT * EE) / 256, 256>>>(embed, idx);
    layernorm_split_k<<<TT, 256>>>(xp, hh, hl, ln1_g, ln1_b);

    for (int it = 0; it < RNUM * LNUM; it++) {
        int l = it % LNUM;
        if (it == 1) cudaStreamWaitEvent(0, ev_w1, 0);
        // QKV: 3-term bf16, split-K=3
        gemm_mma<0,128,3><<<dim3(TT/128, QKVN/128, 3), 256, GSM128>>>(hh, hl,
            wqkvh + (size_t)l*QKVN*EE, wqkvl + (size_t)l*QKVN*EE,
            partp, nullptr, nullptr, nullptr, QKVN, EE);
        qkv_post_k<<<dim3(TT/64, NH + 2*NKV), 256>>>(partp);
        scores_mma<<<dim3(TT/128, TT/64, NH), 256, SCSM>>>();
        softmax_thresh_k<<<dim3(TT, NH), 256>>>(gate, l);
        av_mma<<<dim3(TT/64, NH), 256, AVSM>>>();
        if (it == 0) cudaStreamWaitEvent(0, ev_w0, 0);
        // Wo: 3-term bf16, split-K=2; fused x+= & LN2 (fp16 single out for FFN1)
        gemm_mma<0,128,3><<<dim3(TT/128, EE/128, 2), 256, GSM128>>>(yh, yl,
            woh + (size_t)l*EE*EE, wol + (size_t)l*EE*EE,
            partp, nullptr, nullptr, nullptr, EE, EE);
        add_ln_split_k<<<TT, 256>>>(xp, partp, ln2_g + l * EE, ln2_b + l * EE,
                                    nullptr, nullptr, hf);
        // FFN1: fp16 2-term, gelu -> fp16 single
        fp16_mma<2,256,2><<<dim3(TT/128, FF/256, 1), 256, F16SM256>>>(hf,
            w1fh + (size_t)l*FF*EE, w1fl + (size_t)l*FF*EE,
            nullptr, fff, FF, EE);
        // FFN2: fp16 2-term, split-K=2 -> partials
        fp16_mma<0,128,3><<<dim3(TT/128, EE/128, 2), 256, F16SM128>>>(fff,
            w2fh + (size_t)l*EE*FF, w2fl + (size_t)l*EE*FF,
            partp, nullptr, EE, FF);
        if (it == RNUM * LNUM - 1) {
            // final: fused x+= & LNf -> int8 2-term quantized A for logits
            add_ln_quant_k<<<TT, 256>>>(xp, partp, lnf_g, lnf_b);
        } else {
            int ln = (l + 1) % LNUM;
            add_ln_split_k<<<TT, 256>>>(xp, partp, ln1_g + ln * EE, ln1_b + ln * EE,
                                        hh, hl, nullptr);
        }
    }

    // logits: int8 2-term GEMM (3 s8 MMAs per k32)
    cudaStreamWaitEvent(0, ev_e, 0);
    logits_i8<<<dim3(TT/128, VV/128), 256, LI8SM>>>(a1p, a2p, e1p, e2p,
        saqp, sbvp, logits_dst);

    zero_loss_k<<<1, 1>>>();
    loss_rows_k<<<TT, 256>>>(logits_dst, tgt);
    if (loss_dst) loss_fin_k<<<1, 1>>>(loss_dst);
}

// round 12
// speedup vs baseline: 1.6741x; 1.6741x over previous
#include <cuda_runtime.h>
#include <cuda_bf16.h>
#include <cuda_fp16.h>
#include <math.h>
#include <stdint.h>

// ---------------- problem constants ----------------
#define TT 1024
#define EE 1024
#define VV 32000
#define NH 16
#define NKV 4
#define DHD 64
#define KVD (NKV*DHD)     // 256
#define QKVN 1536
#define LNUM 2
#define RNUM 2
#define FF 4096
#define EPSV 1e-5f

typedef __nv_bfloat16 bf16;

// ---------------- device scratch ----------------
__device__ float g_x[TT*EE];
__device__ bf16  g_hh[TT*EE], g_hl[TT*EE];
__device__ __half g_hf[TT*EE];                         // fp16 LN output (LN2 / final)
__device__ __half g_fff[TT*FF];                        // fp16 gelu(FFN1) output
__device__ float g_att[(size_t)NH*TT*TT];
__device__ bf16  g_atth[(size_t)NH*TT*TT], g_attl[(size_t)NH*TT*TT];
__device__ float g_part[3*TT*QKVN];          // split-K partials (reused)
__device__ bf16  g_qh[NH*TT*DHD],  g_ql[NH*TT*DHD];
__device__ bf16  g_kh[NKV*TT*DHD], g_kl[NKV*TT*DHD];
__device__ bf16  g_vth[NKV*DHD*TT], g_vtl[NKV*DHD*TT];   // transposed V
__device__ __half g_yf[TT*EE];                           // fp16 attention output
__device__ bf16  g_wqkv_h[LNUM*QKVN*EE], g_wqkv_l[LNUM*QKVN*EE];
__device__ __half g_wofh[LNUM*EE*EE],    g_wofl[LNUM*EE*EE];   // fp16 hi/lo Wo
__device__ __half g_w1fh[LNUM*FF*EE],    g_w1fl[LNUM*FF*EE];   // fp16 hi/lo W1
__device__ __half g_w2fh[LNUM*EE*FF],    g_w2fl[LNUM*EE*FF];   // fp16 hi/lo W2
__device__ __half g_efh[(size_t)VV*EE],  g_efl[(size_t)VV*EE]; // fp16 hi/lo embed
__device__ float g_logits[(size_t)TT*VV];
__device__ float g_loss;

// ---------------- generic helpers ----------------
__device__ __forceinline__ float blk_sum256(float v, float* sh) {
    int tid = threadIdx.x;
    sh[tid] = v; __syncthreads();
    #pragma unroll
    for (int s = 128; s > 0; s >>= 1) { if (tid < s) sh[tid] += sh[tid + s]; __syncthreads(); }
    float r = sh[0]; __syncthreads();
    return r;
}
__device__ __forceinline__ float blk_max256(float v, float* sh) {
    int tid = threadIdx.x;
    sh[tid] = v; __syncthreads();
    #pragma unroll
    for (int s = 128; s > 0; s >>= 1) { if (tid < s) sh[tid] = fmaxf(sh[tid], sh[tid + s]); __syncthreads(); }
    float r = sh[0]; __syncthreads();
    return r;
}
__device__ __forceinline__ float gelu_exact(float x) {
    return 0.5f * x * (1.0f + erff(x * 0.7071067811865476f));
}
__device__ __forceinline__ void split_bf16(float v, bf16& h, bf16& l) {
    h = __float2bfloat16(v);
    l = __float2bfloat16(v - __bfloat162float(h));
}
__device__ __forceinline__ void split_fp16(float v, __half& h, __half& l) {
    h = __float2half_rn(v);
    l = __float2half_rn(v - __half2float(h));
}
// MUFU-free exp: rint range reduction + degree-5 Taylor, rel err ~3e-6
__device__ __forceinline__ float fast_exp(float v) {
    float t = v * 1.44269504f;
    t = fmaxf(t, -120.0f);
    float r = rintf(t);
    float f = (t - r) * 0.69314718f;   // |f| <= 0.3466
    float p = 1.0f + f * (1.0f + f * (0.5f + f * (0.166666667f
             + f * (0.0416666667f + f * 0.00833333333f))));
    return __int_as_float(((int)(127.0f + r)) << 23) * p;
}

// ---------------- PTX wrappers ----------------
__device__ __forceinline__ void mma_bf16(float* d, const uint32_t* a, const uint32_t* b) {
    asm volatile("mma.sync.aligned.m16n8k16.row.col.f32.bf16.bf16.f32 "
        "{%0,%1,%2,%3}, {%4,%5,%6,%7}, {%8,%9}, {%0,%1,%2,%3};"
        : "+f"(d[0]), "+f"(d[1]), "+f"(d[2]), "+f"(d[3])
        : "r"(a[0]), "r"(a[1]), "r"(a[2]), "r"(a[3]), "r"(b[0]), "r"(b[1]));
}
__device__ __forceinline__ void mma_fp16(float* d, const uint32_t* a, const uint32_t* b) {
    asm volatile("mma.sync.aligned.m16n8k16.row.col.f32.f16.f16.f32 "
        "{%0,%1,%2,%3}, {%4,%5,%6,%7}, {%8,%9}, {%0,%1,%2,%3};"
        : "+f"(d[0]), "+f"(d[1]), "+f"(d[2]), "+f"(d[3])
        : "r"(a[0]), "r"(a[1]), "r"(a[2]), "r"(a[3]), "r"(b[0]), "r"(b[1]));
}
__device__ __forceinline__ void ldsm4(uint32_t* r, uint32_t addr) {
    asm volatile("ldmatrix.sync.aligned.m8n8.x4.shared.b16 {%0,%1,%2,%3}, [%4];"
        : "=r"(r[0]), "=r"(r[1]), "=r"(r[2]), "=r"(r[3]) : "r"(addr));
}
__device__ __forceinline__ void cp16(uint32_t s, const void* g) {
    asm volatile("cp.async.cg.shared.global [%0], [%1], 16;" :: "r"(s), "l"(g));
}
#define CP_COMMIT()  asm volatile("cp.async.commit_group;")
#define CP_WAIT(n)   asm volatile("cp.async.wait_group %0;" :: "n"(n))

// SW128 swizzle: 128B rows, 16B chunks, chunk ^= row&7  (conflict-free ldmatrix)
__device__ __forceinline__ uint32_t sw_off(int row, int chunk) {
    return (uint32_t)(row * 128 + ((chunk ^ (row & 7)) << 4));
}

// ---------------- split-bf16 3-term HMMA GEMM (QKV) ----------------
template<int MODE, int TN, int NSTG>
__global__ __launch_bounds__(256, 1) void gemm_mma(
    const bf16* __restrict__ Ah, const bf16* __restrict__ Al,
    const bf16* __restrict__ Bh, const bf16* __restrict__ Bl,
    float* C, const float* Rs, bf16* Oh, bf16* Ol,
    int N, int K)
{
    constexpr int TSA = 128 * 128;
    constexpr int TSB = TN * 128;
    constexpr int SB  = 2 * TSA + 2 * TSB;
    constexpr int BCH = TN * 8;
    constexpr int TC  = 2048 + 2 * BCH;
    constexpr int NG  = TN / 64;
    constexpr int NF  = 2 * NG;

    extern __shared__ char dsm[];
    const int tid = threadIdx.x;
    const int lane = tid & 31, warp = tid >> 5;
    const int wm = warp & 1, wn = warp >> 1;
    const int row0 = blockIdx.x * 128, col0 = blockIdx.y * TN;
    const uint32_t sb = (uint32_t)__cvta_generic_to_shared(dsm);

    float acc[4][NF][4];
    #pragma unroll
    for (int i = 0; i < 4; i++)
        #pragma unroll
        for (int j = 0; j < NF; j++)
            #pragma unroll
            for (int r = 0; r < 4; r++) acc[i][j][r] = 0.f;

    auto load_stage = [&](int s) {
        int k0 = s * 64;
        uint32_t base = sb + (s % NSTG) * SB;
        #pragma unroll
        for (int ii = 0; ii < TC / 256; ii++) {
            int i = tid + ii * 256;
            const bf16* src;
            uint32_t toff;
            if (i < 2048) {
                int t = i >> 10, w = i & 1023;
                int r = w >> 3, c = w & 7;
                src = (t ? Al : Ah) + (size_t)(row0 + r) * K + k0 + c * 8;
                toff = t * TSA + sw_off(r, c);
            } else {
                int j = i - 2048;
                int t = j / BCH, w = j & (BCH - 1);
                int r = w >> 3, c = w & 7;
                src = (t ? Bl : Bh) + (size_t)(col0 + r) * K + k0 + c * 8;
                toff = 2 * TSA + t * TSB + sw_off(r, c);
            }
            cp16(base + toff, src);
        }
        CP_COMMIT();
    };

    const int Stot = K >> 6;
    const int SK = gridDim.z;
    const int Sc = (Stot + SK - 1) / SK;
    const int s0 = blockIdx.z * Sc;
    const int s1 = min(Stot, s0 + Sc);

    #pragma unroll
    for (int i = 0; i < NSTG; i++)
        if (s0 + i < s1) load_stage(s0 + i);

    const int lr = lane & 15, lcs = lane >> 4;

    for (int s = s0; s < s1; s++) {
        int ahead = s1 - 1 - s;
        int w = ahead < (NSTG - 1) ? ahead : (NSTG - 1);
        if (w == 2)      { CP_WAIT(2); }
        else if (w == 1) { CP_WAIT(1); }
        else             { CP_WAIT(0); }
        __syncthreads();
        uint32_t ab = sb + (s % NSTG) * SB;
        #pragma unroll
        for (int k16 = 0; k16 < 4; k16++) {
            const int cch = k16 * 2 + lcs;
            uint32_t ah[4][4], al[4][4];
            #pragma unroll
            for (int mf = 0; mf < 4; mf++) {
                int row = wm * 64 + mf * 16 + lr;
                uint32_t off = sw_off(row, cch);
                ldsm4(ah[mf], ab + off);
                ldsm4(al[mf], ab + TSA + off);
            }
            #pragma unroll
            for (int g = 0; g < NG; g++) {
                int row = wn * (TN / 4) + g * 16 + lr;
                uint32_t off = sw_off(row, cch);
                uint32_t rh[4], rl[4];
                ldsm4(rh, ab + 2 * TSA + off);
                ldsm4(rl, ab + 2 * TSA + TSB + off);
                uint32_t b0h[2] = {rh[0], rh[2]}, b1h[2] = {rh[1], rh[3]};
                uint32_t b0l[2] = {rl[0], rl[2]}, b1l[2] = {rl[1], rl[3]};
                #pragma unroll
                for (int mf = 0; mf < 4; mf++) {
                    mma_bf16(acc[mf][g*2], ah[mf], b0h);
                    mma_bf16(acc[mf][g*2], ah[mf], b0l);
                    mma_bf16(acc[mf][g*2], al[mf], b0h);
                    mma_bf16(acc[mf][g*2+1], ah[mf], b1h);
                    mma_bf16(acc[mf][g*2+1], ah[mf], b1l);
                    mma_bf16(acc[mf][g*2+1], al[mf], b1h);
                }
            }
        }
        __syncthreads();
        if (s + NSTG < s1) load_stage(s + NSTG);
    }

    const size_t pstride = (size_t)gridDim.x * 128 * N;
    float* Cp = C + (size_t)blockIdx.z * pstride;
    #pragma unroll
    for (int mf = 0; mf < 4; mf++)
        #pragma unroll
        for (int nf = 0; nf < NF; nf++) {
            int r = row0 + wm * 64 + mf * 16 + (lane >> 2);
            int c = col0 + wn * (TN / 4) + nf * 8 + (lane & 3) * 2;
            float* d = acc[mf][nf];
            *(float2*)(Cp + (size_t)r * N + c)       = make_float2(d[0], d[1]);
            *(float2*)(Cp + (size_t)(r + 8) * N + c) = make_float2(d[2], d[3]);
        }
}

#define GSM128 (3 * (2*128*128 + 2*128*128))   // 196608

// ---------------- fp16 2-term GEMM (Wo / FFN / logits): C = A * (Bh+Bl)^T ----------------
template<int MODE, int TN, int NSTG>
__global__ __launch_bounds__(256, 1) void fp16_mma(
    const __half* __restrict__ A, const __half* __restrict__ Bh,
    const __half* __restrict__ Bl, float* __restrict__ C,
    __half* __restrict__ Of, int N, int K)
{
    constexpr int TSA = 128 * 128;
    constexpr int TSB = TN * 128;
    constexpr int SB  = TSA + 2 * TSB;
    constexpr int BCH = TN * 8;
    constexpr int TC  = 1024 + 2 * BCH;
    constexpr int NG  = TN / 64;
    constexpr int NF  = 2 * NG;

    extern __shared__ char dsm[];
    const int tid = threadIdx.x;
    const int lane = tid & 31, warp = tid >> 5;
    const int wm = warp & 1, wn = warp >> 1;
    const int row0 = blockIdx.x * 128, col0 = blockIdx.y * TN;
    const uint32_t sb = (uint32_t)__cvta_generic_to_shared(dsm);

    float acc[4][NF][4];
    #pragma unroll
    for (int i = 0; i < 4; i++)
        #pragma unroll
        for (int j = 0; j < NF; j++)
            #pragma unroll
            for (int r = 0; r < 4; r++) acc[i][j][r] = 0.f;

    auto load_stage = [&](int s) {
        int k0 = s * 64;
        uint32_t base = sb + (s % NSTG) * SB;
        #pragma unroll
        for (int ii = 0; ii < TC / 256; ii++) {
            int i = tid + ii * 256;
            const __half* src; uint32_t toff;
            if (i < 1024) {
                int r = i >> 3, c = i & 7;
                src = A + (size_t)(row0 + r) * K + k0 + c * 8;
                toff = sw_off(r, c);
            } else {
                int j = i - 1024;
                int t = j / BCH, w = j & (BCH - 1);
                int r = w >> 3, c = w & 7;
                src = (t ? Bl : Bh) + (size_t)(col0 + r) * K + k0 + c * 8;
                toff = TSA + t * TSB + sw_off(r, c);
            }
            cp16(base + toff, src);
        }
        CP_COMMIT();
    };

    const int Stot = K >> 6;
    const int SK = gridDim.z;
    const int Sc = (Stot + SK - 1) / SK;
    const int s0 = blockIdx.z * Sc;
    const int s1 = min(Stot, s0 + Sc);

    #pragma unroll
    for (int i = 0; i < NSTG; i++)
        if (s0 + i < s1) load_stage(s0 + i);

    const int lr = lane & 15, lcs = lane >> 4;

    for (int s = s0; s < s1; s++) {
        int ahead = s1 - 1 - s;
        int w = ahead < (NSTG - 1) ? ahead : (NSTG - 1);
        if (w == 2)      { CP_WAIT(2); }
        else if (w == 1) { CP_WAIT(1); }
        else             { CP_WAIT(0); }
        __syncthreads();
        uint32_t ab = sb + (s % NSTG) * SB;
        #pragma unroll
        for (int k16 = 0; k16 < 4; k16++) {
            const int cch = k16 * 2 + lcs;
            uint32_t ah[4][4];
            #pragma unroll
            for (int mf = 0; mf < 4; mf++)
                ldsm4(ah[mf], ab + sw_off(wm * 64 + mf * 16 + lr, cch));
            #pragma unroll
            for (int g = 0; g < NG; g++) {
                uint32_t off = sw_off(wn * (TN / 4) + g * 16 + lr, cch);
                uint32_t rh[4], rl[4];
                ldsm4(rh, ab + TSA + off);
                ldsm4(rl, ab + TSA + TSB + off);
                uint32_t b0h[2] = {rh[0], rh[2]}, b1h[2] = {rh[1], rh[3]};
                uint32_t b0l[2] = {rl[0], rl[2]}, b1l[2] = {rl[1], rl[3]};
                #pragma unroll
                for (int mf = 0; mf < 4; mf++) {
                    mma_fp16(acc[mf][g*2], ah[mf], b0h);
                    mma_fp16(acc[mf][g*2], ah[mf], b0l);
                    mma_fp16(acc[mf][g*2+1], ah[mf], b1h);
                    mma_fp16(acc[mf][g*2+1], ah[mf], b1l);
                }
            }
        }
        __syncthreads();
        if (s + NSTG < s1) load_stage(s + NSTG);
    }

    const size_t pstride = (size_t)gridDim.x * 128 * N;
    float* Cp = C + (size_t)blockIdx.z * pstride;
    #pragma unroll
    for (int mf = 0; mf < 4; mf++)
        #pragma unroll
        for (int nf = 0; nf < NF; nf++) {
            int r = row0 + wm * 64 + mf * 16 + (lane >> 2);
            int c = col0 + wn * (TN / 4) + nf * 8 + (lane & 3) * 2;
            float* d = acc[mf][nf];
            if (MODE == 0) {
                *(float2*)(Cp + (size_t)r * N + c)       = make_float2(d[0], d[1]);
                *(float2*)(Cp + (size_t)(r + 8) * N + c) = make_float2(d[2], d[3]);
            } else {
                __half o0 = __float2half_rn(gelu_exact(d[0]));
                __half o1 = __float2half_rn(gelu_exact(d[1]));
                __half o2 = __float2half_rn(gelu_exact(d[2]));
                __half o3 = __float2half_rn(gelu_exact(d[3]));
                *(__half2*)(Of + (size_t)r * N + c)       = __halves2half2(o0, o1);
                *(__half2*)(Of + (size_t)(r + 8) * N + c) = __halves2half2(o2, o3);
            }
        }
}

#define F16SM128 (3 * (128*128 + 2*128*128))   // 147456
#define F16SM256 (2 * (128*128 + 2*256*128))   // 163840

// ---------------- fused QKV reduce + RoPE/transpose + split ----------------
__global__ void qkv_post_k(const float* __restrict__ part) {
    __shared__ float tile[64][65];
    int ttile = blockIdx.x, head = blockIdx.y;
    int tid = threadIdx.x;
    int cb;
    if (head < NH)            cb = head * DHD;
    else if (head < NH + NKV) cb = EE + (head - NH) * DHD;
    else                      cb = EE + KVD + (head - NH - NKV) * DHD;
    const int n = TT * QKVN;
    #pragma unroll
    for (int it = 0; it < 16; it++) {
        int i = tid + it * 256;
        int r = i >> 6, c = i & 63;
        size_t idx = (size_t)(ttile * 64 + r) * QKVN + cb + c;
        tile[r][c] = part[idx] + part[idx + n] + part[idx + 2 * (size_t)n];
    }
    __syncthreads();
    if (head < NH + NKV) {
        bf16 *dh, *dl; size_t off;
        if (head < NH) { dh = g_qh; dl = g_ql; off = (size_t)head * TT * DHD; }
        else           { dh = g_kh; dl = g_kl; off = (size_t)(head - NH) * TT * DHD; }
        #pragma unroll
        for (int it = 0; it < 16; it++) {
            int i = tid + it * 256;
            int r = i >> 6, d = i & 63;
            int t = ttile * 64 + r;
            float v;
            if (d < 32) {
                int j = d & 15;
                float theta = powf(10000.0f, -(float)j / 16.0f);
                float ang = (float)t * theta;
                float cs = cosf(ang), sn = sinf(ang);
                if (d < 16) v = tile[r][d] * cs - tile[r][d + 16] * sn;
                else        v = tile[r][d] * cs + tile[r][d - 16] * sn;
            } else v = tile[r][d];
            bf16 h, l; split_bf16(v, h, l);
            size_t o = off + (size_t)t * DHD + d;
            dh[o] = h; dl[o] = l;
        }
    } else {
        int kh = head - NH - NKV;
        #pragma unroll
        for (int it = 0; it < 16; it++) {
            int i = tid + it * 256;
            int d = i >> 6, tc = i & 63;
            float v = tile[tc][d];
            bf16 h, l; split_bf16(v, h, l);
            size_t o = ((size_t)kh * DHD + d) * TT + ttile * 64 + tc;
            g_vth[o] = h; g_vtl[o] = l;
        }
    }
}

// ---------------- HMMA attention scores: 64(t) x 128(s), K=64 ----------------
#define SCSM 49152
__global__ __launch_bounds__(256) void scores_mma() {
    int st = blockIdx.x, tt = blockIdx.y, h = blockIdx.z;
    if (2 * st > tt) return;
    int khid = h >> 2;
    extern __shared__ char dsm[];
    const uint32_t sb = (uint32_t)__cvta_generic_to_shared(dsm);
    const int tid = threadIdx.x;
    const int lane = tid & 31, warp = tid >> 5;

    #pragma unroll
    for (int it = 0; it < 12; it++) {
        int i = tid + it * 256;
        const bf16* src; uint32_t dst;
        if (i < 1024) {
            int sub = i >> 9, w = i & 511, r = w >> 3, c = w & 7;
            src = (sub ? g_ql : g_qh) + ((size_t)h * TT + tt * 64 + r) * DHD + c * 8;
            dst = sub * 8192 + sw_off(r, c);
        } else {
            int j = i - 1024;
            int sub = j >> 10, w = j & 1023, r = w >> 3, c = w & 7;
            src = (sub ? g_kl : g_kh) + ((size_t)khid * TT + st * 128 + r) * DHD + c * 8;
            dst = 16384 + sub * 16384 + sw_off(r, c);
        }
        cp16(sb + dst, src);
    }
    CP_COMMIT(); CP_WAIT(0);
    __syncthreads();

    const int wm = warp & 1, wn = warp >> 1;
    const int lr = lane & 15, lcs = lane >> 4;
    float acc[2][4][4];
    #pragma unroll
    for (int a = 0; a < 2; a++)
        #pragma unroll
        for (int b = 0; b < 4; b++)
            #pragma unroll
            for (int c = 0; c < 4; c++) acc[a][b][c] = 0.f;

    #pragma unroll
    for (int k16 = 0; k16 < 4; k16++) {
        const int cch = k16 * 2 + lcs;
        uint32_t ah[2][4], al[2][4];
        #pragma unroll
        for (int mf = 0; mf < 2; mf++) {
            int row = wm * 32 + mf * 16 + lr;
            uint32_t off = sw_off(row, cch);
            ldsm4(ah[mf], sb + off);
            ldsm4(al[mf], sb + 8192 + off);
        }
        #pragma unroll
        for (int g = 0; g < 2; g++) {
            int row = wn * 32 + g * 16 + lr;
            uint32_t off = sw_off(row, cch);
            uint32_t rh[4], rl[4];
            ldsm4(rh, sb + 16384 + off);
            ldsm4(rl, sb + 32768 + off);
            uint32_t b0h[2] = {rh[0], rh[2]}, b1h[2] = {rh[1], rh[3]};
            uint32_t b0l[2] = {rl[0], rl[2]}, b1l[2] = {rl[1], rl[3]};
            #pragma unroll
            for (int mf = 0; mf < 2; mf++) {
                mma_bf16(acc[mf][g*2], ah[mf], b0h);
                mma_bf16(acc[mf][g*2], ah[mf], b0l);
                mma_bf16(acc[mf][g*2], al[mf], b0h);
                mma_bf16(acc[mf][g*2+1], ah[mf], b1h);
                mma_bf16(acc[mf][g*2+1], ah[mf], b1l);
                mma_bf16(acc[mf][g*2+1], al[mf], b1h);
            }
        }
    }
    float* o = g_att + (size_t)h * TT * TT;
    #pragma unroll
    for (int mf = 0; mf < 2; mf++)
        #pragma unroll
        for (int nf = 0; nf < 4; nf++) {
            int r = tt * 64 + wm * 32 + mf * 16 + (lane >> 2);
            int c = st * 128 + wn * 32 + nf * 8 + (lane & 3) * 2;
            float* d = acc[mf][nf];
            *(float2*)(o + (size_t)r * TT + c)       = make_float2(d[0]*0.125f, d[1]*0.125f);
            *(float2*)(o + (size_t)(r + 8) * TT + c) = make_float2(d[2]*0.125f, d[3]*0.125f);
        }
}

// ---------------- single-pass softmax + gate, writes split-bf16 att ----------------
__global__ void softmax_thresh_k(const float* __restrict__ gate_all, int l) {
    __shared__ float sh[256];
    int t = blockIdx.x, h = blockIdx.y;
    int tid = threadIdx.x;
    const float* p = g_att + (size_t)h * TT * TT + (size_t)t * TT;
    float thr = 1.0f / (1.0f + expf(-gate_all[l * NH + h]));
    float x[4];
    #pragma unroll
    for (int k = 0; k < 4; k++) {
        int i = k * 256 + tid;
        x[k] = (i <= t) ? p[i] : -1e30f;
    }
    float m = fmaxf(fmaxf(x[0], x[1]), fmaxf(x[2], x[3]));
    m = blk_max256(m, sh);
    float e[4], s = 0.f;
    #pragma unroll
    for (int k = 0; k < 4; k++) {
        int i = k * 256 + tid;
        e[k] = (i <= t) ? fast_exp(x[k] - m) : 0.f;
        s += e[k];
    }
    s = blk_sum256(s, sh);
    float inv = 1.0f / s;
    int kend = ((t >> 6) + 1) << 6;
    size_t base = (size_t)h * TT * TT + (size_t)t * TT;
    #pragma unroll
    for (int k = 0; k < 4; k++) {
        int i = k * 256 + tid;
        if (i < kend) {
            float pv = e[k] * inv;
            pv = (pv >= thr) ? pv : 0.f;
            bf16 hh2, ll2; split_bf16(pv, hh2, ll2);
            g_atth[base + i] = hh2;
            g_attl[base + i] = ll2;
        }
    }
}

// ---------------- HMMA AV: 64(t) x 64(d), fp16 single output ----------------
#define AVSM 65536
__global__ __launch_bounds__(256) void av_mma() {
    int tt = gridDim.x - 1 - blockIdx.x;    // largest-K blocks launch first
    int h = blockIdx.y;
    int khid = h >> 2;
    int St = tt + 1;
    extern __shared__ char dsm[];
    const uint32_t sb = (uint32_t)__cvta_generic_to_shared(dsm);
    const int tid = threadIdx.x;
    const int lane = tid & 31, warp = tid >> 5;
    const int wm = warp & 1, wn = warp >> 1;
    const int lr = lane & 15, lcs = lane >> 4;

    auto load = [&](int s) {
        uint32_t base = sb + (s & 1) * 32768;
        #pragma unroll
        for (int it = 0; it < 8; it++) {
            int i = tid + it * 256;
            const bf16* src; uint32_t dst;
            if (i < 1024) {
                int sub = i >> 9, w = i & 511, r = w >> 3, c = w & 7;
                src = (sub ? g_attl : g_atth) + ((size_t)h * TT + tt * 64 + r) * TT + s * 64 + c * 8;
                dst = base + sub * 8192 + sw_off(r, c);
            } else {
                int j = i - 1024;
                int sub = j >> 9, w = j & 511, r = w >> 3, c = w & 7;
                src = (sub ? g_vtl : g_vth) + ((size_t)khid * DHD + r) * TT + s * 64 + c * 8;
                dst = base + 16384 + sub * 8192 + sw_off(r, c);
            }
            cp16(dst, src);
        }
        CP_COMMIT();
    };

    load(0);
    if (St > 1) load(1);

    float acc[2][2][4];
    #pragma unroll
    for (int a = 0; a < 2; a++)
        #pragma unroll
        for (int b = 0; b < 2; b++)
            #pragma unroll
            for (int c = 0; c < 4; c++) acc[a][b][c] = 0.f;

    for (int s = 0; s < St; s++) {
        if (s + 1 < St) { CP_WAIT(1); } else { CP_WAIT(0); }
        __syncthreads();
        uint32_t base = sb + (s & 1) * 32768;
        #pragma unroll
        for (int k16 = 0; k16 < 4; k16++) {
            const int cch = k16 * 2 + lcs;
            uint32_t ah[2][4], al[2][4];
            #pragma unroll
            for (int mf = 0; mf < 2; mf++) {
                int row = wm * 32 + mf * 16 + lr;
                uint32_t off = sw_off(row, cch);
                ldsm4(ah[mf], base + off);
                ldsm4(al[mf], base + 8192 + off);
            }
            int row = wn * 16 + lr;
            uint32_t off = sw_off(row, cch);
            uint32_t rh[4], rl[4];
            ldsm4(rh, base + 16384 + off);
            ldsm4(rl, base + 24576 + off);
            uint32_t b0h[2] = {rh[0], rh[2]}, b1h[2] = {rh[1], rh[3]};
            uint32_t b0l[2] = {rl[0], rl[2]}, b1l[2] = {rl[1], rl[3]};
            #pragma unroll
            for (int mf = 0; mf < 2; mf++) {
                mma_bf16(acc[mf][0], ah[mf], b0h);
                mma_bf16(acc[mf][0], ah[mf], b0l);
                mma_bf16(acc[mf][0], al[mf], b0h);
                mma_bf16(acc[mf][1], ah[mf], b1h);
                mma_bf16(acc[mf][1], ah[mf], b1l);
                mma_bf16(acc[mf][1], al[mf], b1h);
            }
        }
        __syncthreads();
        if (s + 2 < St) load(s + 2);
    }

    #pragma unroll
    for (int mf = 0; mf < 2; mf++)
        #pragma unroll
        for (int nf = 0; nf < 2; nf++) {
            int r = tt * 64 + wm * 32 + mf * 16 + (lane >> 2);
            int c = h * DHD + wn * 16 + nf * 8 + (lane & 3) * 2;
            float* d = acc[mf][nf];
            *(__half2*)(g_yf + (size_t)r * EE + c) =
                __halves2half2(__float2half_rn(d[0]), __float2half_rn(d[1]));
            *(__half2*)(g_yf + (size_t)(r + 8) * EE + c) =
                __halves2half2(__float2half_rn(d[2]), __float2half_rn(d[3]));
        }
}

// ---------------- fused residual-add + layernorm + split (bf16 pair or fp16) ----------------
__global__ void add_ln_split_k(float* __restrict__ x, const float* __restrict__ p,
                               const float* __restrict__ g, const float* __restrict__ b,
                               bf16* __restrict__ oh, bf16* __restrict__ ol,
                               __half* __restrict__ of) {
    __shared__ float sh[256];
    int row = blockIdx.x, tid = threadIdx.x;
    const int n = TT * EE;
    float v[4];
    #pragma unroll
    for (int k = 0; k < 4; k++) {
        int i = row * EE + k * 256 + tid;
        v[k] = x[i] + p[i] + p[i + n];
        x[i] = v[k];
    }
    float mu = blk_sum256(v[0] + v[1] + v[2] + v[3], sh) * (1.0f / EE);
    float vs = 0.f;
    #pragma unroll
    for (int k = 0; k < 4; k++) { float d = v[k] - mu; vs += d * d; }
    float var = blk_sum256(vs, sh) * (1.0f / EE);
    float inv = rsqrtf(var + EPSV);
    #pragma unroll
    for (int k = 0; k < 4; k++) {
        int c = k * 256 + tid;
        float o = (v[k] - mu) * inv * g[c] + b[c];
        if (of) {
            of[row * EE + c] = __float2half_rn(o);
        } else {
            bf16 h, l; split_bf16(o, h, l);
            oh[row * EE + c] = h;
            ol[row * EE + c] = l;
        }
    }
}

// ---------------- plain layernorm + split (first LN only) ----------------
__global__ void layernorm_split_k(const float* __restrict__ in, bf16* __restrict__ oh,
                                  bf16* __restrict__ ol,
                                  const float* __restrict__ g, const float* __restrict__ b) {
    __shared__ float sh[256];
    int row = blockIdx.x;
    const float* x = in + (size_t)row * EE;
    float s = 0.f;
    for (int i = threadIdx.x; i < EE; i += 256) s += x[i];
    float mu = blk_sum256(s, sh) * (1.0f / EE);
    float vs = 0.f;
    for (int i = threadIdx.x; i < EE; i += 256) { float d = x[i] - mu; vs += d * d; }
    float var = blk_sum256(vs, sh) * (1.0f / EE);
    float inv = rsqrtf(var + EPSV);
    for (int i = threadIdx.x; i < EE; i += 256) {
        float v = (x[i] - mu) * inv * g[i] + b[i];
        bf16 h, l; split_bf16(v, h, l);
        oh[(size_t)row * EE + i] = h;
        ol[(size_t)row * EE + i] = l;
    }
}

// ---------------- weight transpose + split (bf16) ----------------
__global__ void wtsplit_k(const float* __restrict__ W, bf16* __restrict__ Th,
                          bf16* __restrict__ Tl, int K, int N, int ldt) {
    __shared__ float t[32][33];
    int n0 = blockIdx.x * 32, k0 = blockIdx.y * 32;
    int tx = threadIdx.x, ty = threadIdx.y;
    #pragma unroll
    for (int r = ty; r < 32; r += 8)
        t[r][tx] = W[(size_t)(k0 + r) * N + n0 + tx];
    __syncthreads();
    #pragma unroll
    for (int r = ty; r < 32; r += 8) {
        float v = t[tx][r];
        bf16 h, l; split_bf16(v, h, l);
        Th[(size_t)(n0 + r) * ldt + k0 + tx] = h;
        Tl[(size_t)(n0 + r) * ldt + k0 + tx] = l;
    }
}

// ---------------- weight transpose + split (fp16) ----------------
__global__ void wtsplit_f16_k(const float* __restrict__ W, __half* __restrict__ Th,
                              __half* __restrict__ Tl, int K, int N, int ldt) {
    __shared__ float t[32][33];
    int n0 = blockIdx.x * 32, k0 = blockIdx.y * 32;
    int tx = threadIdx.x, ty = threadIdx.y;
    #pragma unroll
    for (int r = ty; r < 32; r += 8)
        t[r][tx] = W[(size_t)(k0 + r) * N + n0 + tx];
    __syncthreads();
    #pragma unroll
    for (int r = ty; r < 32; r += 8) {
        float v = t[tx][r];
        __half h, l; split_fp16(v, h, l);
        Th[(size_t)(n0 + r) * ldt + k0 + tx] = h;
        Tl[(size_t)(n0 + r) * ldt + k0 + tx] = l;
    }
}

// ---------------- embed split (fp16 hi/lo) ----------------
__global__ void esplit_f16_k(const float* __restrict__ E, __half* __restrict__ Eh,
                             __half* __restrict__ El) {
    size_t i = ((size_t)blockIdx.x * 256 + threadIdx.x) * 4;
    float4 v = *(const float4*)(E + i);
    __half h0,l0,h1,l1,h2,l2,h3,l3;
    split_fp16(v.x,h0,l0); split_fp16(v.y,h1,l1); split_fp16(v.z,h2,l2); split_fp16(v.w,h3,l3);
    *(__half2*)(Eh + i)     = __halves2half2(h0, h1);
    *(__half2*)(Eh + i + 2) = __halves2half2(h2, h3);
    *(__half2*)(El + i)     = __halves2half2(l0, l1);
    *(__half2*)(El + i + 2) = __halves2half2(l2, l3);
}

// ---------------- embedding gather ----------------
__global__ void gather_embed_k(const float* __restrict__ embed, const int* __restrict__ idx) {
    int i = blockIdx.x * blockDim.x + threadIdx.x;
    int t = i >> 10, e = i & 1023;
    g_x[i] = embed[(size_t)idx[t] * EE + e];
}

// ---------------- loss: single-pass online softmax (MUFU-free exp) ----------------
__global__ void zero_loss_k() { g_loss = 0.f; }

__global__ void loss_rows_k(const float* __restrict__ logits, const int* __restrict__ targets) {
    __shared__ float shm[256], shs[256];
    int t = blockIdx.x, tid = threadIdx.x;
    const float* row = logits + (size_t)t * VV;
    float m = -1e30f, s = 0.f;
    for (int i = tid; i < VV; i += 256) {
        float v = row[i];
        if (v > m) { s = s * fast_exp(m - v) + 1.f; m = v; }
        else       { s += fast_exp(v - m); }
    }
    shm[tid] = m; shs[tid] = s; __syncthreads();
    #pragma unroll
    for (int st = 128; st > 0; st >>= 1) {
        if (tid < st) {
            float m2 = shm[tid + st], s2 = shs[tid + st];
            float M = fmaxf(shm[tid], m2);
            shs[tid] = shs[tid] * fast_exp(shm[tid] - M) + s2 * fast_exp(m2 - M);
            shm[tid] = M;
        }
        __syncthreads();
    }
    if (tid == 0) {
        float lp = row[targets[t]] - shm[0] - logf(shs[0]);
        atomicAdd(&g_loss, -lp);
    }
}

__global__ void loss_fin_k(float* dst) { *dst = g_loss * (1.0f / (float)TT); }

// ---------------- host orchestration ----------------
extern "C" void kernel_launch(void* const* d_in, const int* in_sizes, int n_in,
                              void* d_out, int out_size) {
    const float* embed = (const float*)d_in[0];
    const float* ln1_g = (const float*)d_in[1];
    const float* ln1_b = (const float*)d_in[2];
    const float* Wq    = (const float*)d_in[3];
    const float* Wk    = (const float*)d_in[4];
    const float* Wv    = (const float*)d_in[5];
    const float* Wo    = (const float*)d_in[6];
    const float* gate  = (const float*)d_in[7];
    const float* ln2_g = (const float*)d_in[8];
    const float* ln2_b = (const float*)d_in[9];
    const float* W1    = (const float*)d_in[10];
    const float* W2    = (const float*)d_in[11];
    const float* lnf_g = (const float*)d_in[12];
    const float* lnf_b = (const float*)d_in[13];
    const int*   idx   = (const int*)d_in[14];
    const int*   tgt   = (const int*)d_in[15];

    float *xp, *logp, *partp;
    bf16 *hh, *hl;
    bf16 *wqkvh, *wqkvl;
    __half *hf, *fff, *yf, *wofh, *wofl, *w1fh, *w1fl, *w2fh, *w2fl, *efh, *efl;
    cudaGetSymbolAddress((void**)&xp,    g_x);
    cudaGetSymbolAddress((void**)&logp,  g_logits);
    cudaGetSymbolAddress((void**)&partp, g_part);
    cudaGetSymbolAddress((void**)&hh,    g_hh);
    cudaGetSymbolAddress((void**)&hl,    g_hl);
    cudaGetSymbolAddress((void**)&hf,    g_hf);
    cudaGetSymbolAddress((void**)&fff,   g_fff);
    cudaGetSymbolAddress((void**)&yf,    g_yf);
    cudaGetSymbolAddress((void**)&wqkvh, g_wqkv_h);
    cudaGetSymbolAddress((void**)&wqkvl, g_wqkv_l);
    cudaGetSymbolAddress((void**)&wofh,  g_wofh);
    cudaGetSymbolAddress((void**)&wofl,  g_wofl);
    cudaGetSymbolAddress((void**)&w1fh,  g_w1fh);
    cudaGetSymbolAddress((void**)&w1fl,  g_w1fl);
    cudaGetSymbolAddress((void**)&w2fh,  g_w2fh);
    cudaGetSymbolAddress((void**)&w2fl,  g_w2fl);
    cudaGetSymbolAddress((void**)&efh,   g_efh);
    cudaGetSymbolAddress((void**)&efl,   g_efl);

    cudaFuncSetAttribute(gemm_mma<0,128,3>, cudaFuncAttributeMaxDynamicSharedMemorySize, GSM128);
    cudaFuncSetAttribute(fp16_mma<0,128,3>, cudaFuncAttributeMaxDynamicSharedMemorySize, F16SM128);
    cudaFuncSetAttribute(fp16_mma<0,256,2>, cudaFuncAttributeMaxDynamicSharedMemorySize, F16SM256);
    cudaFuncSetAttribute(fp16_mma<2,256,2>, cudaFuncAttributeMaxDynamicSharedMemorySize, F16SM256);
    cudaFuncSetAttribute(scores_mma, cudaFuncAttributeMaxDynamicSharedMemorySize, SCSM);
    cudaFuncSetAttribute(av_mma, cudaFuncAttributeMaxDynamicSharedMemorySize, AVSM);

    // side stream + events (host-side objects, created once)
    static cudaStream_t s2 = nullptr;
    static cudaEvent_t ev_fork = nullptr, ev_w0 = nullptr, ev_w1 = nullptr, ev_e = nullptr;
    if (!s2) {
        cudaStreamCreateWithFlags(&s2, cudaStreamNonBlocking);
        cudaEventCreateWithFlags(&ev_fork, cudaEventDisableTiming);
        cudaEventCreateWithFlags(&ev_w0, cudaEventDisableTiming);
        cudaEventCreateWithFlags(&ev_w1, cudaEventDisableTiming);
        cudaEventCreateWithFlags(&ev_e, cudaEventDisableTiming);
    }

    const size_t BTV = (size_t)TT * VV;
    float* logits_dst = ((size_t)out_size >= BTV) ? (float*)d_out : logp;
    float* loss_dst = nullptr;
    if ((size_t)out_size > BTV)      loss_dst = (float*)d_out + BTV;
    else if ((size_t)out_size < BTV) loss_dst = (float*)d_out;

    dim3 tb(32, 8);

    // ---- fork: non-immediate preprocessing on s2 ----
    cudaEventRecord(ev_fork, 0);
    cudaStreamWaitEvent(s2, ev_fork, 0);

    wtsplit_f16_k<<<dim3(EE/32, EE/32), tb, 0, s2>>>(Wo, wofh, wofl, EE, EE, EE);
    wtsplit_f16_k<<<dim3(FF/32, EE/32), tb, 0, s2>>>(W1, w1fh, w1fl, EE, FF, EE);
    wtsplit_f16_k<<<dim3(EE/32, FF/32), tb, 0, s2>>>(W2, w2fh, w2fl, FF, EE, FF);
    cudaEventRecord(ev_w0, s2);
    {
        const int l = 1;
        wtsplit_k<<<dim3(EE/32, EE/32), tb, 0, s2>>>(Wq + (size_t)l*EE*EE,
            wqkvh + (size_t)l*QKVN*EE, wqkvl + (size_t)l*QKVN*EE, EE, EE, EE);
        wtsplit_k<<<dim3(KVD/32, EE/32), tb, 0, s2>>>(Wk + (size_t)l*EE*KVD,
            wqkvh + (size_t)l*QKVN*EE + (size_t)EE*EE, wqkvl + (size_t)l*QKVN*EE + (size_t)EE*EE, EE, KVD, EE);
        wtsplit_k<<<dim3(KVD/32, EE/32), tb, 0, s2>>>(Wv + (size_t)l*EE*KVD,
            wqkvh + (size_t)l*QKVN*EE + (size_t)(EE+KVD)*EE, wqkvl + (size_t)l*QKVN*EE + (size_t)(EE+KVD)*EE, EE, KVD, EE);
        wtsplit_f16_k<<<dim3(EE/32, EE/32), tb, 0, s2>>>(Wo + (size_t)l*EE*EE,
            wofh + (size_t)l*EE*EE, wofl + (size_t)l*EE*EE, EE, EE, EE);
        wtsplit_f16_k<<<dim3(FF/32, EE/32), tb, 0, s2>>>(W1 + (size_t)l*EE*FF,
            w1fh + (size_t)l*FF*EE, w1fl + (size_t)l*FF*EE, EE, FF, EE);
        wtsplit_f16_k<<<dim3(EE/32, FF/32), tb, 0, s2>>>(W2 + (size_t)l*FF*EE,
            w2fh + (size_t)l*EE*FF, w2fl + (size_t)l*EE*FF, FF, EE, FF);
    }
    cudaEventRecord(ev_w1, s2);
    esplit_f16_k<<<(int)(((size_t)VV*EE)/1024), 256, 0, s2>>>(embed, efh, efl);
    cudaEventRecord(ev_e, s2);

    // ---- main stream: critical path ----
    wtsplit_k<<<dim3(EE/32, EE/32), tb>>>(Wq, wqkvh, wqkvl, EE, EE, EE);
    wtsplit_k<<<dim3(KVD/32, EE/32), tb>>>(Wk, wqkvh + (size_t)EE*EE, wqkvl + (size_t)EE*EE, EE, KVD, EE);
    wtsplit_k<<<dim3(KVD/32, EE/32), tb>>>(Wv, wqkvh + (size_t)(EE+KVD)*EE, wqkvl + (size_t)(EE+KVD)*EE, EE, KVD, EE);
    gather_embed_k<<<(TT * EE) / 256, 256>>>(embed, idx);
    layernorm_split_k<<<TT, 256>>>(xp, hh, hl, ln1_g, ln1_b);

    for (int it = 0; it < RNUM * LNUM; it++) {
        int l = it % LNUM;
        if (it == 1) cudaStreamWaitEvent(0, ev_w1, 0);
        // QKV: 3-term bf16, split-K=3
        gemm_mma<0,128,3><<<dim3(TT/128, QKVN/128, 3), 256, GSM128>>>(hh, hl,
            wqkvh + (size_t)l*QKVN*EE, wqkvl + (size_t)l*QKVN*EE,
            partp, nullptr, nullptr, nullptr, QKVN, EE);
        qkv_post_k<<<dim3(TT/64, NH + 2*NKV), 256>>>(partp);
        scores_mma<<<dim3(TT/128, TT/64, NH), 256, SCSM>>>();
        softmax_thresh_k<<<dim3(TT, NH), 256>>>(gate, l);
        av_mma<<<dim3(TT/64, NH), 256, AVSM>>>();
        if (it == 0) cudaStreamWaitEvent(0, ev_w0, 0);
        // Wo: fp16 2-term, split-K=2; fused x+= & LN2 (fp16 single out for FFN1)
        fp16_mma<0,128,3><<<dim3(TT/128, EE/128, 2), 256, F16SM128>>>(yf,
            wofh + (size_t)l*EE*EE, wofl + (size_t)l*EE*EE,
            partp, nullptr, EE, EE);
        add_ln_split_k<<<TT, 256>>>(xp, partp, ln2_g + l * EE, ln2_b + l * EE,
                                    nullptr, nullptr, hf);
        // FFN1: fp16 2-term, gelu -> fp16 single
        fp16_mma<2,256,2><<<dim3(TT/128, FF/256, 1), 256, F16SM256>>>(hf,
            w1fh + (size_t)l*FF*EE, w1fl + (size_t)l*FF*EE,
            nullptr, fff, FF, EE);
        // FFN2: fp16 2-term, split-K=2 -> partials
        fp16_mma<0,128,3><<<dim3(TT/128, EE/128, 2), 256, F16SM128>>>(fff,
            w2fh + (size_t)l*EE*FF, w2fl + (size_t)l*EE*FF,
            partp, nullptr, EE, FF);
        if (it == RNUM * LNUM - 1) {
            add_ln_split_k<<<TT, 256>>>(xp, partp, lnf_g, lnf_b, nullptr, nullptr, hf);
        } else {
            int ln = (l + 1) % LNUM;
            add_ln_split_k<<<TT, 256>>>(xp, partp, ln1_g + ln * EE, ln1_b + ln * EE,
                                        hh, hl, nullptr);
        }
    }

    // logits: fp16 2-term GEMM
    cudaStreamWaitEvent(0, ev_e, 0);
    fp16_mma<0,256,2><<<dim3(TT/128, VV/256, 1), 256, F16SM256>>>(hf, efh, efl,
        logits_dst, nullptr, VV, EE);

    zero_loss_k<<<1, 1>>>();
    loss_rows_k<<<TT, 256>>>(logits_dst, tgt);
    if (loss_dst) loss_fin_k<<<1, 1>>>(loss_dst);
}

// round 13
// speedup vs baseline: 1.7278x; 1.0321x over previous
#include <cuda_runtime.h>
#include <cuda_bf16.h>
#include <cuda_fp16.h>
#include <math.h>
#include <stdint.h>

// ---------------- problem constants ----------------
#define TT 1024
#define EE 1024
#define VV 32000
#define NH 16
#define NKV 4
#define DHD 64
#define KVD (NKV*DHD)     // 256
#define QKVN 1536
#define LNUM 2
#define RNUM 2
#define FF 4096
#define EPSV 1e-5f

typedef __nv_bfloat16 bf16;

// ---------------- device scratch ----------------
__device__ float g_x[TT*EE];
__device__ bf16  g_hh[TT*EE], g_hl[TT*EE];
__device__ __half g_hf[TT*EE];                         // fp16 LN output (LN2 / final)
__device__ __half g_fff[TT*FF];                        // fp16 gelu(FFN1) output
__device__ float g_att[(size_t)NH*TT*TT];
__device__ bf16  g_atth[(size_t)NH*TT*TT], g_attl[(size_t)NH*TT*TT];
__device__ float g_part[3*TT*QKVN];          // split-K partials (reused)
__device__ bf16  g_qh[NH*TT*DHD],  g_ql[NH*TT*DHD];
__device__ bf16  g_kh[NKV*TT*DHD], g_kl[NKV*TT*DHD];
__device__ bf16  g_vth[NKV*DHD*TT], g_vtl[NKV*DHD*TT];   // transposed V
__device__ __half g_yf[TT*EE];                           // fp16 attention output
__device__ bf16  g_wqkv_h[LNUM*QKVN*EE], g_wqkv_l[LNUM*QKVN*EE];
__device__ __half g_wofh[LNUM*EE*EE],    g_wofl[LNUM*EE*EE];   // fp16 hi/lo Wo
__device__ __half g_w1fh[LNUM*FF*EE],    g_w1fl[LNUM*FF*EE];   // fp16 hi/lo W1
__device__ __half g_w2fh[LNUM*EE*FF],    g_w2fl[LNUM*EE*FF];   // fp16 hi/lo W2
__device__ __half g_efh[(size_t)VV*EE],  g_efl[(size_t)VV*EE]; // fp16 hi/lo embed
__device__ float g_logits[(size_t)TT*VV];
__device__ float g_rowsum[TT];                           // fused loss: sum exp(logit)
__device__ float g_loss;

// ---------------- generic helpers ----------------
__device__ __forceinline__ float blk_sum256(float v, float* sh) {
    int tid = threadIdx.x;
    sh[tid] = v; __syncthreads();
    #pragma unroll
    for (int s = 128; s > 0; s >>= 1) { if (tid < s) sh[tid] += sh[tid + s]; __syncthreads(); }
    float r = sh[0]; __syncthreads();
    return r;
}
__device__ __forceinline__ float blk_max256(float v, float* sh) {
    int tid = threadIdx.x;
    sh[tid] = v; __syncthreads();
    #pragma unroll
    for (int s = 128; s > 0; s >>= 1) { if (tid < s) sh[tid] = fmaxf(sh[tid], sh[tid + s]); __syncthreads(); }
    float r = sh[0]; __syncthreads();
    return r;
}
__device__ __forceinline__ float gelu_exact(float x) {
    return 0.5f * x * (1.0f + erff(x * 0.7071067811865476f));
}
__device__ __forceinline__ void split_bf16(float v, bf16& h, bf16& l) {
    h = __float2bfloat16(v);
    l = __float2bfloat16(v - __bfloat162float(h));
}
__device__ __forceinline__ void split_fp16(float v, __half& h, __half& l) {
    h = __float2half_rn(v);
    l = __float2half_rn(v - __half2float(h));
}
// MUFU-free exp: rint range reduction + degree-5 Taylor, rel err ~3e-6
__device__ __forceinline__ float fast_exp(float v) {
    float t = v * 1.44269504f;
    t = fmaxf(t, -120.0f);
    float r = rintf(t);
    float f = (t - r) * 0.69314718f;   // |f| <= 0.3466
    float p = 1.0f + f * (1.0f + f * (0.5f + f * (0.166666667f
             + f * (0.0416666667f + f * 0.00833333333f))));
    return __int_as_float(((int)(127.0f + r)) << 23) * p;
}

// ---------------- PTX wrappers ----------------
__device__ __forceinline__ void mma_bf16(float* d, const uint32_t* a, const uint32_t* b) {
    asm volatile("mma.sync.aligned.m16n8k16.row.col.f32.bf16.bf16.f32 "
        "{%0,%1,%2,%3}, {%4,%5,%6,%7}, {%8,%9}, {%0,%1,%2,%3};"
        : "+f"(d[0]), "+f"(d[1]), "+f"(d[2]), "+f"(d[3])
        : "r"(a[0]), "r"(a[1]), "r"(a[2]), "r"(a[3]), "r"(b[0]), "r"(b[1]));
}
__device__ __forceinline__ void mma_fp16(float* d, const uint32_t* a, const uint32_t* b) {
    asm volatile("mma.sync.aligned.m16n8k16.row.col.f32.f16.f16.f32 "
        "{%0,%1,%2,%3}, {%4,%5,%6,%7}, {%8,%9}, {%0,%1,%2,%3};"
        : "+f"(d[0]), "+f"(d[1]), "+f"(d[2]), "+f"(d[3])
        : "r"(a[0]), "r"(a[1]), "r"(a[2]), "r"(a[3]), "r"(b[0]), "r"(b[1]));
}
__device__ __forceinline__ void ldsm4(uint32_t* r, uint32_t addr) {
    asm volatile("ldmatrix.sync.aligned.m8n8.x4.shared.b16 {%0,%1,%2,%3}, [%4];"
        : "=r"(r[0]), "=r"(r[1]), "=r"(r[2]), "=r"(r[3]) : "r"(addr));
}
__device__ __forceinline__ void cp16(uint32_t s, const void* g) {
    asm volatile("cp.async.cg.shared.global [%0], [%1], 16;" :: "r"(s), "l"(g));
}
#define CP_COMMIT()  asm volatile("cp.async.commit_group;")
#define CP_WAIT(n)   asm volatile("cp.async.wait_group %0;" :: "n"(n))

// SW128 swizzle: 128B rows, 16B chunks, chunk ^= row&7  (conflict-free ldmatrix)
__device__ __forceinline__ uint32_t sw_off(int row, int chunk) {
    return (uint32_t)(row * 128 + ((chunk ^ (row & 7)) << 4));
}

// ---------------- split-bf16 3-term HMMA GEMM (QKV) ----------------
template<int MODE, int TN, int NSTG>
__global__ __launch_bounds__(256, 1) void gemm_mma(
    const bf16* __restrict__ Ah, const bf16* __restrict__ Al,
    const bf16* __restrict__ Bh, const bf16* __restrict__ Bl,
    float* C, const float* Rs, bf16* Oh, bf16* Ol,
    int N, int K)
{
    constexpr int TSA = 128 * 128;
    constexpr int TSB = TN * 128;
    constexpr int SB  = 2 * TSA + 2 * TSB;
    constexpr int BCH = TN * 8;
    constexpr int TC  = 2048 + 2 * BCH;
    constexpr int NG  = TN / 64;
    constexpr int NF  = 2 * NG;

    extern __shared__ char dsm[];
    const int tid = threadIdx.x;
    const int lane = tid & 31, warp = tid >> 5;
    const int wm = warp & 1, wn = warp >> 1;
    const int row0 = blockIdx.x * 128, col0 = blockIdx.y * TN;
    const uint32_t sb = (uint32_t)__cvta_generic_to_shared(dsm);

    float acc[4][NF][4];
    #pragma unroll
    for (int i = 0; i < 4; i++)
        #pragma unroll
        for (int j = 0; j < NF; j++)
            #pragma unroll
            for (int r = 0; r < 4; r++) acc[i][j][r] = 0.f;

    auto load_stage = [&](int s) {
        int k0 = s * 64;
        uint32_t base = sb + (s % NSTG) * SB;
        #pragma unroll
        for (int ii = 0; ii < TC / 256; ii++) {
            int i = tid + ii * 256;
            const bf16* src;
            uint32_t toff;
            if (i < 2048) {
                int t = i >> 10, w = i & 1023;
                int r = w >> 3, c = w & 7;
                src = (t ? Al : Ah) + (size_t)(row0 + r) * K + k0 + c * 8;
                toff = t * TSA + sw_off(r, c);
            } else {
                int j = i - 2048;
                int t = j / BCH, w = j & (BCH - 1);
                int r = w >> 3, c = w & 7;
                src = (t ? Bl : Bh) + (size_t)(col0 + r) * K + k0 + c * 8;
                toff = 2 * TSA + t * TSB + sw_off(r, c);
            }
            cp16(base + toff, src);
        }
        CP_COMMIT();
    };

    const int Stot = K >> 6;
    const int SK = gridDim.z;
    const int Sc = (Stot + SK - 1) / SK;
    const int s0 = blockIdx.z * Sc;
    const int s1 = min(Stot, s0 + Sc);

    #pragma unroll
    for (int i = 0; i < NSTG; i++)
        if (s0 + i < s1) load_stage(s0 + i);

    const int lr = lane & 15, lcs = lane >> 4;

    for (int s = s0; s < s1; s++) {
        int ahead = s1 - 1 - s;
        int w = ahead < (NSTG - 1) ? ahead : (NSTG - 1);
        if (w == 2)      { CP_WAIT(2); }
        else if (w == 1) { CP_WAIT(1); }
        else             { CP_WAIT(0); }
        __syncthreads();
        uint32_t ab = sb + (s % NSTG) * SB;
        #pragma unroll
        for (int k16 = 0; k16 < 4; k16++) {
            const int cch = k16 * 2 + lcs;
            uint32_t ah[4][4], al[4][4];
            #pragma unroll
            for (int mf = 0; mf < 4; mf++) {
                int row = wm * 64 + mf * 16 + lr;
                uint32_t off = sw_off(row, cch);
                ldsm4(ah[mf], ab + off);
                ldsm4(al[mf], ab + TSA + off);
            }
            #pragma unroll
            for (int g = 0; g < NG; g++) {
                int row = wn * (TN / 4) + g * 16 + lr;
                uint32_t off = sw_off(row, cch);
                uint32_t rh[4], rl[4];
                ldsm4(rh, ab + 2 * TSA + off);
                ldsm4(rl, ab + 2 * TSA + TSB + off);
                uint32_t b0h[2] = {rh[0], rh[2]}, b1h[2] = {rh[1], rh[3]};
                uint32_t b0l[2] = {rl[0], rl[2]}, b1l[2] = {rl[1], rl[3]};
                #pragma unroll
                for (int mf = 0; mf < 4; mf++) {
                    mma_bf16(acc[mf][g*2], ah[mf], b0h);
                    mma_bf16(acc[mf][g*2], ah[mf], b0l);
                    mma_bf16(acc[mf][g*2], al[mf], b0h);
                    mma_bf16(acc[mf][g*2+1], ah[mf], b1h);
                    mma_bf16(acc[mf][g*2+1], ah[mf], b1l);
                    mma_bf16(acc[mf][g*2+1], al[mf], b1h);
                }
            }
        }
        __syncthreads();
        if (s + NSTG < s1) load_stage(s + NSTG);
    }

    const size_t pstride = (size_t)gridDim.x * 128 * N;
    float* Cp = C + (size_t)blockIdx.z * pstride;
    #pragma unroll
    for (int mf = 0; mf < 4; mf++)
        #pragma unroll
        for (int nf = 0; nf < NF; nf++) {
            int r = row0 + wm * 64 + mf * 16 + (lane >> 2);
            int c = col0 + wn * (TN / 4) + nf * 8 + (lane & 3) * 2;
            float* d = acc[mf][nf];
            *(float2*)(Cp + (size_t)r * N + c)       = make_float2(d[0], d[1]);
            *(float2*)(Cp + (size_t)(r + 8) * N + c) = make_float2(d[2], d[3]);
        }
}

#define GSM128 (3 * (2*128*128 + 2*128*128))   // 196608

// ---------------- fp16 2-term GEMM (Wo / FFN / logits): C = A * (Bh+Bl)^T ----------------
// LOSS=true (logits only): also accumulate per-row sum of exp(logit) into g_rowsum.
template<int MODE, int TN, int NSTG, bool LOSS>
__global__ __launch_bounds__(256, 1) void fp16_mma(
    const __half* __restrict__ A, const __half* __restrict__ Bh,
    const __half* __restrict__ Bl, float* __restrict__ C,
    __half* __restrict__ Of, int N, int K)
{
    constexpr int TSA = 128 * 128;
    constexpr int TSB = TN * 128;
    constexpr int SB  = TSA + 2 * TSB;
    constexpr int BCH = TN * 8;
    constexpr int TC  = 1024 + 2 * BCH;
    constexpr int NG  = TN / 64;
    constexpr int NF  = 2 * NG;

    extern __shared__ char dsm[];
    const int tid = threadIdx.x;
    const int lane = tid & 31, warp = tid >> 5;
    const int wm = warp & 1, wn = warp >> 1;
    const int row0 = blockIdx.x * 128, col0 = blockIdx.y * TN;
    const uint32_t sb = (uint32_t)__cvta_generic_to_shared(dsm);

    float acc[4][NF][4];
    #pragma unroll
    for (int i = 0; i < 4; i++)
        #pragma unroll
        for (int j = 0; j < NF; j++)
            #pragma unroll
            for (int r = 0; r < 4; r++) acc[i][j][r] = 0.f;

    auto load_stage = [&](int s) {
        int k0 = s * 64;
        uint32_t base = sb + (s % NSTG) * SB;
        #pragma unroll
        for (int ii = 0; ii < TC / 256; ii++) {
            int i = tid + ii * 256;
            const __half* src; uint32_t toff;
            if (i < 1024) {
                int r = i >> 3, c = i & 7;
                src = A + (size_t)(row0 + r) * K + k0 + c * 8;
                toff = sw_off(r, c);
            } else {
                int j = i - 1024;
                int t = j / BCH, w = j & (BCH - 1);
                int r = w >> 3, c = w & 7;
                src = (t ? Bl : Bh) + (size_t)(col0 + r) * K + k0 + c * 8;
                toff = TSA + t * TSB + sw_off(r, c);
            }
            cp16(base + toff, src);
        }
        CP_COMMIT();
    };

    const int Stot = K >> 6;
    const int SK = gridDim.z;
    const int Sc = (Stot + SK - 1) / SK;
    const int s0 = blockIdx.z * Sc;
    const int s1 = min(Stot, s0 + Sc);

    #pragma unroll
    for (int i = 0; i < NSTG; i++)
        if (s0 + i < s1) load_stage(s0 + i);

    const int lr = lane & 15, lcs = lane >> 4;

    for (int s = s0; s < s1; s++) {
        int ahead = s1 - 1 - s;
        int w = ahead < (NSTG - 1) ? ahead : (NSTG - 1);
        if (w == 2)      { CP_WAIT(2); }
        else if (w == 1) { CP_WAIT(1); }
        else             { CP_WAIT(0); }
        __syncthreads();
        uint32_t ab = sb + (s % NSTG) * SB;
        #pragma unroll
        for (int k16 = 0; k16 < 4; k16++) {
            const int cch = k16 * 2 + lcs;
            uint32_t ah[4][4];
            #pragma unroll
            for (int mf = 0; mf < 4; mf++)
                ldsm4(ah[mf], ab + sw_off(wm * 64 + mf * 16 + lr, cch));
            #pragma unroll
            for (int g = 0; g < NG; g++) {
                uint32_t off = sw_off(wn * (TN / 4) + g * 16 + lr, cch);
                uint32_t rh[4], rl[4];
                ldsm4(rh, ab + TSA + off);
                ldsm4(rl, ab + TSA + TSB + off);
                uint32_t b0h[2] = {rh[0], rh[2]}, b1h[2] = {rh[1], rh[3]};
                uint32_t b0l[2] = {rl[0], rl[2]}, b1l[2] = {rl[1], rl[3]};
                #pragma unroll
                for (int mf = 0; mf < 4; mf++) {
                    mma_fp16(acc[mf][g*2], ah[mf], b0h);
                    mma_fp16(acc[mf][g*2], ah[mf], b0l);
                    mma_fp16(acc[mf][g*2+1], ah[mf], b1h);
                    mma_fp16(acc[mf][g*2+1], ah[mf], b1l);
                }
            }
        }
        __syncthreads();
        if (s + NSTG < s1) load_stage(s + NSTG);
    }

    const size_t pstride = (size_t)gridDim.x * 128 * N;
    float* Cp = C + (size_t)blockIdx.z * pstride;
    float lsum[4][2];
    if (LOSS) {
        #pragma unroll
        for (int mf = 0; mf < 4; mf++) { lsum[mf][0] = 0.f; lsum[mf][1] = 0.f; }
    }
    #pragma unroll
    for (int mf = 0; mf < 4; mf++)
        #pragma unroll
        for (int nf = 0; nf < NF; nf++) {
            int r = row0 + wm * 64 + mf * 16 + (lane >> 2);
            int c = col0 + wn * (TN / 4) + nf * 8 + (lane & 3) * 2;
            float* d = acc[mf][nf];
            if (MODE == 0) {
                *(float2*)(Cp + (size_t)r * N + c)       = make_float2(d[0], d[1]);
                *(float2*)(Cp + (size_t)(r + 8) * N + c) = make_float2(d[2], d[3]);
                if (LOSS) {
                    lsum[mf][0] += fast_exp(d[0]) + fast_exp(d[1]);
                    lsum[mf][1] += fast_exp(d[2]) + fast_exp(d[3]);
                }
            } else {
                __half o0 = __float2half_rn(gelu_exact(d[0]));
                __half o1 = __float2half_rn(gelu_exact(d[1]));
                __half o2 = __float2half_rn(gelu_exact(d[2]));
                __half o3 = __float2half_rn(gelu_exact(d[3]));
                *(__half2*)(Of + (size_t)r * N + c)       = __halves2half2(o0, o1);
                *(__half2*)(Of + (size_t)(r + 8) * N + c) = __halves2half2(o2, o3);
            }
        }
    if (LOSS) {
        float* rs = (float*)dsm;   // pipeline buffers no longer needed
        if (tid < 128) rs[tid] = 0.f;
        __syncthreads();
        #pragma unroll
        for (int mf = 0; mf < 4; mf++) {
            int rl0 = wm * 64 + mf * 16 + (lane >> 2);
            atomicAdd(&rs[rl0], lsum[mf][0]);
            atomicAdd(&rs[rl0 + 8], lsum[mf][1]);
        }
        __syncthreads();
        if (tid < 128) atomicAdd(&g_rowsum[row0 + tid], rs[tid]);
    }
}

#define F16SM128 (3 * (128*128 + 2*128*128))   // 147456
#define F16SM256 (2 * (128*128 + 2*256*128))   // 163840

// ---------------- fused QKV reduce + RoPE/transpose + split ----------------
__global__ void qkv_post_k(const float* __restrict__ part) {
    __shared__ float tile[64][65];
    int ttile = blockIdx.x, head = blockIdx.y;
    int tid = threadIdx.x;
    int cb;
    if (head < NH)            cb = head * DHD;
    else if (head < NH + NKV) cb = EE + (head - NH) * DHD;
    else                      cb = EE + KVD + (head - NH - NKV) * DHD;
    const int n = TT * QKVN;
    #pragma unroll
    for (int it = 0; it < 16; it++) {
        int i = tid + it * 256;
        int r = i >> 6, c = i & 63;
        size_t idx = (size_t)(ttile * 64 + r) * QKVN + cb + c;
        tile[r][c] = part[idx] + part[idx + n] + part[idx + 2 * (size_t)n];
    }
    __syncthreads();
    if (head < NH + NKV) {
        bf16 *dh, *dl; size_t off;
        if (head < NH) { dh = g_qh; dl = g_ql; off = (size_t)head * TT * DHD; }
        else           { dh = g_kh; dl = g_kl; off = (size_t)(head - NH) * TT * DHD; }
        #pragma unroll
        for (int it = 0; it < 16; it++) {
            int i = tid + it * 256;
            int r = i >> 6, d = i & 63;
            int t = ttile * 64 + r;
            float v;
            if (d < 32) {
                int j = d & 15;
                float theta = powf(10000.0f, -(float)j / 16.0f);
                float ang = (float)t * theta;
                float cs = cosf(ang), sn = sinf(ang);
                if (d < 16) v = tile[r][d] * cs - tile[r][d + 16] * sn;
                else        v = tile[r][d] * cs + tile[r][d - 16] * sn;
            } else v = tile[r][d];
            bf16 h, l; split_bf16(v, h, l);
            size_t o = off + (size_t)t * DHD + d;
            dh[o] = h; dl[o] = l;
        }
    } else {
        int kh = head - NH - NKV;
        #pragma unroll
        for (int it = 0; it < 16; it++) {
            int i = tid + it * 256;
            int d = i >> 6, tc = i & 63;
            float v = tile[tc][d];
            bf16 h, l; split_bf16(v, h, l);
            size_t o = ((size_t)kh * DHD + d) * TT + ttile * 64 + tc;
            g_vth[o] = h; g_vtl[o] = l;
        }
    }
}

// ---------------- HMMA attention scores: 64(t) x 128(s), K=64 ----------------
#define SCSM 49152
__global__ __launch_bounds__(256) void scores_mma() {
    int st = blockIdx.x, tt = blockIdx.y, h = blockIdx.z;
    if (2 * st > tt) return;
    int khid = h >> 2;
    extern __shared__ char dsm[];
    const uint32_t sb = (uint32_t)__cvta_generic_to_shared(dsm);
    const int tid = threadIdx.x;
    const int lane = tid & 31, warp = tid >> 5;

    #pragma unroll
    for (int it = 0; it < 12; it++) {
        int i = tid + it * 256;
        const bf16* src; uint32_t dst;
        if (i < 1024) {
            int sub = i >> 9, w = i & 511, r = w >> 3, c = w & 7;
            src = (sub ? g_ql : g_qh) + ((size_t)h * TT + tt * 64 + r) * DHD + c * 8;
            dst = sub * 8192 + sw_off(r, c);
        } else {
            int j = i - 1024;
            int sub = j >> 10, w = j & 1023, r = w >> 3, c = w & 7;
            src = (sub ? g_kl : g_kh) + ((size_t)khid * TT + st * 128 + r) * DHD + c * 8;
            dst = 16384 + sub * 16384 + sw_off(r, c);
        }
        cp16(sb + dst, src);
    }
    CP_COMMIT(); CP_WAIT(0);
    __syncthreads();

    const int wm = warp & 1, wn = warp >> 1;
    const int lr = lane & 15, lcs = lane >> 4;
    float acc[2][4][4];
    #pragma unroll
    for (int a = 0; a < 2; a++)
        #pragma unroll
        for (int b = 0; b < 4; b++)
            #pragma unroll
            for (int c = 0; c < 4; c++) acc[a][b][c] = 0.f;

    #pragma unroll
    for (int k16 = 0; k16 < 4; k16++) {
        const int cch = k16 * 2 + lcs;
        uint32_t ah[2][4], al[2][4];
        #pragma unroll
        for (int mf = 0; mf < 2; mf++) {
            int row = wm * 32 + mf * 16 + lr;
            uint32_t off = sw_off(row, cch);
            ldsm4(ah[mf], sb + off);
            ldsm4(al[mf], sb + 8192 + off);
        }
        #pragma unroll
        for (int g = 0; g < 2; g++) {
            int row = wn * 32 + g * 16 + lr;
            uint32_t off = sw_off(row, cch);
            uint32_t rh[4], rl[4];
            ldsm4(rh, sb + 16384 + off);
            ldsm4(rl, sb + 32768 + off);
            uint32_t b0h[2] = {rh[0], rh[2]}, b1h[2] = {rh[1], rh[3]};
            uint32_t b0l[2] = {rl[0], rl[2]}, b1l[2] = {rl[1], rl[3]};
            #pragma unroll
            for (int mf = 0; mf < 2; mf++) {
                mma_bf16(acc[mf][g*2], ah[mf], b0h);
                mma_bf16(acc[mf][g*2], ah[mf], b0l);
                mma_bf16(acc[mf][g*2], al[mf], b0h);
                mma_bf16(acc[mf][g*2+1], ah[mf], b1h);
                mma_bf16(acc[mf][g*2+1], ah[mf], b1l);
                mma_bf16(acc[mf][g*2+1], al[mf], b1h);
            }
        }
    }
    float* o = g_att + (size_t)h * TT * TT;
    #pragma unroll
    for (int mf = 0; mf < 2; mf++)
        #pragma unroll
        for (int nf = 0; nf < 4; nf++) {
            int r = tt * 64 + wm * 32 + mf * 16 + (lane >> 2);
            int c = st * 128 + wn * 32 + nf * 8 + (lane & 3) * 2;
            float* d = acc[mf][nf];
            *(float2*)(o + (size_t)r * TT + c)       = make_float2(d[0]*0.125f, d[1]*0.125f);
            *(float2*)(o + (size_t)(r + 8) * TT + c) = make_float2(d[2]*0.125f, d[3]*0.125f);
        }
}

// ---------------- single-pass softmax + gate, writes split-bf16 att ----------------
__global__ void softmax_thresh_k(const float* __restrict__ gate_all, int l) {
    __shared__ float sh[256];
    int t = blockIdx.x, h = blockIdx.y;
    int tid = threadIdx.x;
    const float* p = g_att + (size_t)h * TT * TT + (size_t)t * TT;
    float thr = 1.0f / (1.0f + expf(-gate_all[l * NH + h]));
    float x[4];
    #pragma unroll
    for (int k = 0; k < 4; k++) {
        int i = k * 256 + tid;
        x[k] = (i <= t) ? p[i] : -1e30f;
    }
    float m = fmaxf(fmaxf(x[0], x[1]), fmaxf(x[2], x[3]));
    m = blk_max256(m, sh);
    float e[4], s = 0.f;
    #pragma unroll
    for (int k = 0; k < 4; k++) {
        int i = k * 256 + tid;
        e[k] = (i <= t) ? fast_exp(x[k] - m) : 0.f;
        s += e[k];
    }
    s = blk_sum256(s, sh);
    float inv = 1.0f / s;
    int kend = ((t >> 6) + 1) << 6;
    size_t base = (size_t)h * TT * TT + (size_t)t * TT;
    #pragma unroll
    for (int k = 0; k < 4; k++) {
        int i = k * 256 + tid;
        if (i < kend) {
            float pv = e[k] * inv;
            pv = (pv >= thr) ? pv : 0.f;
            bf16 hh2, ll2; split_bf16(pv, hh2, ll2);
            g_atth[base + i] = hh2;
            g_attl[base + i] = ll2;
        }
    }
}

// ---------------- HMMA AV: 64(t) x 64(d), fp16 single output ----------------
#define AVSM 65536
__global__ __launch_bounds__(256) void av_mma() {
    int tt = gridDim.x - 1 - blockIdx.x;    // largest-K blocks launch first
    int h = blockIdx.y;
    int khid = h >> 2;
    int St = tt + 1;
    extern __shared__ char dsm[];
    const uint32_t sb = (uint32_t)__cvta_generic_to_shared(dsm);
    const int tid = threadIdx.x;
    const int lane = tid & 31, warp = tid >> 5;
    const int wm = warp & 1, wn = warp >> 1;
    const int lr = lane & 15, lcs = lane >> 4;

    auto load = [&](int s) {
        uint32_t base = sb + (s & 1) * 32768;
        #pragma unroll
        for (int it = 0; it < 8; it++) {
            int i = tid + it * 256;
            const bf16* src; uint32_t dst;
            if (i < 1024) {
                int sub = i >> 9, w = i & 511, r = w >> 3, c = w & 7;
                src = (sub ? g_attl : g_atth) + ((size_t)h * TT + tt * 64 + r) * TT + s * 64 + c * 8;
                dst = base + sub * 8192 + sw_off(r, c);
            } else {
                int j = i - 1024;
                int sub = j >> 9, w = j & 511, r = w >> 3, c = w & 7;
                src = (sub ? g_vtl : g_vth) + ((size_t)khid * DHD + r) * TT + s * 64 + c * 8;
                dst = base + 16384 + sub * 8192 + sw_off(r, c);
            }
            cp16(dst, src);
        }
        CP_COMMIT();
    };

    load(0);
    if (St > 1) load(1);

    float acc[2][2][4];
    #pragma unroll
    for (int a = 0; a < 2; a++)
        #pragma unroll
        for (int b = 0; b < 2; b++)
            #pragma unroll
            for (int c = 0; c < 4; c++) acc[a][b][c] = 0.f;

    for (int s = 0; s < St; s++) {
        if (s + 1 < St) { CP_WAIT(1); } else { CP_WAIT(0); }
        __syncthreads();
        uint32_t base = sb + (s & 1) * 32768;
        #pragma unroll
        for (int k16 = 0; k16 < 4; k16++) {
            const int cch = k16 * 2 + lcs;
            uint32_t ah[2][4], al[2][4];
            #pragma unroll
            for (int mf = 0; mf < 2; mf++) {
                int row = wm * 32 + mf * 16 + lr;
                uint32_t off = sw_off(row, cch);
                ldsm4(ah[mf], base + off);
                ldsm4(al[mf], base + 8192 + off);
            }
            int row = wn * 16 + lr;
            uint32_t off = sw_off(row, cch);
            uint32_t rh[4], rl[4];
            ldsm4(rh, base + 16384 + off);
            ldsm4(rl, base + 24576 + off);
            uint32_t b0h[2] = {rh[0], rh[2]}, b1h[2] = {rh[1], rh[3]};
            uint32_t b0l[2] = {rl[0], rl[2]}, b1l[2] = {rl[1], rl[3]};
            #pragma unroll
            for (int mf = 0; mf < 2; mf++) {
                mma_bf16(acc[mf][0], ah[mf], b0h);
                mma_bf16(acc[mf][0], ah[mf], b0l);
                mma_bf16(acc[mf][0], al[mf], b0h);
                mma_bf16(acc[mf][1], ah[mf], b1h);
                mma_bf16(acc[mf][1], ah[mf], b1l);
                mma_bf16(acc[mf][1], al[mf], b1h);
            }
        }
        __syncthreads();
        if (s + 2 < St) load(s + 2);
    }

    #pragma unroll
    for (int mf = 0; mf < 2; mf++)
        #pragma unroll
        for (int nf = 0; nf < 2; nf++) {
            int r = tt * 64 + wm * 32 + mf * 16 + (lane >> 2);
            int c = h * DHD + wn * 16 + nf * 8 + (lane & 3) * 2;
            float* d = acc[mf][nf];
            *(__half2*)(g_yf + (size_t)r * EE + c) =
                __halves2half2(__float2half_rn(d[0]), __float2half_rn(d[1]));
            *(__half2*)(g_yf + (size_t)(r + 8) * EE + c) =
                __halves2half2(__float2half_rn(d[2]), __float2half_rn(d[3]));
        }
}

// ---------------- fused residual-add + layernorm + split (bf16 pair or fp16) ----------------
__global__ void add_ln_split_k(float* __restrict__ x, const float* __restrict__ p,
                               const float* __restrict__ g, const float* __restrict__ b,
                               bf16* __restrict__ oh, bf16* __restrict__ ol,
                               __half* __restrict__ of) {
    __shared__ float sh[256];
    int row = blockIdx.x, tid = threadIdx.x;
    const int n = TT * EE;
    float v[4];
    #pragma unroll
    for (int k = 0; k < 4; k++) {
        int i = row * EE + k * 256 + tid;
        v[k] = x[i] + p[i] + p[i + n];
        x[i] = v[k];
    }
    float mu = blk_sum256(v[0] + v[1] + v[2] + v[3], sh) * (1.0f / EE);
    float vs = 0.f;
    #pragma unroll
    for (int k = 0; k < 4; k++) { float d = v[k] - mu; vs += d * d; }
    float var = blk_sum256(vs, sh) * (1.0f / EE);
    float inv = rsqrtf(var + EPSV);
    #pragma unroll
    for (int k = 0; k < 4; k++) {
        int c = k * 256 + tid;
        float o = (v[k] - mu) * inv * g[c] + b[c];
        if (of) {
            of[row * EE + c] = __float2half_rn(o);
        } else {
            bf16 h, l; split_bf16(o, h, l);
            oh[row * EE + c] = h;
            ol[row * EE + c] = l;
        }
    }
}

// ---------------- plain layernorm + split (first LN only) ----------------
__global__ void layernorm_split_k(const float* __restrict__ in, bf16* __restrict__ oh,
                                  bf16* __restrict__ ol,
                                  const float* __restrict__ g, const float* __restrict__ b) {
    __shared__ float sh[256];
    int row = blockIdx.x;
    const float* x = in + (size_t)row * EE;
    float s = 0.f;
    for (int i = threadIdx.x; i < EE; i += 256) s += x[i];
    float mu = blk_sum256(s, sh) * (1.0f / EE);
    float vs = 0.f;
    for (int i = threadIdx.x; i < EE; i += 256) { float d = x[i] - mu; vs += d * d; }
    float var = blk_sum256(vs, sh) * (1.0f / EE);
    float inv = rsqrtf(var + EPSV);
    for (int i = threadIdx.x; i < EE; i += 256) {
        float v = (x[i] - mu) * inv * g[i] + b[i];
        bf16 h, l; split_bf16(v, h, l);
        oh[(size_t)row * EE + i] = h;
        ol[(size_t)row * EE + i] = l;
    }
}

// ---------------- weight transpose + split (bf16) ----------------
__global__ void wtsplit_k(const float* __restrict__ W, bf16* __restrict__ Th,
                          bf16* __restrict__ Tl, int K, int N, int ldt) {
    __shared__ float t[32][33];
    int n0 = blockIdx.x * 32, k0 = blockIdx.y * 32;
    int tx = threadIdx.x, ty = threadIdx.y;
    #pragma unroll
    for (int r = ty; r < 32; r += 8)
        t[r][tx] = W[(size_t)(k0 + r) * N + n0 + tx];
    __syncthreads();
    #pragma unroll
    for (int r = ty; r < 32; r += 8) {
        float v = t[tx][r];
        bf16 h, l; split_bf16(v, h, l);
        Th[(size_t)(n0 + r) * ldt + k0 + tx] = h;
        Tl[(size_t)(n0 + r) * ldt + k0 + tx] = l;
    }
}

// ---------------- weight transpose + split (fp16) ----------------
__global__ void wtsplit_f16_k(const float* __restrict__ W, __half* __restrict__ Th,
                              __half* __restrict__ Tl, int K, int N, int ldt) {
    __shared__ float t[32][33];
    int n0 = blockIdx.x * 32, k0 = blockIdx.y * 32;
    int tx = threadIdx.x, ty = threadIdx.y;
    #pragma unroll
    for (int r = ty; r < 32; r += 8)
        t[r][tx] = W[(size_t)(k0 + r) * N + n0 + tx];
    __syncthreads();
    #pragma unroll
    for (int r = ty; r < 32; r += 8) {
        float v = t[tx][r];
        __half h, l; split_fp16(v, h, l);
        Th[(size_t)(n0 + r) * ldt + k0 + tx] = h;
        Tl[(size_t)(n0 + r) * ldt + k0 + tx] = l;
    }
}

// ---------------- embed split (fp16 hi/lo) ----------------
__global__ void esplit_f16_k(const float* __restrict__ E, __half* __restrict__ Eh,
                             __half* __restrict__ El) {
    size_t i = ((size_t)blockIdx.x * 256 + threadIdx.x) * 4;
    float4 v = *(const float4*)(E + i);
    __half h0,l0,h1,l1,h2,l2,h3,l3;
    split_fp16(v.x,h0,l0); split_fp16(v.y,h1,l1); split_fp16(v.z,h2,l2); split_fp16(v.w,h3,l3);
    *(__half2*)(Eh + i)     = __halves2half2(h0, h1);
    *(__half2*)(Eh + i + 2) = __halves2half2(h2, h3);
    *(__half2*)(El + i)     = __halves2half2(l0, l1);
    *(__half2*)(El + i + 2) = __halves2half2(l2, l3);
}

// ---------------- embedding gather ----------------
__global__ void gather_embed_k(const float* __restrict__ embed, const int* __restrict__ idx) {
    int i = blockIdx.x * blockDim.x + threadIdx.x;
    int t = i >> 10, e = i & 1023;
    g_x[i] = embed[(size_t)idx[t] * EE + e];
}

// ---------------- fused loss: zero rowsums / final reduce ----------------
__global__ void zero_rows_k() {
    int i = blockIdx.x * 256 + threadIdx.x;
    g_rowsum[i] = 0.f;
}

__global__ void loss_fin2_k(const float* __restrict__ logits,
                            const int* __restrict__ tgt, float* __restrict__ dst) {
    __shared__ float sh[1024];
    int t = threadIdx.x;
    float lp = logits[(size_t)t * VV + tgt[t]] - logf(g_rowsum[t]);
    sh[t] = lp; __syncthreads();
    #pragma unroll
    for (int s = 512; s > 0; s >>= 1) {
        if (t < s) sh[t] += sh[t + s];
        __syncthreads();
    }
    if (t == 0) *dst = -sh[0] * (1.0f / (float)TT);
}

// ---------------- host orchestration ----------------
extern "C" void kernel_launch(void* const* d_in, const int* in_sizes, int n_in,
                              void* d_out, int out_size) {
    const float* embed = (const float*)d_in[0];
    const float* ln1_g = (const float*)d_in[1];
    const float* ln1_b = (const float*)d_in[2];
    const float* Wq    = (const float*)d_in[3];
    const float* Wk    = (const float*)d_in[4];
    const float* Wv    = (const float*)d_in[5];
    const float* Wo    = (const float*)d_in[6];
    const float* gate  = (const float*)d_in[7];
    const float* ln2_g = (const float*)d_in[8];
    const float* ln2_b = (const float*)d_in[9];
    const float* W1    = (const float*)d_in[10];
    const float* W2    = (const float*)d_in[11];
    const float* lnf_g = (const float*)d_in[12];
    const float* lnf_b = (const float*)d_in[13];
    const int*   idx   = (const int*)d_in[14];
    const int*   tgt   = (const int*)d_in[15];

    float *xp, *logp, *partp;
    bf16 *hh, *hl;
    bf16 *wqkvh, *wqkvl;
    __half *hf, *fff, *yf, *wofh, *wofl, *w1fh, *w1fl, *w2fh, *w2fl, *efh, *efl;
    cudaGetSymbolAddress((void**)&xp,    g_x);
    cudaGetSymbolAddress((void**)&logp,  g_logits);
    cudaGetSymbolAddress((void**)&partp, g_part);
    cudaGetSymbolAddress((void**)&hh,    g_hh);
    cudaGetSymbolAddress((void**)&hl,    g_hl);
    cudaGetSymbolAddress((void**)&hf,    g_hf);
    cudaGetSymbolAddress((void**)&fff,   g_fff);
    cudaGetSymbolAddress((void**)&yf,    g_yf);
    cudaGetSymbolAddress((void**)&wqkvh, g_wqkv_h);
    cudaGetSymbolAddress((void**)&wqkvl, g_wqkv_l);
    cudaGetSymbolAddress((void**)&wofh,  g_wofh);
    cudaGetSymbolAddress((void**)&wofl,  g_wofl);
    cudaGetSymbolAddress((void**)&w1fh,  g_w1fh);
    cudaGetSymbolAddress((void**)&w1fl,  g_w1fl);
    cudaGetSymbolAddress((void**)&w2fh,  g_w2fh);
    cudaGetSymbolAddress((void**)&w2fl,  g_w2fl);
    cudaGetSymbolAddress((void**)&efh,   g_efh);
    cudaGetSymbolAddress((void**)&efl,   g_efl);

    cudaFuncSetAttribute(gemm_mma<0,128,3>, cudaFuncAttributeMaxDynamicSharedMemorySize, GSM128);
    cudaFuncSetAttribute(fp16_mma<0,128,3,false>, cudaFuncAttributeMaxDynamicSharedMemorySize, F16SM128);
    cudaFuncSetAttribute(fp16_mma<0,256,2,true>, cudaFuncAttributeMaxDynamicSharedMemorySize, F16SM256);
    cudaFuncSetAttribute(fp16_mma<2,256,2,false>, cudaFuncAttributeMaxDynamicSharedMemorySize, F16SM256);
    cudaFuncSetAttribute(scores_mma, cudaFuncAttributeMaxDynamicSharedMemorySize, SCSM);
    cudaFuncSetAttribute(av_mma, cudaFuncAttributeMaxDynamicSharedMemorySize, AVSM);

    // side stream + events (host-side objects, created once)
    static cudaStream_t s2 = nullptr;
    static cudaEvent_t ev_fork = nullptr, ev_w0 = nullptr, ev_w1 = nullptr, ev_e = nullptr;
    if (!s2) {
        cudaStreamCreateWithFlags(&s2, cudaStreamNonBlocking);
        cudaEventCreateWithFlags(&ev_fork, cudaEventDisableTiming);
        cudaEventCreateWithFlags(&ev_w0, cudaEventDisableTiming);
        cudaEventCreateWithFlags(&ev_w1, cudaEventDisableTiming);
        cudaEventCreateWithFlags(&ev_e, cudaEventDisableTiming);
    }

    const size_t BTV = (size_t)TT * VV;
    float* logits_dst = ((size_t)out_size >= BTV) ? (float*)d_out : logp;
    float* loss_dst = nullptr;
    if ((size_t)out_size > BTV)      loss_dst = (float*)d_out + BTV;
    else if ((size_t)out_size < BTV) loss_dst = (float*)d_out;

    dim3 tb(32, 8);

    // ---- fork: non-immediate preprocessing on s2 ----
    cudaEventRecord(ev_fork, 0);
    cudaStreamWaitEvent(s2, ev_fork, 0);

    wtsplit_f16_k<<<dim3(EE/32, EE/32), tb, 0, s2>>>(Wo, wofh, wofl, EE, EE, EE);
    wtsplit_f16_k<<<dim3(FF/32, EE/32), tb, 0, s2>>>(W1, w1fh, w1fl, EE, FF, EE);
    wtsplit_f16_k<<<dim3(EE/32, FF/32), tb, 0, s2>>>(W2, w2fh, w2fl, FF, EE, FF);
    cudaEventRecord(ev_w0, s2);
    {
        const int l = 1;
        wtsplit_k<<<dim3(EE/32, EE/32), tb, 0, s2>>>(Wq + (size_t)l*EE*EE,
            wqkvh + (size_t)l*QKVN*EE, wqkvl + (size_t)l*QKVN*EE, EE, EE, EE);
        wtsplit_k<<<dim3(KVD/32, EE/32), tb, 0, s2>>>(Wk + (size_t)l*EE*KVD,
            wqkvh + (size_t)l*QKVN*EE + (size_t)EE*EE, wqkvl + (size_t)l*QKVN*EE + (size_t)EE*EE, EE, KVD, EE);
        wtsplit_k<<<dim3(KVD/32, EE/32), tb, 0, s2>>>(Wv + (size_t)l*EE*KVD,
            wqkvh + (size_t)l*QKVN*EE + (size_t)(EE+KVD)*EE, wqkvl + (size_t)l*QKVN*EE + (size_t)(EE+KVD)*EE, EE, KVD, EE);
        wtsplit_f16_k<<<dim3(EE/32, EE/32), tb, 0, s2>>>(Wo + (size_t)l*EE*EE,
            wofh + (size_t)l*EE*EE, wofl + (size_t)l*EE*EE, EE, EE, EE);
        wtsplit_f16_k<<<dim3(FF/32, EE/32), tb, 0, s2>>>(W1 + (size_t)l*EE*FF,
            w1fh + (size_t)l*FF*EE, w1fl + (size_t)l*FF*EE, EE, FF, EE);
        wtsplit_f16_k<<<dim3(EE/32, FF/32), tb, 0, s2>>>(W2 + (size_t)l*FF*EE,
            w2fh + (size_t)l*EE*FF, w2fl + (size_t)l*EE*FF, FF, EE, FF);
    }
    cudaEventRecord(ev_w1, s2);
    esplit_f16_k<<<(int)(((size_t)VV*EE)/1024), 256, 0, s2>>>(embed, efh, efl);
    cudaEventRecord(ev_e, s2);

    // ---- main stream: critical path ----
    wtsplit_k<<<dim3(EE/32, EE/32), tb>>>(Wq, wqkvh, wqkvl, EE, EE, EE);
    wtsplit_k<<<dim3(KVD/32, EE/32), tb>>>(Wk, wqkvh + (size_t)EE*EE, wqkvl + (size_t)EE*EE, EE, KVD, EE);
    wtsplit_k<<<dim3(KVD/32, EE/32), tb>>>(Wv, wqkvh + (size_t)(EE+KVD)*EE, wqkvl + (size_t)(EE+KVD)*EE, EE, KVD, EE);
    gather_embed_k<<<(TT * EE) / 256, 256>>>(embed, idx);
    layernorm_split_k<<<TT, 256>>>(xp, hh, hl, ln1_g, ln1_b);

    for (int it = 0; it < RNUM * LNUM; it++) {
        int l = it % LNUM;
        if (it == 1) cudaStreamWaitEvent(0, ev_w1, 0);
        // QKV: 3-term bf16, split-K=3
        gemm_mma<0,128,3><<<dim3(TT/128, QKVN/128, 3), 256, GSM128>>>(hh, hl,
            wqkvh + (size_t)l*QKVN*EE, wqkvl + (size_t)l*QKVN*EE,
            partp, nullptr, nullptr, nullptr, QKVN, EE);
        qkv_post_k<<<dim3(TT/64, NH + 2*NKV), 256>>>(partp);
        scores_mma<<<dim3(TT/128, TT/64, NH), 256, SCSM>>>();
        softmax_thresh_k<<<dim3(TT, NH), 256>>>(gate, l);
        av_mma<<<dim3(TT/64, NH), 256, AVSM>>>();
        if (it == 0) cudaStreamWaitEvent(0, ev_w0, 0);
        // Wo: fp16 2-term, split-K=2; fused x+= & LN2 (fp16 single out for FFN1)
        fp16_mma<0,128,3,false><<<dim3(TT/128, EE/128, 2), 256, F16SM128>>>(yf,
            wofh + (size_t)l*EE*EE, wofl + (size_t)l*EE*EE,
            partp, nullptr, EE, EE);
        add_ln_split_k<<<TT, 256>>>(xp, partp, ln2_g + l * EE, ln2_b + l * EE,
                                    nullptr, nullptr, hf);
        // FFN1: fp16 2-term, gelu -> fp16 single
        fp16_mma<2,256,2,false><<<dim3(TT/128, FF/256, 1), 256, F16SM256>>>(hf,
            w1fh + (size_t)l*FF*EE, w1fl + (size_t)l*FF*EE,
            nullptr, fff, FF, EE);
        // FFN2: fp16 2-term, split-K=2 -> partials
        fp16_mma<0,128,3,false><<<dim3(TT/128, EE/128, 2), 256, F16SM128>>>(fff,
            w2fh + (size_t)l*EE*FF, w2fl + (size_t)l*EE*FF,
            partp, nullptr, EE, FF);
        if (it == RNUM * LNUM - 1) {
            add_ln_split_k<<<TT, 256>>>(xp, partp, lnf_g, lnf_b, nullptr, nullptr, hf);
        } else {
            int ln = (l + 1) % LNUM;
            add_ln_split_k<<<TT, 256>>>(xp, partp, ln1_g + ln * EE, ln1_b + ln * EE,
                                        hh, hl, nullptr);
        }
    }

    // logits: fp16 2-term GEMM with fused per-row sum-of-exp
    zero_rows_k<<<TT/256, 256>>>();
    cudaStreamWaitEvent(0, ev_e, 0);
    fp16_mma<0,256,2,true><<<dim3(TT/128, VV/256, 1), 256, F16SM256>>>(hf, efh, efl,
        logits_dst, nullptr, VV, EE);

    if (loss_dst) loss_fin2_k<<<1, 1024>>>(logits_dst, tgt, loss_dst);
}

// round 14
// speedup vs baseline: 2.2308x; 1.2911x over previous
#include <cuda_runtime.h>
#include <cuda_bf16.h>
#include <cuda_fp16.h>
#include <math.h>
#include <stdint.h>

// ---------------- problem constants ----------------
#define TT 1024
#define EE 1024
#define VV 32000
#define NH 16
#define NKV 4
#define DHD 64
#define KVD (NKV*DHD)     // 256
#define QKVN 1536
#define LNUM 2
#define RNUM 2
#define FF 4096
#define EPSV 1e-5f

typedef __nv_bfloat16 bf16;

// ---------------- device scratch ----------------
__device__ float g_x[TT*EE];
__device__ bf16  g_hh[TT*EE], g_hl[TT*EE];
__device__ __half g_hf[TT*EE];                         // fp16 LN output (LN2 / final)
__device__ __half g_fff[TT*FF];                        // fp16 gelu(FFN1) output
__device__ float g_att[(size_t)NH*TT*TT];
__device__ bf16  g_atth[(size_t)NH*TT*TT], g_attl[(size_t)NH*TT*TT];
__device__ float g_part[3*TT*QKVN];          // split-K partials (reused)
__device__ bf16  g_qh[NH*TT*DHD],  g_ql[NH*TT*DHD];
__device__ bf16  g_kh[NKV*TT*DHD], g_kl[NKV*TT*DHD];
__device__ bf16  g_vth[NKV*DHD*TT], g_vtl[NKV*DHD*TT];   // transposed V
__device__ __half g_yf[TT*EE];                           // fp16 attention output
__device__ bf16  g_wqkv_h[LNUM*QKVN*EE], g_wqkv_l[LNUM*QKVN*EE];
__device__ __half g_wof[LNUM*EE*EE];                     // fp16 Wo (single)
__device__ __half g_w1f[LNUM*FF*EE];                     // fp16 W1 (single)
__device__ __half g_w2f[LNUM*EE*FF];                     // fp16 W2 (single)
__device__ __half g_ef[(size_t)VV*EE];                   // fp16 embed (single)
__device__ float g_logits[(size_t)TT*VV];
__device__ float g_rowsum[TT];                           // fused loss: sum exp(logit)

// ---------------- generic helpers ----------------
__device__ __forceinline__ float blk_sum256(float v, float* sh) {
    int tid = threadIdx.x;
    sh[tid] = v; __syncthreads();
    #pragma unroll
    for (int s = 128; s > 0; s >>= 1) { if (tid < s) sh[tid] += sh[tid + s]; __syncthreads(); }
    float r = sh[0]; __syncthreads();
    return r;
}
__device__ __forceinline__ float blk_max256(float v, float* sh) {
    int tid = threadIdx.x;
    sh[tid] = v; __syncthreads();
    #pragma unroll
    for (int s = 128; s > 0; s >>= 1) { if (tid < s) sh[tid] = fmaxf(sh[tid], sh[tid + s]); __syncthreads(); }
    float r = sh[0]; __syncthreads();
    return r;
}
__device__ __forceinline__ float gelu_exact(float x) {
    return 0.5f * x * (1.0f + erff(x * 0.7071067811865476f));
}
__device__ __forceinline__ void split_bf16(float v, bf16& h, bf16& l) {
    h = __float2bfloat16(v);
    l = __float2bfloat16(v - __bfloat162float(h));
}
// MUFU-free exp: rint range reduction + degree-5 Taylor, rel err ~3e-6
__device__ __forceinline__ float fast_exp(float v) {
    float t = v * 1.44269504f;
    t = fmaxf(t, -120.0f);
    float r = rintf(t);
    float f = (t - r) * 0.69314718f;   // |f| <= 0.3466
    float p = 1.0f + f * (1.0f + f * (0.5f + f * (0.166666667f
             + f * (0.0416666667f + f * 0.00833333333f))));
    return __int_as_float(((int)(127.0f + r)) << 23) * p;
}

// ---------------- PTX wrappers ----------------
__device__ __forceinline__ void mma_bf16(float* d, const uint32_t* a, const uint32_t* b) {
    asm volatile("mma.sync.aligned.m16n8k16.row.col.f32.bf16.bf16.f32 "
        "{%0,%1,%2,%3}, {%4,%5,%6,%7}, {%8,%9}, {%0,%1,%2,%3};"
        : "+f"(d[0]), "+f"(d[1]), "+f"(d[2]), "+f"(d[3])
        : "r"(a[0]), "r"(a[1]), "r"(a[2]), "r"(a[3]), "r"(b[0]), "r"(b[1]));
}
__device__ __forceinline__ void mma_fp16(float* d, const uint32_t* a, const uint32_t* b) {
    asm volatile("mma.sync.aligned.m16n8k16.row.col.f32.f16.f16.f32 "
        "{%0,%1,%2,%3}, {%4,%5,%6,%7}, {%8,%9}, {%0,%1,%2,%3};"
        : "+f"(d[0]), "+f"(d[1]), "+f"(d[2]), "+f"(d[3])
        : "r"(a[0]), "r"(a[1]), "r"(a[2]), "r"(a[3]), "r"(b[0]), "r"(b[1]));
}
__device__ __forceinline__ void ldsm4(uint32_t* r, uint32_t addr) {
    asm volatile("ldmatrix.sync.aligned.m8n8.x4.shared.b16 {%0,%1,%2,%3}, [%4];"
        : "=r"(r[0]), "=r"(r[1]), "=r"(r[2]), "=r"(r[3]) : "r"(addr));
}
__device__ __forceinline__ void cp16(uint32_t s, const void* g) {
    asm volatile("cp.async.cg.shared.global [%0], [%1], 16;" :: "r"(s), "l"(g));
}
#define CP_COMMIT()  asm volatile("cp.async.commit_group;")
#define CP_WAIT(n)   asm volatile("cp.async.wait_group %0;" :: "n"(n))

// SW128 swizzle: 128B rows, 16B chunks, chunk ^= row&7  (conflict-free ldmatrix)
__device__ __forceinline__ uint32_t sw_off(int row, int chunk) {
    return (uint32_t)(row * 128 + ((chunk ^ (row & 7)) << 4));
}

// ---------------- split-bf16 3-term HMMA GEMM (QKV only) ----------------
template<int MODE, int TN, int NSTG>
__global__ __launch_bounds__(256, 1) void gemm_mma(
    const bf16* __restrict__ Ah, const bf16* __restrict__ Al,
    const bf16* __restrict__ Bh, const bf16* __restrict__ Bl,
    float* C, int N, int K)
{
    constexpr int TSA = 128 * 128;
    constexpr int TSB = TN * 128;
    constexpr int SB  = 2 * TSA + 2 * TSB;
    constexpr int BCH = TN * 8;
    constexpr int TC  = 2048 + 2 * BCH;
    constexpr int NG  = TN / 64;
    constexpr int NF  = 2 * NG;

    extern __shared__ char dsm[];
    const int tid = threadIdx.x;
    const int lane = tid & 31, warp = tid >> 5;
    const int wm = warp & 1, wn = warp >> 1;
    const int row0 = blockIdx.x * 128, col0 = blockIdx.y * TN;
    const uint32_t sb = (uint32_t)__cvta_generic_to_shared(dsm);

    float acc[4][NF][4];
    #pragma unroll
    for (int i = 0; i < 4; i++)
        #pragma unroll
        for (int j = 0; j < NF; j++)
            #pragma unroll
            for (int r = 0; r < 4; r++) acc[i][j][r] = 0.f;

    auto load_stage = [&](int s) {
        int k0 = s * 64;
        uint32_t base = sb + (s % NSTG) * SB;
        #pragma unroll
        for (int ii = 0; ii < TC / 256; ii++) {
            int i = tid + ii * 256;
            const bf16* src;
            uint32_t toff;
            if (i < 2048) {
                int t = i >> 10, w = i & 1023;
                int r = w >> 3, c = w & 7;
                src = (t ? Al : Ah) + (size_t)(row0 + r) * K + k0 + c * 8;
                toff = t * TSA + sw_off(r, c);
            } else {
                int j = i - 2048;
                int t = j / BCH, w = j & (BCH - 1);
                int r = w >> 3, c = w & 7;
                src = (t ? Bl : Bh) + (size_t)(col0 + r) * K + k0 + c * 8;
                toff = 2 * TSA + t * TSB + sw_off(r, c);
            }
            cp16(base + toff, src);
        }
        CP_COMMIT();
    };

    const int Stot = K >> 6;
    const int SK = gridDim.z;
    const int Sc = (Stot + SK - 1) / SK;
    const int s0 = blockIdx.z * Sc;
    const int s1 = min(Stot, s0 + Sc);

    #pragma unroll
    for (int i = 0; i < NSTG; i++)
        if (s0 + i < s1) load_stage(s0 + i);

    const int lr = lane & 15, lcs = lane >> 4;

    for (int s = s0; s < s1; s++) {
        int ahead = s1 - 1 - s;
        int w = ahead < (NSTG - 1) ? ahead : (NSTG - 1);
        if (w == 2)      { CP_WAIT(2); }
        else if (w == 1) { CP_WAIT(1); }
        else             { CP_WAIT(0); }
        __syncthreads();
        uint32_t ab = sb + (s % NSTG) * SB;
        #pragma unroll
        for (int k16 = 0; k16 < 4; k16++) {
            const int cch = k16 * 2 + lcs;
            uint32_t ah[4][4], al[4][4];
            #pragma unroll
            for (int mf = 0; mf < 4; mf++) {
                int row = wm * 64 + mf * 16 + lr;
                uint32_t off = sw_off(row, cch);
                ldsm4(ah[mf], ab + off);
                ldsm4(al[mf], ab + TSA + off);
            }
            #pragma unroll
            for (int g = 0; g < NG; g++) {
                int row = wn * (TN / 4) + g * 16 + lr;
                uint32_t off = sw_off(row, cch);
                uint32_t rh[4], rl[4];
                ldsm4(rh, ab + 2 * TSA + off);
                ldsm4(rl, ab + 2 * TSA + TSB + off);
                uint32_t b0h[2] = {rh[0], rh[2]}, b1h[2] = {rh[1], rh[3]};
                uint32_t b0l[2] = {rl[0], rl[2]}, b1l[2] = {rl[1], rl[3]};
                #pragma unroll
                for (int mf = 0; mf < 4; mf++) {
                    mma_bf16(acc[mf][g*2], ah[mf], b0h);
                    mma_bf16(acc[mf][g*2], ah[mf], b0l);
                    mma_bf16(acc[mf][g*2], al[mf], b0h);
                    mma_bf16(acc[mf][g*2+1], ah[mf], b1h);
                    mma_bf16(acc[mf][g*2+1], ah[mf], b1l);
                    mma_bf16(acc[mf][g*2+1], al[mf], b1h);
                }
            }
        }
        __syncthreads();
        if (s + NSTG < s1) load_stage(s + NSTG);
    }

    const size_t pstride = (size_t)gridDim.x * 128 * N;
    float* Cp = C + (size_t)blockIdx.z * pstride;
    #pragma unroll
    for (int mf = 0; mf < 4; mf++)
        #pragma unroll
        for (int nf = 0; nf < NF; nf++) {
            int r = row0 + wm * 64 + mf * 16 + (lane >> 2);
            int c = col0 + wn * (TN / 4) + nf * 8 + (lane & 3) * 2;
            float* d = acc[mf][nf];
            *(float2*)(Cp + (size_t)r * N + c)       = make_float2(d[0], d[1]);
            *(float2*)(Cp + (size_t)(r + 8) * N + c) = make_float2(d[2], d[3]);
        }
}

#define GSM128 (3 * (2*128*128 + 2*128*128))   // 196608

// ---------------- 1-term fp16 GEMM (Wo / FFN / logits): C = A * B^T ----------------
// A fp16 single, B fp16 single. 1 MMA per logical op.
// MODE 0: fp32 store (split-K slab if gridDim.z>1). MODE 2: gelu -> fp16 single Of.
// LOSS: accumulate per-row sum of exp(logit) into g_rowsum (logits only).
template<int MODE, int TN, int NSTG, bool LOSS>
__global__ __launch_bounds__(256, 1) void fp16_mma(
    const __half* __restrict__ A, const __half* __restrict__ B,
    float* __restrict__ C, __half* __restrict__ Of, int N, int K)
{
    constexpr int TSA = 128 * 128;
    constexpr int TSB = TN * 128;
    constexpr int SB  = TSA + TSB;
    constexpr int BCH = TN * 8;
    constexpr int TC  = 1024 + BCH;
    constexpr int NG  = TN / 64;
    constexpr int NF  = 2 * NG;

    extern __shared__ char dsm[];
    const int tid = threadIdx.x;
    const int lane = tid & 31, warp = tid >> 5;
    const int wm = warp & 1, wn = warp >> 1;
    const int row0 = blockIdx.x * 128, col0 = blockIdx.y * TN;
    const uint32_t sb = (uint32_t)__cvta_generic_to_shared(dsm);

    float acc[4][NF][4];
    #pragma unroll
    for (int i = 0; i < 4; i++)
        #pragma unroll
        for (int j = 0; j < NF; j++)
            #pragma unroll
            for (int r = 0; r < 4; r++) acc[i][j][r] = 0.f;

    auto load_stage = [&](int s) {
        int k0 = s * 64;
        uint32_t base = sb + (s % NSTG) * SB;
        #pragma unroll
        for (int ii = 0; ii < TC / 256; ii++) {
            int i = tid + ii * 256;
            const __half* src; uint32_t toff;
            if (i < 1024) {
                int r = i >> 3, c = i & 7;
                src = A + (size_t)(row0 + r) * K + k0 + c * 8;
                toff = sw_off(r, c);
            } else {
                int j = i - 1024;
                int r = j >> 3, c = j & 7;
                src = B + (size_t)(col0 + r) * K + k0 + c * 8;
                toff = TSA + sw_off(r, c);
            }
            cp16(base + toff, src);
        }
        CP_COMMIT();
    };

    const int Stot = K >> 6;
    const int SK = gridDim.z;
    const int Sc = (Stot + SK - 1) / SK;
    const int s0 = blockIdx.z * Sc;
    const int s1 = min(Stot, s0 + Sc);

    #pragma unroll
    for (int i = 0; i < NSTG; i++)
        if (s0 + i < s1) load_stage(s0 + i);

    const int lr = lane & 15, lcs = lane >> 4;

    for (int s = s0; s < s1; s++) {
        int ahead = s1 - 1 - s;
        int w = ahead < (NSTG - 1) ? ahead : (NSTG - 1);
        if (w == 2)      { CP_WAIT(2); }
        else if (w == 1) { CP_WAIT(1); }
        else             { CP_WAIT(0); }
        __syncthreads();
        uint32_t ab = sb + (s % NSTG) * SB;
        #pragma unroll
        for (int k16 = 0; k16 < 4; k16++) {
            const int cch = k16 * 2 + lcs;
            uint32_t ah[4][4];
            #pragma unroll
            for (int mf = 0; mf < 4; mf++)
                ldsm4(ah[mf], ab + sw_off(wm * 64 + mf * 16 + lr, cch));
            #pragma unroll
            for (int g = 0; g < NG; g++) {
                uint32_t off = sw_off(wn * (TN / 4) + g * 16 + lr, cch);
                uint32_t rh[4];
                ldsm4(rh, ab + TSA + off);
                uint32_t b0[2] = {rh[0], rh[2]}, b1[2] = {rh[1], rh[3]};
                #pragma unroll
                for (int mf = 0; mf < 4; mf++) {
                    mma_fp16(acc[mf][g*2],   ah[mf], b0);
                    mma_fp16(acc[mf][g*2+1], ah[mf], b1);
                }
            }
        }
        __syncthreads();
        if (s + NSTG < s1) load_stage(s + NSTG);
    }

    const size_t pstride = (size_t)gridDim.x * 128 * N;
    float* Cp = C + (size_t)blockIdx.z * pstride;
    float lsum[4][2];
    if (LOSS) {
        #pragma unroll
        for (int mf = 0; mf < 4; mf++) { lsum[mf][0] = 0.f; lsum[mf][1] = 0.f; }
    }
    #pragma unroll
    for (int mf = 0; mf < 4; mf++)
        #pragma unroll
        for (int nf = 0; nf < NF; nf++) {
            int r = row0 + wm * 64 + mf * 16 + (lane >> 2);
            int c = col0 + wn * (TN / 4) + nf * 8 + (lane & 3) * 2;
            float* d = acc[mf][nf];
            if (MODE == 0) {
                *(float2*)(Cp + (size_t)r * N + c)       = make_float2(d[0], d[1]);
                *(float2*)(Cp + (size_t)(r + 8) * N + c) = make_float2(d[2], d[3]);
                if (LOSS) {
                    lsum[mf][0] += fast_exp(d[0]) + fast_exp(d[1]);
                    lsum[mf][1] += fast_exp(d[2]) + fast_exp(d[3]);
                }
            } else {
                __half o0 = __float2half_rn(gelu_exact(d[0]));
                __half o1 = __float2half_rn(gelu_exact(d[1]));
                __half o2 = __float2half_rn(gelu_exact(d[2]));
                __half o3 = __float2half_rn(gelu_exact(d[3]));
                *(__half2*)(Of + (size_t)r * N + c)       = __halves2half2(o0, o1);
                *(__half2*)(Of + (size_t)(r + 8) * N + c) = __halves2half2(o2, o3);
            }
        }
    if (LOSS) {
        float* rs = (float*)dsm;
        if (tid < 128) rs[tid] = 0.f;
        __syncthreads();
        #pragma unroll
        for (int mf = 0; mf < 4; mf++) {
            int rl0 = wm * 64 + mf * 16 + (lane >> 2);
            atomicAdd(&rs[rl0], lsum[mf][0]);
            atomicAdd(&rs[rl0 + 8], lsum[mf][1]);
        }
        __syncthreads();
        if (tid < 128) atomicAdd(&g_rowsum[row0 + tid], rs[tid]);
    }
}

#define F16SM128 (3 * (128*128 + 128*128))     // 98304
#define F16SM256 (2 * (128*128 + 256*128))     // 98304

// ---------------- fused QKV reduce + RoPE/transpose + split ----------------
__global__ void qkv_post_k(const float* __restrict__ part) {
    __shared__ float tile[64][65];
    int ttile = blockIdx.x, head = blockIdx.y;
    int tid = threadIdx.x;
    int cb;
    if (head < NH)            cb = head * DHD;
    else if (head < NH + NKV) cb = EE + (head - NH) * DHD;
    else                      cb = EE + KVD + (head - NH - NKV) * DHD;
    const int n = TT * QKVN;
    #pragma unroll
    for (int it = 0; it < 16; it++) {
        int i = tid + it * 256;
        int r = i >> 6, c = i & 63;
        size_t idx = (size_t)(ttile * 64 + r) * QKVN + cb + c;
        tile[r][c] = part[idx] + part[idx + n] + part[idx + 2 * (size_t)n];
    }
    __syncthreads();
    if (head < NH + NKV) {
        bf16 *dh, *dl; size_t off;
        if (head < NH) { dh = g_qh; dl = g_ql; off = (size_t)head * TT * DHD; }
        else           { dh = g_kh; dl = g_kl; off = (size_t)(head - NH) * TT * DHD; }
        #pragma unroll
        for (int it = 0; it < 16; it++) {
            int i = tid + it * 256;
            int r = i >> 6, d = i & 63;
            int t = ttile * 64 + r;
            float v;
            if (d < 32) {
                int j = d & 15;
                float theta = powf(10000.0f, -(float)j / 16.0f);
                float ang = (float)t * theta;
                float cs = cosf(ang), sn = sinf(ang);
                if (d < 16) v = tile[r][d] * cs - tile[r][d + 16] * sn;
                else        v = tile[r][d] * cs + tile[r][d - 16] * sn;
            } else v = tile[r][d];
            bf16 h, l; split_bf16(v, h, l);
            size_t o = off + (size_t)t * DHD + d;
            dh[o] = h; dl[o] = l;
        }
    } else {
        int kh = head - NH - NKV;
        #pragma unroll
        for (int it = 0; it < 16; it++) {
            int i = tid + it * 256;
            int d = i >> 6, tc = i & 63;
            float v = tile[tc][d];
            bf16 h, l; split_bf16(v, h, l);
            size_t o = ((size_t)kh * DHD + d) * TT + ttile * 64 + tc;
            g_vth[o] = h; g_vtl[o] = l;
        }
    }
}

// ---------------- HMMA attention scores: 64(t) x 128(s), K=64 ----------------
#define SCSM 49152
__global__ __launch_bounds__(256) void scores_mma() {
    int st = blockIdx.x, tt = blockIdx.y, h = blockIdx.z;
    if (2 * st > tt) return;
    int khid = h >> 2;
    extern __shared__ char dsm[];
    const uint32_t sb = (uint32_t)__cvta_generic_to_shared(dsm);
    const int tid = threadIdx.x;
    const int lane = tid & 31, warp = tid >> 5;

    #pragma unroll
    for (int it = 0; it < 12; it++) {
        int i = tid + it * 256;
        const bf16* src; uint32_t dst;
        if (i < 1024) {
            int sub = i >> 9, w = i & 511, r = w >> 3, c = w & 7;
            src = (sub ? g_ql : g_qh) + ((size_t)h * TT + tt * 64 + r) * DHD + c * 8;
            dst = sub * 8192 + sw_off(r, c);
        } else {
            int j = i - 1024;
            int sub = j >> 10, w = j & 1023, r = w >> 3, c = w & 7;
            src = (sub ? g_kl : g_kh) + ((size_t)khid * TT + st * 128 + r) * DHD + c * 8;
            dst = 16384 + sub * 16384 + sw_off(r, c);
        }
        cp16(sb + dst, src);
    }
    CP_COMMIT(); CP_WAIT(0);
    __syncthreads();

    const int wm = warp & 1, wn = warp >> 1;
    const int lr = lane & 15, lcs = lane >> 4;
    float acc[2][4][4];
    #pragma unroll
    for (int a = 0; a < 2; a++)
        #pragma unroll
        for (int b = 0; b < 4; b++)
            #pragma unroll
            for (int c = 0; c < 4; c++) acc[a][b][c] = 0.f;

    #pragma unroll
    for (int k16 = 0; k16 < 4; k16++) {
        const int cch = k16 * 2 + lcs;
        uint32_t ah[2][4], al[2][4];
        #pragma unroll
        for (int mf = 0; mf < 2; mf++) {
            int row = wm * 32 + mf * 16 + lr;
            uint32_t off = sw_off(row, cch);
            ldsm4(ah[mf], sb + off);
            ldsm4(al[mf], sb + 8192 + off);
        }
        #pragma unroll
        for (int g = 0; g < 2; g++) {
            int row = wn * 32 + g * 16 + lr;
            uint32_t off = sw_off(row, cch);
            uint32_t rh[4], rl[4];
            ldsm4(rh, sb + 16384 + off);
            ldsm4(rl, sb + 32768 + off);
            uint32_t b0h[2] = {rh[0], rh[2]}, b1h[2] = {rh[1], rh[3]};
            uint32_t b0l[2] = {rl[0], rl[2]}, b1l[2] = {rl[1], rl[3]};
            #pragma unroll
            for (int mf = 0; mf < 2; mf++) {
                mma_bf16(acc[mf][g*2], ah[mf], b0h);
                mma_bf16(acc[mf][g*2], ah[mf], b0l);
                mma_bf16(acc[mf][g*2], al[mf], b0h);
                mma_bf16(acc[mf][g*2+1], ah[mf], b1h);
                mma_bf16(acc[mf][g*2+1], ah[mf], b1l);
                mma_bf16(acc[mf][g*2+1], al[mf], b1h);
            }
        }
    }
    float* o = g_att + (size_t)h * TT * TT;
    #pragma unroll
    for (int mf = 0; mf < 2; mf++)
        #pragma unroll
        for (int nf = 0; nf < 4; nf++) {
            int r = tt * 64 + wm * 32 + mf * 16 + (lane >> 2);
            int c = st * 128 + wn * 32 + nf * 8 + (lane & 3) * 2;
            float* d = acc[mf][nf];
            *(float2*)(o + (size_t)r * TT + c)       = make_float2(d[0]*0.125f, d[1]*0.125f);
            *(float2*)(o + (size_t)(r + 8) * TT + c) = make_float2(d[2]*0.125f, d[3]*0.125f);
        }
}

// ---------------- single-pass softmax + gate, writes split-bf16 att ----------------
__global__ void softmax_thresh_k(const float* __restrict__ gate_all, int l) {
    __shared__ float sh[256];
    int t = blockIdx.x, h = blockIdx.y;
    int tid = threadIdx.x;
    const float* p = g_att + (size_t)h * TT * TT + (size_t)t * TT;
    float thr = 1.0f / (1.0f + expf(-gate_all[l * NH + h]));
    float x[4];
    #pragma unroll
    for (int k = 0; k < 4; k++) {
        int i = k * 256 + tid;
        x[k] = (i <= t) ? p[i] : -1e30f;
    }
    float m = fmaxf(fmaxf(x[0], x[1]), fmaxf(x[2], x[3]));
    m = blk_max256(m, sh);
    float e[4], s = 0.f;
    #pragma unroll
    for (int k = 0; k < 4; k++) {
        int i = k * 256 + tid;
        e[k] = (i <= t) ? fast_exp(x[k] - m) : 0.f;
        s += e[k];
    }
    s = blk_sum256(s, sh);
    float inv = 1.0f / s;
    int kend = ((t >> 6) + 1) << 6;
    size_t base = (size_t)h * TT * TT + (size_t)t * TT;
    #pragma unroll
    for (int k = 0; k < 4; k++) {
        int i = k * 256 + tid;
        if (i < kend) {
            float pv = e[k] * inv;
            pv = (pv >= thr) ? pv : 0.f;
            bf16 hh2, ll2; split_bf16(pv, hh2, ll2);
            g_atth[base + i] = hh2;
            g_attl[base + i] = ll2;
        }
    }
}

// ---------------- HMMA AV: 64(t) x 64(d), fp16 single output ----------------
#define AVSM 65536
__global__ __launch_bounds__(256) void av_mma() {
    int tt = gridDim.x - 1 - blockIdx.x;    // largest-K blocks launch first
    int h = blockIdx.y;
    int khid = h >> 2;
    int St = tt + 1;
    extern __shared__ char dsm[];
    const uint32_t sb = (uint32_t)__cvta_generic_to_shared(dsm);
    const int tid = threadIdx.x;
    const int lane = tid & 31, warp = tid >> 5;
    const int wm = warp & 1, wn = warp >> 1;
    const int lr = lane & 15, lcs = lane >> 4;

    auto load = [&](int s) {
        uint32_t base = sb + (s & 1) * 32768;
        #pragma unroll
        for (int it = 0; it < 8; it++) {
            int i = tid + it * 256;
            const bf16* src; uint32_t dst;
            if (i < 1024) {
                int sub = i >> 9, w = i & 511, r = w >> 3, c = w & 7;
                src = (sub ? g_attl : g_atth) + ((size_t)h * TT + tt * 64 + r) * TT + s * 64 + c * 8;
                dst = base + sub * 8192 + sw_off(r, c);
            } else {
                int j = i - 1024;
                int sub = j >> 9, w = j & 511, r = w >> 3, c = w & 7;
                src = (sub ? g_vtl : g_vth) + ((size_t)khid * DHD + r) * TT + s * 64 + c * 8;
                dst = base + 16384 + sub * 8192 + sw_off(r, c);
            }
            cp16(dst, src);
        }
        CP_COMMIT();
    };

    load(0);
    if (St > 1) load(1);

    float acc[2][2][4];
    #pragma unroll
    for (int a = 0; a < 2; a++)
        #pragma unroll
        for (int b = 0; b < 2; b++)
            #pragma unroll
            for (int c = 0; c < 4; c++) acc[a][b][c] = 0.f;

    for (int s = 0; s < St; s++) {
        if (s + 1 < St) { CP_WAIT(1); } else { CP_WAIT(0); }
        __syncthreads();
        uint32_t base = sb + (s & 1) * 32768;
        #pragma unroll
        for (int k16 = 0; k16 < 4; k16++) {
            const int cch = k16 * 2 + lcs;
            uint32_t ah[2][4], al[2][4];
            #pragma unroll
            for (int mf = 0; mf < 2; mf++) {
                int row = wm * 32 + mf * 16 + lr;
                uint32_t off = sw_off(row, cch);
                ldsm4(ah[mf], base + off);
                ldsm4(al[mf], base + 8192 + off);
            }
            int row = wn * 16 + lr;
            uint32_t off = sw_off(row, cch);
            uint32_t rh[4], rl[4];
            ldsm4(rh, base + 16384 + off);
            ldsm4(rl, base + 24576 + off);
            uint32_t b0h[2] = {rh[0], rh[2]}, b1h[2] = {rh[1], rh[3]};
            uint32_t b0l[2] = {rl[0], rl[2]}, b1l[2] = {rl[1], rl[3]};
            #pragma unroll
            for (int mf = 0; mf < 2; mf++) {
                mma_bf16(acc[mf][0], ah[mf], b0h);
                mma_bf16(acc[mf][0], ah[mf], b0l);
                mma_bf16(acc[mf][0], al[mf], b0h);
                mma_bf16(acc[mf][1], ah[mf], b1h);
                mma_bf16(acc[mf][1], ah[mf], b1l);
                mma_bf16(acc[mf][1], al[mf], b1h);
            }
        }
        __syncthreads();
        if (s + 2 < St) load(s + 2);
    }

    #pragma unroll
    for (int mf = 0; mf < 2; mf++)
        #pragma unroll
        for (int nf = 0; nf < 2; nf++) {
            int r = tt * 64 + wm * 32 + mf * 16 + (lane >> 2);
            int c = h * DHD + wn * 16 + nf * 8 + (lane & 3) * 2;
            float* d = acc[mf][nf];
            *(__half2*)(g_yf + (size_t)r * EE + c) =
                __halves2half2(__float2half_rn(d[0]), __float2half_rn(d[1]));
            *(__half2*)(g_yf + (size_t)(r + 8) * EE + c) =
                __halves2half2(__float2half_rn(d[2]), __float2half_rn(d[3]));
        }
}

// ---------------- fused residual-add + layernorm + split (bf16 pair or fp16) ----------------
__global__ void add_ln_split_k(float* __restrict__ x, const float* __restrict__ p,
                               const float* __restrict__ g, const float* __restrict__ b,
                               bf16* __restrict__ oh, bf16* __restrict__ ol,
                               __half* __restrict__ of) {
    __shared__ float sh[256];
    int row = blockIdx.x, tid = threadIdx.x;
    const int n = TT * EE;
    float v[4];
    #pragma unroll
    for (int k = 0; k < 4; k++) {
        int i = row * EE + k * 256 + tid;
        v[k] = x[i] + p[i] + p[i + n];
        x[i] = v[k];
    }
    float mu = blk_sum256(v[0] + v[1] + v[2] + v[3], sh) * (1.0f / EE);
    float vs = 0.f;
    #pragma unroll
    for (int k = 0; k < 4; k++) { float d = v[k] - mu; vs += d * d; }
    float var = blk_sum256(vs, sh) * (1.0f / EE);
    float inv = rsqrtf(var + EPSV);
    #pragma unroll
    for (int k = 0; k < 4; k++) {
        int c = k * 256 + tid;
        float o = (v[k] - mu) * inv * g[c] + b[c];
        if (of) {
            of[row * EE + c] = __float2half_rn(o);
        } else {
            bf16 h, l; split_bf16(o, h, l);
            oh[row * EE + c] = h;
            ol[row * EE + c] = l;
        }
    }
}

// ---------------- plain layernorm + split (first LN only) ----------------
__global__ void layernorm_split_k(const float* __restrict__ in, bf16* __restrict__ oh,
                                  bf16* __restrict__ ol,
                                  const float* __restrict__ g, const float* __restrict__ b) {
    __shared__ float sh[256];
    int row = blockIdx.x;
    const float* x = in + (size_t)row * EE;
    float s = 0.f;
    for (int i = threadIdx.x; i < EE; i += 256) s += x[i];
    float mu = blk_sum256(s, sh) * (1.0f / EE);
    float vs = 0.f;
    for (int i = threadIdx.x; i < EE; i += 256) { float d = x[i] - mu; vs += d * d; }
    float var = blk_sum256(vs, sh) * (1.0f / EE);
    float inv = rsqrtf(var + EPSV);
    for (int i = threadIdx.x; i < EE; i += 256) {
        float v = (x[i] - mu) * inv * g[i] + b[i];
        bf16 h, l; split_bf16(v, h, l);
        oh[(size_t)row * EE + i] = h;
        ol[(size_t)row * EE + i] = l;
    }
}

// ---------------- weight transpose + split (bf16 hi/lo, QKV only) ----------------
__global__ void wtsplit_k(const float* __restrict__ W, bf16* __restrict__ Th,
                          bf16* __restrict__ Tl, int K, int N, int ldt) {
    __shared__ float t[32][33];
    int n0 = blockIdx.x * 32, k0 = blockIdx.y * 32;
    int tx = threadIdx.x, ty = threadIdx.y;
    #pragma unroll
    for (int r = ty; r < 32; r += 8)
        t[r][tx] = W[(size_t)(k0 + r) * N + n0 + tx];
    __syncthreads();
    #pragma unroll
    for (int r = ty; r < 32; r += 8) {
        float v = t[tx][r];
        bf16 h, l; split_bf16(v, h, l);
        Th[(size_t)(n0 + r) * ldt + k0 + tx] = h;
        Tl[(size_t)(n0 + r) * ldt + k0 + tx] = l;
    }
}

// ---------------- weight transpose (fp16 single) ----------------
__global__ void wtf16_k(const float* __restrict__ W, __half* __restrict__ T,
                        int K, int N, int ldt) {
    __shared__ float t[32][33];
    int n0 = blockIdx.x * 32, k0 = blockIdx.y * 32;
    int tx = threadIdx.x, ty = threadIdx.y;
    #pragma unroll
    for (int r = ty; r < 32; r += 8)
        t[r][tx] = W[(size_t)(k0 + r) * N + n0 + tx];
    __syncthreads();
    #pragma unroll
    for (int r = ty; r < 32; r += 8)
        T[(size_t)(n0 + r) * ldt + k0 + tx] = __float2half_rn(t[tx][r]);
}

// ---------------- embed convert (fp16 single) ----------------
__global__ void ef16_k(const float* __restrict__ E, __half* __restrict__ T) {
    size_t i = ((size_t)blockIdx.x * 256 + threadIdx.x) * 4;
    float4 v = *(const float4*)(E + i);
    *(__half2*)(T + i)     = __halves2half2(__float2half_rn(v.x), __float2half_rn(v.y));
    *(__half2*)(T + i + 2) = __halves2half2(__float2half_rn(v.z), __float2half_rn(v.w));
}

// ---------------- embedding gather ----------------
__global__ void gather_embed_k(const float* __restrict__ embed, const int* __restrict__ idx) {
    int i = blockIdx.x * blockDim.x + threadIdx.x;
    int t = i >> 10, e = i & 1023;
    g_x[i] = embed[(size_t)idx[t] * EE + e];
}

// ---------------- fused loss helpers ----------------
__global__ void zero_rows_k() {
    int i = blockIdx.x * 256 + threadIdx.x;
    g_rowsum[i] = 0.f;
}

__global__ void loss_fin2_k(const float* __restrict__ logits,
                            const int* __restrict__ tgt, float* __restrict__ dst) {
    __shared__ float sh[1024];
    int t = threadIdx.x;
    float lp = logits[(size_t)t * VV + tgt[t]] - logf(g_rowsum[t]);
    sh[t] = lp; __syncthreads();
    #pragma unroll
    for (int s = 512; s > 0; s >>= 1) {
        if (t < s) sh[t] += sh[t + s];
        __syncthreads();
    }
    if (t == 0) *dst = -sh[0] * (1.0f / (float)TT);
}

// ---------------- host orchestration ----------------
extern "C" void kernel_launch(void* const* d_in, const int* in_sizes, int n_in,
                              void* d_out, int out_size) {
    const float* embed = (const float*)d_in[0];
    const float* ln1_g = (const float*)d_in[1];
    const float* ln1_b = (const float*)d_in[2];
    const float* Wq    = (const float*)d_in[3];
    const float* Wk    = (const float*)d_in[4];
    const float* Wv    = (const float*)d_in[5];
    const float* Wo    = (const float*)d_in[6];
    const float* gate  = (const float*)d_in[7];
    const float* ln2_g = (const float*)d_in[8];
    const float* ln2_b = (const float*)d_in[9];
    const float* W1    = (const float*)d_in[10];
    const float* W2    = (const float*)d_in[11];
    const float* lnf_g = (const float*)d_in[12];
    const float* lnf_b = (const float*)d_in[13];
    const int*   idx   = (const int*)d_in[14];
    const int*   tgt   = (const int*)d_in[15];

    float *xp, *logp, *partp;
    bf16 *hh, *hl;
    bf16 *wqkvh, *wqkvl;
    __half *hf, *fff, *yf, *wof, *w1f, *w2f, *ef;
    cudaGetSymbolAddress((void**)&xp,    g_x);
    cudaGetSymbolAddress((void**)&logp,  g_logits);
    cudaGetSymbolAddress((void**)&partp, g_part);
    cudaGetSymbolAddress((void**)&hh,    g_hh);
    cudaGetSymbolAddress((void**)&hl,    g_hl);
    cudaGetSymbolAddress((void**)&hf,    g_hf);
    cudaGetSymbolAddress((void**)&fff,   g_fff);
    cudaGetSymbolAddress((void**)&yf,    g_yf);
    cudaGetSymbolAddress((void**)&wqkvh, g_wqkv_h);
    cudaGetSymbolAddress((void**)&wqkvl, g_wqkv_l);
    cudaGetSymbolAddress((void**)&wof,   g_wof);
    cudaGetSymbolAddress((void**)&w1f,   g_w1f);
    cudaGetSymbolAddress((void**)&w2f,   g_w2f);
    cudaGetSymbolAddress((void**)&ef,    g_ef);

    cudaFuncSetAttribute(gemm_mma<0,128,3>, cudaFuncAttributeMaxDynamicSharedMemorySize, GSM128);
    cudaFuncSetAttribute(fp16_mma<0,128,3,false>, cudaFuncAttributeMaxDynamicSharedMemorySize, F16SM128);
    cudaFuncSetAttribute(fp16_mma<0,256,2,true>, cudaFuncAttributeMaxDynamicSharedMemorySize, F16SM256);
    cudaFuncSetAttribute(fp16_mma<2,256,2,false>, cudaFuncAttributeMaxDynamicSharedMemorySize, F16SM256);
    cudaFuncSetAttribute(scores_mma, cudaFuncAttributeMaxDynamicSharedMemorySize, SCSM);
    cudaFuncSetAttribute(av_mma, cudaFuncAttributeMaxDynamicSharedMemorySize, AVSM);

    // side stream + events (host-side objects, created once)
    static cudaStream_t s2 = nullptr;
    static cudaEvent_t ev_fork = nullptr, ev_w0 = nullptr, ev_w1 = nullptr, ev_e = nullptr;
    if (!s2) {
        cudaStreamCreateWithFlags(&s2, cudaStreamNonBlocking);
        cudaEventCreateWithFlags(&ev_fork, cudaEventDisableTiming);
        cudaEventCreateWithFlags(&ev_w0, cudaEventDisableTiming);
        cudaEventCreateWithFlags(&ev_w1, cudaEventDisableTiming);
        cudaEventCreateWithFlags(&ev_e, cudaEventDisableTiming);
    }

    const size_t BTV = (size_t)TT * VV;
    float* logits_dst = ((size_t)out_size >= BTV) ? (float*)d_out : logp;
    float* loss_dst = nullptr;
    if ((size_t)out_size > BTV)      loss_dst = (float*)d_out + BTV;
    else if ((size_t)out_size < BTV) loss_dst = (float*)d_out;

    dim3 tb(32, 8);

    // ---- fork: non-immediate preprocessing on s2 ----
    cudaEventRecord(ev_fork, 0);
    cudaStreamWaitEvent(s2, ev_fork, 0);

    wtf16_k<<<dim3(EE/32, EE/32), tb, 0, s2>>>(Wo, wof, EE, EE, EE);
    wtf16_k<<<dim3(FF/32, EE/32), tb, 0, s2>>>(W1, w1f, EE, FF, EE);
    wtf16_k<<<dim3(EE/32, FF/32), tb, 0, s2>>>(W2, w2f, FF, EE, FF);
    cudaEventRecord(ev_w0, s2);
    {
        const int l = 1;
        wtsplit_k<<<dim3(EE/32, EE/32), tb, 0, s2>>>(Wq + (size_t)l*EE*EE,
            wqkvh + (size_t)l*QKVN*EE, wqkvl + (size_t)l*QKVN*EE, EE, EE, EE);
        wtsplit_k<<<dim3(KVD/32, EE/32), tb, 0, s2>>>(Wk + (size_t)l*EE*KVD,
            wqkvh + (size_t)l*QKVN*EE + (size_t)EE*EE, wqkvl + (size_t)l*QKVN*EE + (size_t)EE*EE, EE, KVD, EE);
        wtsplit_k<<<dim3(KVD/32, EE/32), tb, 0, s2>>>(Wv + (size_t)l*EE*KVD,
            wqkvh + (size_t)l*QKVN*EE + (size_t)(EE+KVD)*EE, wqkvl + (size_t)l*QKVN*EE + (size_t)(EE+KVD)*EE, EE, KVD, EE);
        wtf16_k<<<dim3(EE/32, EE/32), tb, 0, s2>>>(Wo + (size_t)l*EE*EE,
            wof + (size_t)l*EE*EE, EE, EE, EE);
        wtf16_k<<<dim3(FF/32, EE/32), tb, 0, s2>>>(W1 + (size_t)l*EE*FF,
            w1f + (size_t)l*FF*EE, EE, FF, EE);
        wtf16_k<<<dim3(EE/32, FF/32), tb, 0, s2>>>(W2 + (size_t)l*FF*EE,
            w2f + (size_t)l*EE*FF, FF, EE, FF);
    }
    cudaEventRecord(ev_w1, s2);
    ef16_k<<<(int)(((size_t)VV*EE)/1024), 256, 0, s2>>>(embed, ef);
    cudaEventRecord(ev_e, s2);

    // ---- main stream: critical path ----
    wtsplit_k<<<dim3(EE/32, EE/32), tb>>>(Wq, wqkvh, wqkvl, EE, EE, EE);
    wtsplit_k<<<dim3(KVD/32, EE/32), tb>>>(Wk, wqkvh + (size_t)EE*EE, wqkvl + (size_t)EE*EE, EE, KVD, EE);
    wtsplit_k<<<dim3(KVD/32, EE/32), tb>>>(Wv, wqkvh + (size_t)(EE+KVD)*EE, wqkvl + (size_t)(EE+KVD)*EE, EE, KVD, EE);
    gather_embed_k<<<(TT * EE) / 256, 256>>>(embed, idx);
    layernorm_split_k<<<TT, 256>>>(xp, hh, hl, ln1_g, ln1_b);

    for (int it = 0; it < RNUM * LNUM; it++) {
        int l = it % LNUM;
        if (it == 1) cudaStreamWaitEvent(0, ev_w1, 0);
        // QKV: 3-term bf16, split-K=3
        gemm_mma<0,128,3><<<dim3(TT/128, QKVN/128, 3), 256, GSM128>>>(hh, hl,
            wqkvh + (size_t)l*QKVN*EE, wqkvl + (size_t)l*QKVN*EE,
            partp, QKVN, EE);
        qkv_post_k<<<dim3(TT/64, NH + 2*NKV), 256>>>(partp);
        scores_mma<<<dim3(TT/128, TT/64, NH), 256, SCSM>>>();
        softmax_thresh_k<<<dim3(TT, NH), 256>>>(gate, l);
        av_mma<<<dim3(TT/64, NH), 256, AVSM>>>();
        if (it == 0) cudaStreamWaitEvent(0, ev_w0, 0);
        // Wo: fp16 1-term, split-K=2; fused x+= & LN2 (fp16 single out for FFN1)
        fp16_mma<0,128,3,false><<<dim3(TT/128, EE/128, 2), 256, F16SM128>>>(yf,
            wof + (size_t)l*EE*EE, partp, nullptr, EE, EE);
        add_ln_split_k<<<TT, 256>>>(xp, partp, ln2_g + l * EE, ln2_b + l * EE,
                                    nullptr, nullptr, hf);
        // FFN1: fp16 1-term, gelu -> fp16 single
        fp16_mma<2,256,2,false><<<dim3(TT/128, FF/256, 1), 256, F16SM256>>>(hf,
            w1f + (size_t)l*FF*EE, nullptr, fff, FF, EE);
        // FFN2: fp16 1-term, split-K=2 -> partials
        fp16_mma<0,128,3,false><<<dim3(TT/128, EE/128, 2), 256, F16SM128>>>(fff,
            w2f + (size_t)l*EE*FF, partp, nullptr, EE, FF);
        if (it == RNUM * LNUM - 1) {
            add_ln_split_k<<<TT, 256>>>(xp, partp, lnf_g, lnf_b, nullptr, nullptr, hf);
        } else {
            int ln = (l + 1) % LNUM;
            add_ln_split_k<<<TT, 256>>>(xp, partp, ln1_g + ln * EE, ln1_b + ln * EE,
                                        hh, hl, nullptr);
        }
    }

    // logits: fp16 1-term GEMM with fused per-row sum-of-exp
    zero_rows_k<<<TT/256, 256>>>();
    cudaStreamWaitEvent(0, ev_e, 0);
    fp16_mma<0,256,2,true><<<dim3(TT/128, VV/256, 1), 256, F16SM256>>>(hf, ef,
        logits_dst, nullptr, VV, EE);

    if (loss_dst) loss_fin2_k<<<1, 1024>>>(logits_dst, tgt, loss_dst);
}

// round 15
// speedup vs baseline: 2.3093x; 1.0352x over previous
#include <cuda_runtime.h>
#include <cuda_bf16.h>
#include <cuda_fp16.h>
#include <math.h>
#include <stdint.h>

// ---------------- problem constants ----------------
#define TT 1024
#define EE 1024
#define VV 32000
#define NH 16
#define NKV 4
#define DHD 64
#define KVD (NKV*DHD)     // 256
#define QKVN 1536
#define LNUM 2
#define RNUM 2
#define FF 4096
#define EPSV 1e-5f

typedef __nv_bfloat16 bf16;

// ---------------- device scratch ----------------
__device__ float g_x[TT*EE];
__device__ bf16  g_hh[TT*EE], g_hl[TT*EE];
__device__ __half g_hf[TT*EE];                         // fp16 LN output (LN2 / final)
__device__ __half g_fff[TT*FF];                        // fp16 gelu(FFN1) output
__device__ float g_att[(size_t)NH*TT*TT];
__device__ __half g_attf[(size_t)NH*TT*TT];            // fp16 att probs (single)
__device__ float g_part[3*TT*QKVN];          // split-K partials (reused)
__device__ bf16  g_qh[NH*TT*DHD],  g_ql[NH*TT*DHD];
__device__ bf16  g_kh[NKV*TT*DHD], g_kl[NKV*TT*DHD];
__device__ __half g_vtf[NKV*DHD*TT];                   // transposed V, fp16 single
__device__ __half g_yf[TT*EE];                         // fp16 attention output
__device__ bf16  g_wqkv_h[LNUM*QKVN*EE], g_wqkv_l[LNUM*QKVN*EE];
__device__ __half g_wof[LNUM*EE*EE];                   // fp16 Wo (single)
__device__ __half g_w1f[LNUM*FF*EE];                   // fp16 W1 (single)
__device__ __half g_w2f[LNUM*EE*FF];                   // fp16 W2 (single)
__device__ __half g_ef[(size_t)VV*EE];                 // fp16 embed (single)
__device__ float g_logits[(size_t)TT*VV];
__device__ float g_rowsum[TT];                         // fused loss: sum exp(logit)

// ---------------- generic helpers ----------------
__device__ __forceinline__ float blk_sum256(float v, float* sh) {
    int tid = threadIdx.x;
    sh[tid] = v; __syncthreads();
    #pragma unroll
    for (int s = 128; s > 0; s >>= 1) { if (tid < s) sh[tid] += sh[tid + s]; __syncthreads(); }
    float r = sh[0]; __syncthreads();
    return r;
}
__device__ __forceinline__ float blk_max256(float v, float* sh) {
    int tid = threadIdx.x;
    sh[tid] = v; __syncthreads();
    #pragma unroll
    for (int s = 128; s > 0; s >>= 1) { if (tid < s) sh[tid] = fmaxf(sh[tid], sh[tid + s]); __syncthreads(); }
    float r = sh[0]; __syncthreads();
    return r;
}
__device__ __forceinline__ float gelu_exact(float x) {
    return 0.5f * x * (1.0f + erff(x * 0.7071067811865476f));
}
__device__ __forceinline__ void split_bf16(float v, bf16& h, bf16& l) {
    h = __float2bfloat16(v);
    l = __float2bfloat16(v - __bfloat162float(h));
}
// MUFU-free exp: rint range reduction + degree-5 Taylor, rel err ~3e-6
__device__ __forceinline__ float fast_exp(float v) {
    float t = v * 1.44269504f;
    t = fmaxf(t, -120.0f);
    float r = rintf(t);
    float f = (t - r) * 0.69314718f;
    float p = 1.0f + f * (1.0f + f * (0.5f + f * (0.166666667f
             + f * (0.0416666667f + f * 0.00833333333f))));
    return __int_as_float(((int)(127.0f + r)) << 23) * p;
}

// ---------------- PTX wrappers ----------------
__device__ __forceinline__ void mma_bf16(float* d, const uint32_t* a, const uint32_t* b) {
    asm volatile("mma.sync.aligned.m16n8k16.row.col.f32.bf16.bf16.f32 "
        "{%0,%1,%2,%3}, {%4,%5,%6,%7}, {%8,%9}, {%0,%1,%2,%3};"
        : "+f"(d[0]), "+f"(d[1]), "+f"(d[2]), "+f"(d[3])
        : "r"(a[0]), "r"(a[1]), "r"(a[2]), "r"(a[3]), "r"(b[0]), "r"(b[1]));
}
__device__ __forceinline__ void mma_fp16(float* d, const uint32_t* a, const uint32_t* b) {
    asm volatile("mma.sync.aligned.m16n8k16.row.col.f32.f16.f16.f32 "
        "{%0,%1,%2,%3}, {%4,%5,%6,%7}, {%8,%9}, {%0,%1,%2,%3};"
        : "+f"(d[0]), "+f"(d[1]), "+f"(d[2]), "+f"(d[3])
        : "r"(a[0]), "r"(a[1]), "r"(a[2]), "r"(a[3]), "r"(b[0]), "r"(b[1]));
}
__device__ __forceinline__ void ldsm4(uint32_t* r, uint32_t addr) {
    asm volatile("ldmatrix.sync.aligned.m8n8.x4.shared.b16 {%0,%1,%2,%3}, [%4];"
        : "=r"(r[0]), "=r"(r[1]), "=r"(r[2]), "=r"(r[3]) : "r"(addr));
}
__device__ __forceinline__ void cp16(uint32_t s, const void* g) {
    asm volatile("cp.async.cg.shared.global [%0], [%1], 16;" :: "r"(s), "l"(g));
}
#define CP_COMMIT()  asm volatile("cp.async.commit_group;")
#define CP_WAIT(n)   asm volatile("cp.async.wait_group %0;" :: "n"(n))

// SW128 swizzle: 128B rows, 16B chunks, chunk ^= row&7  (conflict-free ldmatrix)
__device__ __forceinline__ uint32_t sw_off(int row, int chunk) {
    return (uint32_t)(row * 128 + ((chunk ^ (row & 7)) << 4));
}

// ---------------- split-bf16 3-term HMMA GEMM (QKV only) ----------------
template<int MODE, int TN, int NSTG>
__global__ __launch_bounds__(256, 1) void gemm_mma(
    const bf16* __restrict__ Ah, const bf16* __restrict__ Al,
    const bf16* __restrict__ Bh, const bf16* __restrict__ Bl,
    float* C, int N, int K)
{
    constexpr int TSA = 128 * 128;
    constexpr int TSB = TN * 128;
    constexpr int SB  = 2 * TSA + 2 * TSB;
    constexpr int BCH = TN * 8;
    constexpr int TC  = 2048 + 2 * BCH;
    constexpr int NG  = TN / 64;
    constexpr int NF  = 2 * NG;

    extern __shared__ char dsm[];
    const int tid = threadIdx.x;
    const int lane = tid & 31, warp = tid >> 5;
    const int wm = warp & 1, wn = warp >> 1;
    const int row0 = blockIdx.x * 128, col0 = blockIdx.y * TN;
    const uint32_t sb = (uint32_t)__cvta_generic_to_shared(dsm);

    float acc[4][NF][4];
    #pragma unroll
    for (int i = 0; i < 4; i++)
        #pragma unroll
        for (int j = 0; j < NF; j++)
            #pragma unroll
            for (int r = 0; r < 4; r++) acc[i][j][r] = 0.f;

    auto load_stage = [&](int s) {
        int k0 = s * 64;
        uint32_t base = sb + (s % NSTG) * SB;
        #pragma unroll
        for (int ii = 0; ii < TC / 256; ii++) {
            int i = tid + ii * 256;
            const bf16* src;
            uint32_t toff;
            if (i < 2048) {
                int t = i >> 10, w = i & 1023;
                int r = w >> 3, c = w & 7;
                src = (t ? Al : Ah) + (size_t)(row0 + r) * K + k0 + c * 8;
                toff = t * TSA + sw_off(r, c);
            } else {
                int j = i - 2048;
                int t = j / BCH, w = j & (BCH - 1);
                int r = w >> 3, c = w & 7;
                src = (t ? Bl : Bh) + (size_t)(col0 + r) * K + k0 + c * 8;
                toff = 2 * TSA + t * TSB + sw_off(r, c);
            }
            cp16(base + toff, src);
        }
        CP_COMMIT();
    };

    const int Stot = K >> 6;
    const int SK = gridDim.z;
    const int Sc = (Stot + SK - 1) / SK;
    const int s0 = blockIdx.z * Sc;
    const int s1 = min(Stot, s0 + Sc);

    #pragma unroll
    for (int i = 0; i < NSTG; i++)
        if (s0 + i < s1) load_stage(s0 + i);

    const int lr = lane & 15, lcs = lane >> 4;

    for (int s = s0; s < s1; s++) {
        int ahead = s1 - 1 - s;
        int w = ahead < (NSTG - 1) ? ahead : (NSTG - 1);
        if (w == 2)      { CP_WAIT(2); }
        else if (w == 1) { CP_WAIT(1); }
        else             { CP_WAIT(0); }
        __syncthreads();
        uint32_t ab = sb + (s % NSTG) * SB;
        #pragma unroll
        for (int k16 = 0; k16 < 4; k16++) {
            const int cch = k16 * 2 + lcs;
            uint32_t ah[4][4], al[4][4];
            #pragma unroll
            for (int mf = 0; mf < 4; mf++) {
                int row = wm * 64 + mf * 16 + lr;
                uint32_t off = sw_off(row, cch);
                ldsm4(ah[mf], ab + off);
                ldsm4(al[mf], ab + TSA + off);
            }
            #pragma unroll
            for (int g = 0; g < NG; g++) {
                int row = wn * (TN / 4) + g * 16 + lr;
                uint32_t off = sw_off(row, cch);
                uint32_t rh[4], rl[4];
                ldsm4(rh, ab + 2 * TSA + off);
                ldsm4(rl, ab + 2 * TSA + TSB + off);
                uint32_t b0h[2] = {rh[0], rh[2]}, b1h[2] = {rh[1], rh[3]};
                uint32_t b0l[2] = {rl[0], rl[2]}, b1l[2] = {rl[1], rl[3]};
                #pragma unroll
                for (int mf = 0; mf < 4; mf++) {
                    mma_bf16(acc[mf][g*2], ah[mf], b0h);
                    mma_bf16(acc[mf][g*2], ah[mf], b0l);
                    mma_bf16(acc[mf][g*2], al[mf], b0h);
                    mma_bf16(acc[mf][g*2+1], ah[mf], b1h);
                    mma_bf16(acc[mf][g*2+1], ah[mf], b1l);
                    mma_bf16(acc[mf][g*2+1], al[mf], b1h);
                }
            }
        }
        __syncthreads();
        if (s + NSTG < s1) load_stage(s + NSTG);
    }

    const size_t pstride = (size_t)gridDim.x * 128 * N;
    float* Cp = C + (size_t)blockIdx.z * pstride;
    #pragma unroll
    for (int mf = 0; mf < 4; mf++)
        #pragma unroll
        for (int nf = 0; nf < NF; nf++) {
            int r = row0 + wm * 64 + mf * 16 + (lane >> 2);
            int c = col0 + wn * (TN / 4) + nf * 8 + (lane & 3) * 2;
            float* d = acc[mf][nf];
            *(float2*)(Cp + (size_t)r * N + c)       = make_float2(d[0], d[1]);
            *(float2*)(Cp + (size_t)(r + 8) * N + c) = make_float2(d[2], d[3]);
        }
}

#define GSM128 (3 * (2*128*128 + 2*128*128))   // 196608

// ---------------- 1-term fp16 GEMM (Wo / FFN / logits): C = A * B^T ----------------
template<int MODE, int TN, int NSTG, bool LOSS>
__global__ __launch_bounds__(256, 1) void fp16_mma(
    const __half* __restrict__ A, const __half* __restrict__ B,
    float* __restrict__ C, __half* __restrict__ Of, int N, int K)
{
    constexpr int TSA = 128 * 128;
    constexpr int TSB = TN * 128;
    constexpr int SB  = TSA + TSB;
    constexpr int BCH = TN * 8;
    constexpr int TC  = 1024 + BCH;
    constexpr int NG  = TN / 64;
    constexpr int NF  = 2 * NG;

    extern __shared__ char dsm[];
    const int tid = threadIdx.x;
    const int lane = tid & 31, warp = tid >> 5;
    const int wm = warp & 1, wn = warp >> 1;
    const int row0 = blockIdx.x * 128, col0 = blockIdx.y * TN;
    const uint32_t sb = (uint32_t)__cvta_generic_to_shared(dsm);

    float acc[4][NF][4];
    #pragma unroll
    for (int i = 0; i < 4; i++)
        #pragma unroll
        for (int j = 0; j < NF; j++)
            #pragma unroll
            for (int r = 0; r < 4; r++) acc[i][j][r] = 0.f;

    auto load_stage = [&](int s) {
        int k0 = s * 64;
        uint32_t base = sb + (s % NSTG) * SB;
        #pragma unroll
        for (int ii = 0; ii < TC / 256; ii++) {
            int i = tid + ii * 256;
            const __half* src; uint32_t toff;
            if (i < 1024) {
                int r = i >> 3, c = i & 7;
                src = A + (size_t)(row0 + r) * K + k0 + c * 8;
                toff = sw_off(r, c);
            } else {
                int j = i - 1024;
                int r = j >> 3, c = j & 7;
                src = B + (size_t)(col0 + r) * K + k0 + c * 8;
                toff = TSA + sw_off(r, c);
            }
            cp16(base + toff, src);
        }
        CP_COMMIT();
    };

    const int Stot = K >> 6;
    const int SK = gridDim.z;
    const int Sc = (Stot + SK - 1) / SK;
    const int s0 = blockIdx.z * Sc;
    const int s1 = min(Stot, s0 + Sc);

    #pragma unroll
    for (int i = 0; i < NSTG; i++)
        if (s0 + i < s1) load_stage(s0 + i);

    const int lr = lane & 15, lcs = lane >> 4;

    for (int s = s0; s < s1; s++) {
        int ahead = s1 - 1 - s;
        int w = ahead < (NSTG - 1) ? ahead : (NSTG - 1);
        if (w == 2)      { CP_WAIT(2); }
        else if (w == 1) { CP_WAIT(1); }
        else             { CP_WAIT(0); }
        __syncthreads();
        uint32_t ab = sb + (s % NSTG) * SB;
        #pragma unroll
        for (int k16 = 0; k16 < 4; k16++) {
            const int cch = k16 * 2 + lcs;
            uint32_t ah[4][4];
            #pragma unroll
            for (int mf = 0; mf < 4; mf++)
                ldsm4(ah[mf], ab + sw_off(wm * 64 + mf * 16 + lr, cch));
            #pragma unroll
            for (int g = 0; g < NG; g++) {
                uint32_t off = sw_off(wn * (TN / 4) + g * 16 + lr, cch);
                uint32_t rh[4];
                ldsm4(rh, ab + TSA + off);
                uint32_t b0[2] = {rh[0], rh[2]}, b1[2] = {rh[1], rh[3]};
                #pragma unroll
                for (int mf = 0; mf < 4; mf++) {
                    mma_fp16(acc[mf][g*2],   ah[mf], b0);
                    mma_fp16(acc[mf][g*2+1], ah[mf], b1);
                }
            }
        }
        __syncthreads();
        if (s + NSTG < s1) load_stage(s + NSTG);
    }

    const size_t pstride = (size_t)gridDim.x * 128 * N;
    float* Cp = C + (size_t)blockIdx.z * pstride;
    float lsum[4][2];
    if (LOSS) {
        #pragma unroll
        for (int mf = 0; mf < 4; mf++) { lsum[mf][0] = 0.f; lsum[mf][1] = 0.f; }
    }
    #pragma unroll
    for (int mf = 0; mf < 4; mf++)
        #pragma unroll
        for (int nf = 0; nf < NF; nf++) {
            int r = row0 + wm * 64 + mf * 16 + (lane >> 2);
            int c = col0 + wn * (TN / 4) + nf * 8 + (lane & 3) * 2;
            float* d = acc[mf][nf];
            if (MODE == 0) {
                *(float2*)(Cp + (size_t)r * N + c)       = make_float2(d[0], d[1]);
                *(float2*)(Cp + (size_t)(r + 8) * N + c) = make_float2(d[2], d[3]);
                if (LOSS) {
                    lsum[mf][0] += fast_exp(d[0]) + fast_exp(d[1]);
                    lsum[mf][1] += fast_exp(d[2]) + fast_exp(d[3]);
                }
            } else {
                __half o0 = __float2half_rn(gelu_exact(d[0]));
                __half o1 = __float2half_rn(gelu_exact(d[1]));
                __half o2 = __float2half_rn(gelu_exact(d[2]));
                __half o3 = __float2half_rn(gelu_exact(d[3]));
                *(__half2*)(Of + (size_t)r * N + c)       = __halves2half2(o0, o1);
                *(__half2*)(Of + (size_t)(r + 8) * N + c) = __halves2half2(o2, o3);
            }
        }
    if (LOSS) {
        float* rs = (float*)dsm;
        if (tid < 128) rs[tid] = 0.f;
        __syncthreads();
        #pragma unroll
        for (int mf = 0; mf < 4; mf++) {
            int rl0 = wm * 64 + mf * 16 + (lane >> 2);
            atomicAdd(&rs[rl0], lsum[mf][0]);
            atomicAdd(&rs[rl0 + 8], lsum[mf][1]);
        }
        __syncthreads();
        if (tid < 128) atomicAdd(&g_rowsum[row0 + tid], rs[tid]);
    }
}

#define F16SM128 (3 * (128*128 + 128*128))     // 98304
#define F16SM256 (2 * (128*128 + 256*128))     // 98304

// ---------------- fused QKV reduce + RoPE/transpose + split (2 slabs) ----------------
__global__ void qkv_post_k(const float* __restrict__ part) {
    __shared__ float tile[64][65];
    int ttile = blockIdx.x, head = blockIdx.y;
    int tid = threadIdx.x;
    int cb;
    if (head < NH)            cb = head * DHD;
    else if (head < NH + NKV) cb = EE + (head - NH) * DHD;
    else                      cb = EE + KVD + (head - NH - NKV) * DHD;
    const int n = TT * QKVN;
    #pragma unroll
    for (int it = 0; it < 16; it++) {
        int i = tid + it * 256;
        int r = i >> 6, c = i & 63;
        size_t idx = (size_t)(ttile * 64 + r) * QKVN + cb + c;
        tile[r][c] = part[idx] + part[idx + n];
    }
    __syncthreads();
    if (head < NH + NKV) {
        bf16 *dh, *dl; size_t off;
        if (head < NH) { dh = g_qh; dl = g_ql; off = (size_t)head * TT * DHD; }
        else           { dh = g_kh; dl = g_kl; off = (size_t)(head - NH) * TT * DHD; }
        #pragma unroll
        for (int it = 0; it < 16; it++) {
            int i = tid + it * 256;
            int r = i >> 6, d = i & 63;
            int t = ttile * 64 + r;
            float v;
            if (d < 32) {
                int j = d & 15;
                float theta = powf(10000.0f, -(float)j / 16.0f);
                float ang = (float)t * theta;
                float cs = cosf(ang), sn = sinf(ang);
                if (d < 16) v = tile[r][d] * cs - tile[r][d + 16] * sn;
                else        v = tile[r][d] * cs + tile[r][d - 16] * sn;
            } else v = tile[r][d];
            bf16 h, l; split_bf16(v, h, l);
            size_t o = off + (size_t)t * DHD + d;
            dh[o] = h; dl[o] = l;
        }
    } else {
        int kh = head - NH - NKV;
        #pragma unroll
        for (int it = 0; it < 16; it++) {
            int i = tid + it * 256;
            int d = i >> 6, tc = i & 63;
            size_t o = ((size_t)kh * DHD + d) * TT + ttile * 64 + tc;
            g_vtf[o] = __float2half_rn(tile[tc][d]);
        }
    }
}

// ---------------- HMMA attention scores: 64(t) x 128(s), K=64 (3-term bf16) ----------------
#define SCSM 49152
__global__ __launch_bounds__(256) void scores_mma() {
    int st = blockIdx.x, tt = blockIdx.y, h = blockIdx.z;
    if (2 * st > tt) return;
    int khid = h >> 2;
    extern __shared__ char dsm[];
    const uint32_t sb = (uint32_t)__cvta_generic_to_shared(dsm);
    const int tid = threadIdx.x;
    const int lane = tid & 31, warp = tid >> 5;

    #pragma unroll
    for (int it = 0; it < 12; it++) {
        int i = tid + it * 256;
        const bf16* src; uint32_t dst;
        if (i < 1024) {
            int sub = i >> 9, w = i & 511, r = w >> 3, c = w & 7;
            src = (sub ? g_ql : g_qh) + ((size_t)h * TT + tt * 64 + r) * DHD + c * 8;
            dst = sub * 8192 + sw_off(r, c);
        } else {
            int j = i - 1024;
            int sub = j >> 10, w = j & 1023, r = w >> 3, c = w & 7;
            src = (sub ? g_kl : g_kh) + ((size_t)khid * TT + st * 128 + r) * DHD + c * 8;
            dst = 16384 + sub * 16384 + sw_off(r, c);
        }
        cp16(sb + dst, src);
    }
    CP_COMMIT(); CP_WAIT(0);
    __syncthreads();

    const int wm = warp & 1, wn = warp >> 1;
    const int lr = lane & 15, lcs = lane >> 4;
    float acc[2][4][4];
    #pragma unroll
    for (int a = 0; a < 2; a++)
        #pragma unroll
        for (int b = 0; b < 4; b++)
            #pragma unroll
            for (int c = 0; c < 4; c++) acc[a][b][c] = 0.f;

    #pragma unroll
    for (int k16 = 0; k16 < 4; k16++) {
        const int cch = k16 * 2 + lcs;
        uint32_t ah[2][4], al[2][4];
        #pragma unroll
        for (int mf = 0; mf < 2; mf++) {
            int row = wm * 32 + mf * 16 + lr;
            uint32_t off = sw_off(row, cch);
            ldsm4(ah[mf], sb + off);
            ldsm4(al[mf], sb + 8192 + off);
        }
        #pragma unroll
        for (int g = 0; g < 2; g++) {
            int row = wn * 32 + g * 16 + lr;
            uint32_t off = sw_off(row, cch);
            uint32_t rh[4], rl[4];
            ldsm4(rh, sb + 16384 + off);
            ldsm4(rl, sb + 32768 + off);
            uint32_t b0h[2] = {rh[0], rh[2]}, b1h[2] = {rh[1], rh[3]};
            uint32_t b0l[2] = {rl[0], rl[2]}, b1l[2] = {rl[1], rl[3]};
            #pragma unroll
            for (int mf = 0; mf < 2; mf++) {
                mma_bf16(acc[mf][g*2], ah[mf], b0h);
                mma_bf16(acc[mf][g*2], ah[mf], b0l);
                mma_bf16(acc[mf][g*2], al[mf], b0h);
                mma_bf16(acc[mf][g*2+1], ah[mf], b1h);
                mma_bf16(acc[mf][g*2+1], ah[mf], b1l);
                mma_bf16(acc[mf][g*2+1], al[mf], b1h);
            }
        }
    }
    float* o = g_att + (size_t)h * TT * TT;
    #pragma unroll
    for (int mf = 0; mf < 2; mf++)
        #pragma unroll
        for (int nf = 0; nf < 4; nf++) {
            int r = tt * 64 + wm * 32 + mf * 16 + (lane >> 2);
            int c = st * 128 + wn * 32 + nf * 8 + (lane & 3) * 2;
            float* d = acc[mf][nf];
            *(float2*)(o + (size_t)r * TT + c)       = make_float2(d[0]*0.125f, d[1]*0.125f);
            *(float2*)(o + (size_t)(r + 8) * TT + c) = make_float2(d[2]*0.125f, d[3]*0.125f);
        }
}

// ---------------- single-pass softmax + gate, writes fp16 att ----------------
__global__ void softmax_thresh_k(const float* __restrict__ gate_all, int l) {
    __shared__ float sh[256];
    int t = blockIdx.x, h = blockIdx.y;
    int tid = threadIdx.x;
    const float* p = g_att + (size_t)h * TT * TT + (size_t)t * TT;
    float thr = 1.0f / (1.0f + expf(-gate_all[l * NH + h]));
    float x[4];
    #pragma unroll
    for (int k = 0; k < 4; k++) {
        int i = k * 256 + tid;
        x[k] = (i <= t) ? p[i] : -1e30f;
    }
    float m = fmaxf(fmaxf(x[0], x[1]), fmaxf(x[2], x[3]));
    m = blk_max256(m, sh);
    float e[4], s = 0.f;
    #pragma unroll
    for (int k = 0; k < 4; k++) {
        int i = k * 256 + tid;
        e[k] = (i <= t) ? fast_exp(x[k] - m) : 0.f;
        s += e[k];
    }
    s = blk_sum256(s, sh);
    float inv = 1.0f / s;
    int kend = ((t >> 6) + 1) << 6;
    size_t base = (size_t)h * TT * TT + (size_t)t * TT;
    #pragma unroll
    for (int k = 0; k < 4; k++) {
        int i = k * 256 + tid;
        if (i < kend) {
            float pv = e[k] * inv;
            pv = (pv >= thr) ? pv : 0.f;
            g_attf[base + i] = __float2half_rn(pv);
        }
    }
}

// ---------------- fp16 1-term AV: 64(t) x 64(d), K-loop over s ----------------
#define AVSM 32768
__global__ __launch_bounds__(256) void av_mma() {
    int tt = gridDim.x - 1 - blockIdx.x;    // largest-K blocks launch first
    int h = blockIdx.y;
    int khid = h >> 2;
    int St = tt + 1;
    extern __shared__ char dsm[];
    const uint32_t sb = (uint32_t)__cvta_generic_to_shared(dsm);
    const int tid = threadIdx.x;
    const int lane = tid & 31, warp = tid >> 5;
    const int wm = warp & 1, wn = warp >> 1;
    const int lr = lane & 15, lcs = lane >> 4;

    auto load = [&](int s) {
        uint32_t base = sb + (s & 1) * 16384;
        #pragma unroll
        for (int it = 0; it < 4; it++) {
            int i = tid + it * 256;
            const __half* src; uint32_t dst;
            if (i < 512) {
                int r = i >> 3, c = i & 7;
                src = g_attf + ((size_t)h * TT + tt * 64 + r) * TT + s * 64 + c * 8;
                dst = base + sw_off(r, c);
            } else {
                int j = i - 512;
                int r = j >> 3, c = j & 7;
                src = g_vtf + ((size_t)khid * DHD + r) * TT + s * 64 + c * 8;
                dst = base + 8192 + sw_off(r, c);
            }
            cp16(dst, src);
        }
        CP_COMMIT();
    };

    load(0);
    if (St > 1) load(1);

    float acc[2][2][4];
    #pragma unroll
    for (int a = 0; a < 2; a++)
        #pragma unroll
        for (int b = 0; b < 2; b++)
            #pragma unroll
            for (int c = 0; c < 4; c++) acc[a][b][c] = 0.f;

    for (int s = 0; s < St; s++) {
        if (s + 1 < St) { CP_WAIT(1); } else { CP_WAIT(0); }
        __syncthreads();
        uint32_t base = sb + (s & 1) * 16384;
        #pragma unroll
        for (int k16 = 0; k16 < 4; k16++) {
            const int cch = k16 * 2 + lcs;
            uint32_t ah[2][4];
            #pragma unroll
            for (int mf = 0; mf < 2; mf++)
                ldsm4(ah[mf], base + sw_off(wm * 32 + mf * 16 + lr, cch));
            uint32_t rh[4];
            ldsm4(rh, base + 8192 + sw_off(wn * 16 + lr, cch));
            uint32_t b0[2] = {rh[0], rh[2]}, b1[2] = {rh[1], rh[3]};
            #pragma unroll
            for (int mf = 0; mf < 2; mf++) {
                mma_fp16(acc[mf][0], ah[mf], b0);
                mma_fp16(acc[mf][1], ah[mf], b1);
            }
        }
        __syncthreads();
        if (s + 2 < St) load(s + 2);
    }

    #pragma unroll
    for (int mf = 0; mf < 2; mf++)
        #pragma unroll
        for (int nf = 0; nf < 2; nf++) {
            int r = tt * 64 + wm * 32 + mf * 16 + (lane >> 2);
            int c = h * DHD + wn * 16 + nf * 8 + (lane & 3) * 2;
            float* d = acc[mf][nf];
            *(__half2*)(g_yf + (size_t)r * EE + c) =
                __halves2half2(__float2half_rn(d[0]), __float2half_rn(d[1]));
            *(__half2*)(g_yf + (size_t)(r + 8) * EE + c) =
                __halves2half2(__float2half_rn(d[2]), __float2half_rn(d[3]));
        }
}

// ---------------- fused residual-add + layernorm + split (bf16 pair or fp16) ----------------
__global__ void add_ln_split_k(float* __restrict__ x, const float* __restrict__ p,
                               const float* __restrict__ g, const float* __restrict__ b,
                               bf16* __restrict__ oh, bf16* __restrict__ ol,
                               __half* __restrict__ of) {
    __shared__ float sh[256];
    int row = blockIdx.x, tid = threadIdx.x;
    const int n = TT * EE;
    float v[4];
    #pragma unroll
    for (int k = 0; k < 4; k++) {
        int i = row * EE + k * 256 + tid;
        v[k] = x[i] + p[i] + p[i + n];
        x[i] = v[k];
    }
    float mu = blk_sum256(v[0] + v[1] + v[2] + v[3], sh) * (1.0f / EE);
    float vs = 0.f;
    #pragma unroll
    for (int k = 0; k < 4; k++) { float d = v[k] - mu; vs += d * d; }
    float var = blk_sum256(vs, sh) * (1.0f / EE);
    float inv = rsqrtf(var + EPSV);
    #pragma unroll
    for (int k = 0; k < 4; k++) {
        int c = k * 256 + tid;
        float o = (v[k] - mu) * inv * g[c] + b[c];
        if (of) {
            of[row * EE + c] = __float2half_rn(o);
        } else {
            bf16 h, l; split_bf16(o, h, l);
            oh[row * EE + c] = h;
            ol[row * EE + c] = l;
        }
    }
}

// ---------------- plain layernorm + split (first LN only) ----------------
__global__ void layernorm_split_k(const float* __restrict__ in, bf16* __restrict__ oh,
                                  bf16* __restrict__ ol,
                                  const float* __restrict__ g, const float* __restrict__ b) {
    __shared__ float sh[256];
    int row = blockIdx.x;
    const float* x = in + (size_t)row * EE;
    float s = 0.f;
    for (int i = threadIdx.x; i < EE; i += 256) s += x[i];
    float mu = blk_sum256(s, sh) * (1.0f / EE);
    float vs = 0.f;
    for (int i = threadIdx.x; i < EE; i += 256) { float d = x[i] - mu; vs += d * d; }
    float var = blk_sum256(vs, sh) * (1.0f / EE);
    float inv = rsqrtf(var + EPSV);
    for (int i = threadIdx.x; i < EE; i += 256) {
        float v = (x[i] - mu) * inv * g[i] + b[i];
        bf16 h, l; split_bf16(v, h, l);
        oh[(size_t)row * EE + i] = h;
        ol[(size_t)row * EE + i] = l;
    }
}

// ---------------- weight transpose + split (bf16 hi/lo, QKV only) ----------------
__global__ void wtsplit_k(const float* __restrict__ W, bf16* __restrict__ Th,
                          bf16* __restrict__ Tl, int K, int N, int ldt) {
    __shared__ float t[32][33];
    int n0 = blockIdx.x * 32, k0 = blockIdx.y * 32;
    int tx = threadIdx.x, ty = threadIdx.y;
    #pragma unroll
    for (int r = ty; r < 32; r += 8)
        t[r][tx] = W[(size_t)(k0 + r) * N + n0 + tx];
    __syncthreads();
    #pragma unroll
    for (int r = ty; r < 32; r += 8) {
        float v = t[tx][r];
        bf16 h, l; split_bf16(v, h, l);
        Th[(size_t)(n0 + r) * ldt + k0 + tx] = h;
        Tl[(size_t)(n0 + r) * ldt + k0 + tx] = l;
    }
}

// ---------------- weight transpose (fp16 single) ----------------
__global__ void wtf16_k(const float* __restrict__ W, __half* __restrict__ T,
                        int K, int N, int ldt) {
    __shared__ float t[32][33];
    int n0 = blockIdx.x * 32, k0 = blockIdx.y * 32;
    int tx = threadIdx.x, ty = threadIdx.y;
    #pragma unroll
    for (int r = ty; r < 32; r += 8)
        t[r][tx] = W[(size_t)(k0 + r) * N + n0 + tx];
    __syncthreads();
    #pragma unroll
    for (int r = ty; r < 32; r += 8)
        T[(size_t)(n0 + r) * ldt + k0 + tx] = __float2half_rn(t[tx][r]);
}

// ---------------- embed convert (fp16 single) ----------------
__global__ void ef16_k(const float* __restrict__ E, __half* __restrict__ T) {
    size_t i = ((size_t)blockIdx.x * 256 + threadIdx.x) * 4;
    float4 v = *(const float4*)(E + i);
    *(__half2*)(T + i)     = __halves2half2(__float2half_rn(v.x), __float2half_rn(v.y));
    *(__half2*)(T + i + 2) = __halves2half2(__float2half_rn(v.z), __float2half_rn(v.w));
}

// ---------------- embedding gather ----------------
__global__ void gather_embed_k(const float* __restrict__ embed, const int* __restrict__ idx) {
    int i = blockIdx.x * blockDim.x + threadIdx.x;
    int t = i >> 10, e = i & 1023;
    g_x[i] = embed[(size_t)idx[t] * EE + e];
}

// ---------------- fused loss helpers ----------------
__global__ void zero_rows_k() {
    int i = blockIdx.x * 256 + threadIdx.x;
    g_rowsum[i] = 0.f;
}

__global__ void loss_fin2_k(const float* __restrict__ logits,
                            const int* __restrict__ tgt, float* __restrict__ dst) {
    __shared__ float sh[1024];
    int t = threadIdx.x;
    float lp = logits[(size_t)t * VV + tgt[t]] - logf(g_rowsum[t]);
    sh[t] = lp; __syncthreads();
    #pragma unroll
    for (int s = 512; s > 0; s >>= 1) {
        if (t < s) sh[t] += sh[t + s];
        __syncthreads();
    }
    if (t == 0) *dst = -sh[0] * (1.0f / (float)TT);
}

// ---------------- host orchestration ----------------
extern "C" void kernel_launch(void* const* d_in, const int* in_sizes, int n_in,
                              void* d_out, int out_size) {
    const float* embed = (const float*)d_in[0];
    const float* ln1_g = (const float*)d_in[1];
    const float* ln1_b = (const float*)d_in[2];
    const float* Wq    = (const float*)d_in[3];
    const float* Wk    = (const float*)d_in[4];
    const float* Wv    = (const float*)d_in[5];
    const float* Wo    = (const float*)d_in[6];
    const float* gate  = (const float*)d_in[7];
    const float* ln2_g = (const float*)d_in[8];
    const float* ln2_b = (const float*)d_in[9];
    const float* W1    = (const float*)d_in[10];
    const float* W2    = (const float*)d_in[11];
    const float* lnf_g = (const float*)d_in[12];
    const float* lnf_b = (const float*)d_in[13];
    const int*   idx   = (const int*)d_in[14];
    const int*   tgt   = (const int*)d_in[15];

    float *xp, *logp, *partp;
    bf16 *hh, *hl;
    bf16 *wqkvh, *wqkvl;
    __half *hf, *fff, *yf, *wof, *w1f, *w2f, *ef;
    cudaGetSymbolAddress((void**)&xp,    g_x);
    cudaGetSymbolAddress((void**)&logp,  g_logits);
    cudaGetSymbolAddress((void**)&partp, g_part);
    cudaGetSymbolAddress((void**)&hh,    g_hh);
    cudaGetSymbolAddress((void**)&hl,    g_hl);
    cudaGetSymbolAddress((void**)&hf,    g_hf);
    cudaGetSymbolAddress((void**)&fff,   g_fff);
    cudaGetSymbolAddress((void**)&yf,    g_yf);
    cudaGetSymbolAddress((void**)&wqkvh, g_wqkv_h);
    cudaGetSymbolAddress((void**)&wqkvl, g_wqkv_l);
    cudaGetSymbolAddress((void**)&wof,   g_wof);
    cudaGetSymbolAddress((void**)&w1f,   g_w1f);
    cudaGetSymbolAddress((void**)&w2f,   g_w2f);
    cudaGetSymbolAddress((void**)&ef,    g_ef);

    cudaFuncSetAttribute(gemm_mma<0,128,3>, cudaFuncAttributeMaxDynamicSharedMemorySize, GSM128);
    cudaFuncSetAttribute(fp16_mma<0,128,3,false>, cudaFuncAttributeMaxDynamicSharedMemorySize, F16SM128);
    cudaFuncSetAttribute(fp16_mma<2,128,3,false>, cudaFuncAttributeMaxDynamicSharedMemorySize, F16SM128);
    cudaFuncSetAttribute(fp16_mma<0,256,2,true>, cudaFuncAttributeMaxDynamicSharedMemorySize, F16SM256);
    cudaFuncSetAttribute(scores_mma, cudaFuncAttributeMaxDynamicSharedMemorySize, SCSM);
    cudaFuncSetAttribute(av_mma, cudaFuncAttributeMaxDynamicSharedMemorySize, AVSM);

    // side stream + events (host-side objects, created once)
    static cudaStream_t s2 = nullptr;
    static cudaEvent_t ev_fork = nullptr, ev_w0 = nullptr, ev_w1 = nullptr, ev_e = nullptr;
    if (!s2) {
        cudaStreamCreateWithFlags(&s2, cudaStreamNonBlocking);
        cudaEventCreateWithFlags(&ev_fork, cudaEventDisableTiming);
        cudaEventCreateWithFlags(&ev_w0, cudaEventDisableTiming);
        cudaEventCreateWithFlags(&ev_w1, cudaEventDisableTiming);
        cudaEventCreateWithFlags(&ev_e, cudaEventDisableTiming);
    }

    const size_t BTV = (size_t)TT * VV;
    float* logits_dst = ((size_t)out_size >= BTV) ? (float*)d_out : logp;
    float* loss_dst = nullptr;
    if ((size_t)out_size > BTV)      loss_dst = (float*)d_out + BTV;
    else if ((size_t)out_size < BTV) loss_dst = (float*)d_out;

    dim3 tb(32, 8);

    // ---- fork: non-immediate preprocessing on s2 ----
    cudaEventRecord(ev_fork, 0);
    cudaStreamWaitEvent(s2, ev_fork, 0);

    wtf16_k<<<dim3(EE/32, EE/32), tb, 0, s2>>>(Wo, wof, EE, EE, EE);
    wtf16_k<<<dim3(FF/32, EE/32), tb, 0, s2>>>(W1, w1f, EE, FF, EE);
    wtf16_k<<<dim3(EE/32, FF/32), tb, 0, s2>>>(W2, w2f, FF, EE, FF);
    cudaEventRecord(ev_w0, s2);
    {
        const int l = 1;
        wtsplit_k<<<dim3(EE/32, EE/32), tb, 0, s2>>>(Wq + (size_t)l*EE*EE,
            wqkvh + (size_t)l*QKVN*EE, wqkvl + (size_t)l*QKVN*EE, EE, EE, EE);
        wtsplit_k<<<dim3(KVD/32, EE/32), tb, 0, s2>>>(Wk + (size_t)l*EE*KVD,
            wqkvh + (size_t)l*QKVN*EE + (size_t)EE*EE, wqkvl + (size_t)l*QKVN*EE + (size_t)EE*EE, EE, KVD, EE);
        wtsplit_k<<<dim3(KVD/32, EE/32), tb, 0, s2>>>(Wv + (size_t)l*EE*KVD,
            wqkvh + (size_t)l*QKVN*EE + (size_t)(EE+KVD)*EE, wqkvl + (size_t)l*QKVN*EE + (size_t)(EE+KVD)*EE, EE, KVD, EE);
        wtf16_k<<<dim3(EE/32, EE/32), tb, 0, s2>>>(Wo + (size_t)l*EE*EE,
            wof + (size_t)l*EE*EE, EE, EE, EE);
        wtf16_k<<<dim3(FF/32, EE/32), tb, 0, s2>>>(W1 + (size_t)l*EE*FF,
            w1f + (size_t)l*FF*EE, EE, FF, EE);
        wtf16_k<<<dim3(EE/32, FF/32), tb, 0, s2>>>(W2 + (size_t)l*FF*EE,
            w2f + (size_t)l*EE*FF, FF, EE, FF);
    }
    cudaEventRecord(ev_w1, s2);
    ef16_k<<<(int)(((size_t)VV*EE)/1024), 256, 0, s2>>>(embed, ef);
    cudaEventRecord(ev_e, s2);

    // ---- main stream: critical path ----
    wtsplit_k<<<dim3(EE/32, EE/32), tb>>>(Wq, wqkvh, wqkvl, EE, EE, EE);
    wtsplit_k<<<dim3(KVD/32, EE/32), tb>>>(Wk, wqkvh + (size_t)EE*EE, wqkvl + (size_t)EE*EE, EE, KVD, EE);
    wtsplit_k<<<dim3(KVD/32, EE/32), tb>>>(Wv, wqkvh + (size_t)(EE+KVD)*EE, wqkvl + (size_t)(EE+KVD)*EE, EE, KVD, EE);
    gather_embed_k<<<(TT * EE) / 256, 256>>>(embed, idx);
    layernorm_split_k<<<TT, 256>>>(xp, hh, hl, ln1_g, ln1_b);

    for (int it = 0; it < RNUM * LNUM; it++) {
        int l = it % LNUM;
        if (it == 1) cudaStreamWaitEvent(0, ev_w1, 0);
        // QKV: 3-term bf16, split-K=2
        gemm_mma<0,128,3><<<dim3(TT/128, QKVN/128, 2), 256, GSM128>>>(hh, hl,
            wqkvh + (size_t)l*QKVN*EE, wqkvl + (size_t)l*QKVN*EE,
            partp, QKVN, EE);
        qkv_post_k<<<dim3(TT/64, NH + 2*NKV), 256>>>(partp);
        scores_mma<<<dim3(TT/128, TT/64, NH), 256, SCSM>>>();
        softmax_thresh_k<<<dim3(TT, NH), 256>>>(gate, l);
        av_mma<<<dim3(TT/64, NH), 256, AVSM>>>();
        if (it == 0) cudaStreamWaitEvent(0, ev_w0, 0);
        // Wo: fp16 1-term, split-K=2; fused x+= & LN2 (fp16 single out for FFN1)
        fp16_mma<0,128,3,false><<<dim3(TT/128, EE/128, 2), 256, F16SM128>>>(yf,
            wof + (size_t)l*EE*EE, partp, nullptr, EE, EE);
        add_ln_split_k<<<TT, 256>>>(xp, partp, ln2_g + l * EE, ln2_b + l * EE,
                                    nullptr, nullptr, hf);
        // FFN1: fp16 1-term, TN=128 (256 blocks), gelu -> fp16 single
        fp16_mma<2,128,3,false><<<dim3(TT/128, FF/128, 1), 256, F16SM128>>>(hf,
            w1f + (size_t)l*FF*EE, nullptr, fff, FF, EE);
        // FFN2: fp16 1-term, split-K=2 -> partials
        fp16_mma<0,128,3,false><<<dim3(TT/128, EE/128, 2), 256, F16SM128>>>(fff,
            w2f + (size_t)l*EE*FF, partp, nullptr, EE, FF);
        if (it == RNUM * LNUM - 1) {
            add_ln_split_k<<<TT, 256>>>(xp, partp, lnf_g, lnf_b, nullptr, nullptr, hf);
        } else {
            int ln = (l + 1) % LNUM;
            add_ln_split_k<<<TT, 256>>>(xp, partp, ln1_g + ln * EE, ln1_b + ln * EE,
                                        hh, hl, nullptr);
        }
    }

    // logits: fp16 1-term GEMM with fused per-row sum-of-exp
    zero_rows_k<<<TT/256, 256>>>();
    cudaStreamWaitEvent(0, ev_e, 0);
    fp16_mma<0,256,2,true><<<dim3(TT/128, VV/256, 1), 256, F16SM256>>>(hf, ef,
        logits_dst, nullptr, VV, EE);

    if (loss_dst) loss_fin2_k<<<1, 1024>>>(logits_dst, tgt, loss_dst);
}